// round 8
// baseline (speedup 1.0000x reference)
#include <cuda_runtime.h>
#include <cuda_bf16.h>

// ---------------------------------------------------------------------------
// GraphEncoder relative-position attention, GB300 sm_103a — round 8
// B=2, S=2048, H=768, NH=12, D=64, R=256, MAX_REL=128
//
// R8: 8x2 thread microtile (rows x cols) to halve LDS-crossbar traffic
// (K/V read 8B/lane instead of 16B, Q/P broadcast) — kernel was
// LDS-bound (L1=69%). Same smem layout as R6 (115448 B, 2 CTAs/SM).
// Epilogue: exp(W-mu) converted in-place once (E table), GEMM is MUFU-free.
// ---------------------------------------------------------------------------

namespace {
constexpr int Bn  = 2;
constexpr int Sn  = 2048;
constexpr int Hn  = 768;
constexpr int NHn = 12;

// float region (float indices):
constexpr int QST   = 0;              // Q^T [d][m] swz / mu overlay    4096 f
constexpr int KSTo  = 4096;           // K^T [d][n] swz / P^T overlay   4096 f
constexpr int VSo   = 8192;           // V   [n][d]                     4096 f
// bf16 region (half indices; float region = 12288 f = 24576 h):
constexpr int RELCh = 24576;          // relc [m][256]                 16384 h
constexpr int WHo   = 40960;          // W/E  [254][66]                16764 h
constexpr int SMEMB = (40960 + 16764) * 2;   // 115448 bytes
}

__device__ float g_Q[Bn * NHn * Sn * 64];
__device__ float g_K[Bn * NHn * Sn * 64];
__device__ float g_V[Bn * NHn * Sn * 64];

typedef unsigned long long u64;
typedef unsigned int u32;

__device__ __forceinline__ u64 pk2(float lo, float hi) {
    u64 r; asm("mov.b64 %0,{%1,%2};" : "=l"(r) : "f"(lo), "f"(hi)); return r;
}
__device__ __forceinline__ u64 dup2(float v) { return pk2(v, v); }
__device__ __forceinline__ u64 ffma2(u64 a, u64 b, u64 c) {
    u64 d; asm("fma.rn.f32x2 %0,%1,%2,%3;" : "=l"(d) : "l"(a), "l"(b), "l"(c)); return d;
}
__device__ __forceinline__ u64 fmul2(u64 a, u64 b) {
    u64 d; asm("mul.rn.f32x2 %0,%1,%2;" : "=l"(d) : "l"(a), "l"(b)); return d;
}
__device__ __forceinline__ float2 up2(u64 v) {
    float2 f; asm("mov.b64 {%0,%1},%2;" : "=f"(f.x), "=f"(f.y) : "l"(v)); return f;
}

// XOR swizzle: 4-float groups of the m axis permuted per d (transposed tiles)
__device__ __forceinline__ int swz(int d, int m) {
    return d * 64 + (m ^ (((d >> 2) & 15) << 2));
}

__device__ __forceinline__ float wredmax(float v) {
    v = fmaxf(v, __shfl_xor_sync(0xffffffffu, v, 1));
    v = fmaxf(v, __shfl_xor_sync(0xffffffffu, v, 2));
    v = fmaxf(v, __shfl_xor_sync(0xffffffffu, v, 4));
    v = fmaxf(v, __shfl_xor_sync(0xffffffffu, v, 8));
    v = fmaxf(v, __shfl_xor_sync(0xffffffffu, v, 16));
    return v;
}
__device__ __forceinline__ float wredsum(float v) {
    v += __shfl_xor_sync(0xffffffffu, v, 1);
    v += __shfl_xor_sync(0xffffffffu, v, 2);
    v += __shfl_xor_sync(0xffffffffu, v, 4);
    v += __shfl_xor_sync(0xffffffffu, v, 8);
    v += __shfl_xor_sync(0xffffffffu, v, 16);
    return v;
}

// ---------------------------------------------------------------------------
// Kernel 1: fused QKV projection, FFMA2 microkernel (~fp32x2 peak).
// ---------------------------------------------------------------------------
__global__ __launch_bounds__(256) void qkv_kernel(
    const float* __restrict__ X,
    const float* __restrict__ Wq, const float* __restrict__ bq,
    const float* __restrict__ Wk, const float* __restrict__ bk,
    const float* __restrict__ Wv, const float* __restrict__ bv)
{
    __shared__ float As[16][128];
    __shared__ float Bs[16][128];

    const int z = blockIdx.z;
    const float* Wp   = (z == 0) ? Wq : ((z == 1) ? Wk : Wv);
    const float* bp   = (z == 0) ? bq : ((z == 1) ? bk : bv);
    float*       outp = (z == 0) ? g_Q : ((z == 1) ? g_K : g_V);
    const float  sc   = (z == 0) ? 0.125f : 1.0f;

    const int r0 = blockIdx.x * 128;
    const int c0 = blockIdx.y * 128;
    const int tid = threadIdx.x;
    const int ty = tid >> 4, tx = tid & 15;

    u64 acc2[8][4] = {};

    for (int kt = 0; kt < 768; kt += 16) {
        #pragma unroll
        for (int s2 = 0; s2 < 2; s2++) {
            int f = tid + s2 * 256;
            int row = f >> 2, cg = f & 3;
            float4 v = *(const float4*)(X + (size_t)(r0 + row) * 768 + kt + cg * 4);
            As[cg * 4 + 0][row] = v.x;
            As[cg * 4 + 1][row] = v.y;
            As[cg * 4 + 2][row] = v.z;
            As[cg * 4 + 3][row] = v.w;
        }
        #pragma unroll
        for (int s2 = 0; s2 < 2; s2++) {
            int f = tid + s2 * 256;
            int kr = f >> 5, cg = f & 31;
            *(float4*)(&Bs[kr][cg * 4]) =
                *(const float4*)(Wp + (size_t)(kt + kr) * 768 + c0 + cg * 4);
        }
        __syncthreads();

        #pragma unroll
        for (int k = 0; k < 16; k++) {
            float a[8];
            *(float4*)(a)     = *(const float4*)&As[k][ty * 4];
            *(float4*)(a + 4) = *(const float4*)&As[k][64 + ty * 4];
            ulonglong2 b0 = *(const ulonglong2*)&Bs[k][tx * 4];
            ulonglong2 b1 = *(const ulonglong2*)&Bs[k][64 + tx * 4];
            u64 bpk[4] = {b0.x, b0.y, b1.x, b1.y};
            #pragma unroll
            for (int i = 0; i < 8; i++) {
                u64 ad = dup2(a[i]);
                #pragma unroll
                for (int j = 0; j < 4; j++)
                    acc2[i][j] = ffma2(ad, bpk[j], acc2[i][j]);
            }
        }
        __syncthreads();
    }

    #pragma unroll
    for (int i = 0; i < 8; i++) {
        int r = r0 + ((i < 4) ? (ty * 4 + i) : (64 + ty * 4 + (i - 4)));
        int b = r >> 11, s = r & 2047;
        #pragma unroll
        for (int jg = 0; jg < 2; jg++) {
            int c = c0 + ((jg == 0) ? (tx * 4) : (64 + tx * 4));
            int h = c >> 6, d = c & 63;
            float2 lo = up2(acc2[i][jg * 2 + 0]);
            float2 hi = up2(acc2[i][jg * 2 + 1]);
            float4 o;
            o.x = (lo.x + bp[c + 0]) * sc;
            o.y = (lo.y + bp[c + 1]) * sc;
            o.z = (hi.x + bp[c + 2]) * sc;
            o.w = (hi.y + bp[c + 3]) * sc;
            *(float4*)(outp + ((size_t)(b * NHn + h) * Sn + s) * 64 + d) = o;
        }
    }
}

// ---------------------------------------------------------------------------
// Kernel 2: flash attention, 8x2 microtile. Thread: rows ty*8..+7 (ty=tid>>5),
// cols tx*2..+1 (tx=tid&31). Accumulators row-paired in f32x2.
// ---------------------------------------------------------------------------
__global__ __launch_bounds__(256, 2) void attn_kernel(
    const float* __restrict__ mask,
    const float* __restrict__ rke,
    const float* __restrict__ rve,
    float* __restrict__ out)
{
    extern __shared__ float sm[];
    __nv_bfloat16* smh = (__nv_bfloat16*)sm;

    const int tid = threadIdx.x;
    const int ty = tid >> 5, tx = tid & 31;
    const int hq = blockIdx.y, bz = blockIdx.z;
    const int bh = bz * NHn + hq;
    const int i0 = blockIdx.x * 64;

    const float* Qg = g_Q + ((size_t)bh * Sn + i0) * 64;
    const float* Kg = g_K + (size_t)bh * Sn * 64;
    const float* Vg = g_V + (size_t)bh * Sn * 64;
    const float* maskg = mask + (size_t)bz * Sn + tx * 2;

    // ---- init W (bf16) to -1e30: 16764 halves = 8382 u32 ----
    {
        __nv_bfloat16 hneg = __float2bfloat16(-1e30f);
        unsigned short us = __bfloat16_as_ushort(hneg);
        u32 vv = (u32)us | ((u32)us << 16);
        u32* w32 = (u32*)&smh[WHo];
        #pragma unroll
        for (int t = 0; t < 32; t++)
            w32[tid + t * 256] = vv;
        if (tid < 8382 - 32 * 256)
            w32[tid + 32 * 256] = vv;
    }

    // ---- load Q tile, transposed + swizzled ----
    #pragma unroll
    for (int s2 = 0; s2 < 4; s2++) {
        int f = tid + s2 * 256;
        int m = f >> 4, dg = f & 15;
        float4 v = *(const float4*)(Qg + m * 64 + dg * 4);
        sm[QST + swz(dg * 4 + 0, m)] = v.x;
        sm[QST + swz(dg * 4 + 1, m)] = v.y;
        sm[QST + swz(dg * 4 + 2, m)] = v.z;
        sm[QST + swz(dg * 4 + 3, m)] = v.w;
    }
    __syncthreads();

    // ---- rel-key cache: relc[m][r] = q_m . rke_r  (stored bf16) ----
    for (int rc = 0; rc < 4; rc++) {
        #pragma unroll
        for (int s2 = 0; s2 < 4; s2++) {
            int f = tid + s2 * 256;
            int n = f >> 4, dg = f & 15;
            float4 v = *(const float4*)(rke + (rc * 64 + n) * 64 + dg * 4);
            sm[KSTo + swz(dg * 4 + 0, n)] = v.x;
            sm[KSTo + swz(dg * 4 + 1, n)] = v.y;
            sm[KSTo + swz(dg * 4 + 2, n)] = v.z;
            sm[KSTo + swz(dg * 4 + 3, n)] = v.w;
        }
        __syncthreads();
        u64 t2[4][2] = {};
        #pragma unroll
        for (int d = 0; d < 64; d++) {
            int s = ((d >> 2) & 15) << 2;
            ulonglong2 qa = *(const ulonglong2*)&sm[QST + d * 64 + ((ty * 8) ^ s)];
            ulonglong2 qb = *(const ulonglong2*)&sm[QST + d * 64 + ((ty * 8 + 4) ^ s)];
            float2 kf = *(const float2*)&sm[KSTo + d * 64 + ((tx * 2) ^ s)];
            u64 k0 = dup2(kf.x), k1 = dup2(kf.y);
            t2[0][0] = ffma2(qa.x, k0, t2[0][0]);
            t2[0][1] = ffma2(qa.x, k1, t2[0][1]);
            t2[1][0] = ffma2(qa.y, k0, t2[1][0]);
            t2[1][1] = ffma2(qa.y, k1, t2[1][1]);
            t2[2][0] = ffma2(qb.x, k0, t2[2][0]);
            t2[2][1] = ffma2(qb.x, k1, t2[2][1]);
            t2[3][0] = ffma2(qb.y, k0, t2[3][0]);
            t2[3][1] = ffma2(qb.y, k1, t2[3][1]);
        }
        #pragma unroll
        for (int rp = 0; rp < 4; rp++) {
            #pragma unroll
            for (int ni = 0; ni < 2; ni++) {
                float2 v = up2(t2[rp][ni]);
                int col = rc * 64 + tx * 2 + ni;
                smh[RELCh + (ty * 8 + 2 * rp)     * 256 + col] = __float2bfloat16(v.x);
                smh[RELCh + (ty * 8 + 2 * rp + 1) * 256 + col] = __float2bfloat16(v.y);
            }
        }
        __syncthreads();
    }

    // ---- accumulators: o2[rp][di] pairs rows (2rp,2rp+1) for dim di ----
    u64 o2[4][2] = {};
    float mu[8], l[8] = {}, plo[8] = {}, phi[8] = {};
    #pragma unroll
    for (int ri = 0; ri < 8; ri++) mu[ri] = -1e30f;

    for (int jt = 0; jt < 32; jt++) {
        const int j0 = jt * 64;
        const int doff = j0 - i0;
        __syncthreads();   // prior PV reads of P^T/V done before overwrite

        // ---- load K^T (swz), V ----
        #pragma unroll
        for (int s2 = 0; s2 < 4; s2++) {
            int f = tid + s2 * 256;
            int n = f >> 4, dg = f & 15;
            float4 v = *(const float4*)(Kg + (size_t)(j0 + n) * 64 + dg * 4);
            sm[KSTo + swz(dg * 4 + 0, n)] = v.x;
            sm[KSTo + swz(dg * 4 + 1, n)] = v.y;
            sm[KSTo + swz(dg * 4 + 2, n)] = v.z;
            sm[KSTo + swz(dg * 4 + 3, n)] = v.w;
            float4 w = *(const float4*)(Vg + (size_t)(j0 + n) * 64 + dg * 4);
            *(float4*)&sm[VSo + n * 64 + dg * 4] = w;
        }
        float2 mk = __ldg((const float2*)(maskg + j0));
        float mb0 = (1.0f - mk.x) * -10000.0f;
        float mb1 = (1.0f - mk.y) * -10000.0f;
        __syncthreads();

        // ---- scores (FFMA2, row-paired) ----
        u64 p2[4][2] = {};
        #pragma unroll
        for (int d = 0; d < 64; d++) {
            int s = ((d >> 2) & 15) << 2;
            ulonglong2 qa = *(const ulonglong2*)&sm[QST + d * 64 + ((ty * 8) ^ s)];
            ulonglong2 qb = *(const ulonglong2*)&sm[QST + d * 64 + ((ty * 8 + 4) ^ s)];
            float2 kf = *(const float2*)&sm[KSTo + d * 64 + ((tx * 2) ^ s)];
            u64 k0 = dup2(kf.x), k1 = dup2(kf.y);
            p2[0][0] = ffma2(qa.x, k0, p2[0][0]);
            p2[0][1] = ffma2(qa.x, k1, p2[0][1]);
            p2[1][0] = ffma2(qa.y, k0, p2[1][0]);
            p2[1][1] = ffma2(qa.y, k1, p2[1][1]);
            p2[2][0] = ffma2(qb.x, k0, p2[2][0]);
            p2[2][1] = ffma2(qb.x, k1, p2[2][1]);
            p2[3][0] = ffma2(qb.y, k0, p2[3][0]);
            p2[3][1] = ffma2(qb.y, k1, p2[3][1]);
        }
        float p[8][2];
        #pragma unroll
        for (int rp = 0; rp < 4; rp++) {
            float2 c0 = up2(p2[rp][0]), c1 = up2(p2[rp][1]);
            p[2 * rp][0]     = c0.x; p[2 * rp][1]     = c1.x;
            p[2 * rp + 1][0] = c0.y; p[2 * rp + 1][1] = c1.y;
        }

        const bool pure_lo = (doff + 63 <= -128);
        const bool pure_hi = (doff - 63 >= 127);
        const bool pure = pure_lo || pure_hi;
        const bool has_clamp = !pure && !((doff - 63 >= -127) && (doff + 63 <= 126));

        // ---- bias add (+ stage in-band biased scores into W, bf16) ----
        if (pure) {
            const int b = pure_lo ? 0 : 255;
            #pragma unroll
            for (int ri = 0; ri < 8; ri++) {
                float rb = __bfloat162float(smh[RELCh + (ty * 8 + ri) * 256 + b]);
                p[ri][0] += rb + mb0;
                p[ri][1] += rb + mb1;
            }
        } else {
            #pragma unroll
            for (int ri = 0; ri < 8; ri++) {
                int row = ty * 8 + ri;
                #pragma unroll
                for (int ni = 0; ni < 2; ni++) {
                    int dlt = doff + tx * 2 + ni - row;
                    int bkt = max(-128, min(127, dlt)) + 128;
                    p[ri][ni] += __bfloat162float(smh[RELCh + row * 256 + bkt])
                               + (ni ? mb1 : mb0);
                }
            }
            #pragma unroll
            for (int ri = 0; ri < 8; ri++) {
                int row = ty * 8 + ri;
                #pragma unroll
                for (int ni = 0; ni < 2; ni++) {
                    int dlt = doff + tx * 2 + ni - row;
                    if (dlt > -128 && dlt < 127)
                        smh[WHo + (dlt + 127) * 66 + row] = __float2bfloat16(p[ri][ni]);
                }
            }
        }

        // ---- online softmax (full-warp reductions; warp == row group) ----
        float al[8];
        float rsv[8];
        #pragma unroll
        for (int ri = 0; ri < 8; ri++) {
            float rm = wredmax(fmaxf(p[ri][0], p[ri][1]));
            float nm = fmaxf(mu[ri], rm);
            al[ri] = __expf(mu[ri] - nm);
            mu[ri] = nm;
            p[ri][0] = __expf(p[ri][0] - nm);
            p[ri][1] = __expf(p[ri][1] - nm);
            float rs = wredsum(p[ri][0] + p[ri][1]);
            rsv[ri] = rs;
            l[ri] = l[ri] * al[ri] + rs;
            plo[ri] *= al[ri];
            phi[ri] *= al[ri];
        }
        #pragma unroll
        for (int rp = 0; rp < 4; rp++) {
            u64 ap = pk2(al[2 * rp], al[2 * rp + 1]);
            o2[rp][0] = fmul2(o2[rp][0], ap);
            o2[rp][1] = fmul2(o2[rp][1], ap);
        }
        if (pure_lo) {
            #pragma unroll
            for (int ri = 0; ri < 8; ri++) plo[ri] += rsv[ri];
        }
        if (pure_hi) {
            #pragma unroll
            for (int ri = 0; ri < 8; ri++) phi[ri] += rsv[ri];
        }
        if (has_clamp) {
            #pragma unroll
            for (int ri = 0; ri < 8; ri++) {
                int row = ty * 8 + ri;
                float cl = 0.f, ch = 0.f;
                #pragma unroll
                for (int ni = 0; ni < 2; ni++) {
                    int dlt = doff + tx * 2 + ni - row;
                    if (dlt <= -128)     cl += p[ri][ni];
                    else if (dlt >= 127) ch += p[ri][ni];
                }
                plo[ri] += wredsum(cl);
                phi[ri] += wredsum(ch);
            }
        }

        // ---- stage P^T into dead K region: PT[n][m] swizzled ----
        __syncthreads();
        #pragma unroll
        for (int ni = 0; ni < 2; ni++) {
            int n = tx * 2 + ni;
            int s = ((n >> 2) & 15) << 2;
            *(float4*)&sm[KSTo + n * 64 + ((ty * 8) ^ s)] =
                make_float4(p[0][ni], p[1][ni], p[2][ni], p[3][ni]);
            *(float4*)&sm[KSTo + n * 64 + ((ty * 8 + 4) ^ s)] =
                make_float4(p[4][ni], p[5][ni], p[6][ni], p[7][ni]);
        }
        __syncthreads();

        // ---- PV (FFMA2): P^T broadcast pairs x V dim pair ----
        #pragma unroll 4
        for (int n = 0; n < 64; n++) {
            int s = ((n >> 2) & 15) << 2;
            ulonglong2 pa = *(const ulonglong2*)&sm[KSTo + n * 64 + ((ty * 8) ^ s)];
            ulonglong2 pb = *(const ulonglong2*)&sm[KSTo + n * 64 + ((ty * 8 + 4) ^ s)];
            float2 vf = *(const float2*)&sm[VSo + n * 64 + tx * 2];
            u64 v0 = dup2(vf.x), v1 = dup2(vf.y);
            o2[0][0] = ffma2(pa.x, v0, o2[0][0]);
            o2[0][1] = ffma2(pa.x, v1, o2[0][1]);
            o2[1][0] = ffma2(pa.y, v0, o2[1][0]);
            o2[1][1] = ffma2(pa.y, v1, o2[1][1]);
            o2[2][0] = ffma2(pb.x, v0, o2[2][0]);
            o2[2][1] = ffma2(pb.x, v1, o2[2][1]);
            o2[3][0] = ffma2(pb.y, v0, o2[3][0]);
            o2[3][1] = ffma2(pb.y, v1, o2[3][1]);
        }
    }

    // ---- epilogue: stage mu into dead Q region, build E = exp(W-mu) ----
    __syncthreads();
    if (tx < 8)
        sm[QST + ty * 8 + tx] = mu[tx];
    __syncthreads();
    #pragma unroll 4
    for (int t = 0; t < 64; t++) {
        int idx = tid + t * 256;
        if (idx < 254 * 64) {
            int r = idx >> 6, m = idx & 63;
            float w = __bfloat162float(smh[WHo + r * 66 + m]);
            smh[WHo + r * 66 + m] = __float2bfloat16(__expf(w - sm[QST + m]));
        }
    }
    __syncthreads();

    // ---- rel-value GEMM: o += E @ rve[1..254]  (MUFU-free) ----
    #pragma unroll 2
    for (int r = 0; r < 254; r++) {
        const __nv_bfloat162* wr = (const __nv_bfloat162*)&smh[WHo + r * 66 + ty * 8];
        __nv_bfloat162 e0 = wr[0], e1 = wr[1], e2 = wr[2], e3 = wr[3];
        float2 rv = __ldg((const float2*)(rve + (r + 1) * 64 + tx * 2));
        u64 r0 = dup2(rv.x), r1 = dup2(rv.y);
        float2 f0 = __bfloat1622float2(e0);
        float2 f1 = __bfloat1622float2(e1);
        float2 f2 = __bfloat1622float2(e2);
        float2 f3 = __bfloat1622float2(e3);
        u64 ep0 = pk2(f0.x, f0.y), ep1 = pk2(f1.x, f1.y);
        u64 ep2 = pk2(f2.x, f2.y), ep3 = pk2(f3.x, f3.y);
        o2[0][0] = ffma2(ep0, r0, o2[0][0]);
        o2[0][1] = ffma2(ep0, r1, o2[0][1]);
        o2[1][0] = ffma2(ep1, r0, o2[1][0]);
        o2[1][1] = ffma2(ep1, r1, o2[1][1]);
        o2[2][0] = ffma2(ep2, r0, o2[2][0]);
        o2[2][1] = ffma2(ep2, r1, o2[2][1]);
        o2[3][0] = ffma2(ep3, r0, o2[3][0]);
        o2[3][1] = ffma2(ep3, r1, o2[3][1]);
    }

    // ---- clamp-bucket terms, normalize, write [B,S,H] ----
    float2 rv0 = __ldg((const float2*)(rve + 0 * 64 + tx * 2));
    float2 rvN = __ldg((const float2*)(rve + 255 * 64 + tx * 2));
    #pragma unroll
    for (int rp = 0; rp < 4; rp++) {
        float2 c0 = up2(o2[rp][0]), c1 = up2(o2[rp][1]);
        #pragma unroll
        for (int h = 0; h < 2; h++) {
            int ri = 2 * rp + h;
            float ox = h ? c0.y : c0.x;
            float oy = h ? c1.y : c1.x;
            float inv = 1.0f / l[ri];
            int row = i0 + ty * 8 + ri;
            float2 res;
            res.x = (ox + plo[ri] * rv0.x + phi[ri] * rvN.x) * inv;
            res.y = (oy + plo[ri] * rv0.y + phi[ri] * rvN.y) * inv;
            *(float2*)(out + ((size_t)bz * Sn + row) * Hn + hq * 64 + tx * 2) = res;
        }
    }
}

// ---------------------------------------------------------------------------
extern "C" void kernel_launch(void* const* d_in, const int* in_sizes, int n_in,
                              void* d_out, int out_size)
{
    const float* X    = (const float*)d_in[0];
    const float* mask = (const float*)d_in[1];
    const float* Wq   = (const float*)d_in[2];
    const float* bq   = (const float*)d_in[3];
    const float* Wk   = (const float*)d_in[4];
    const float* bk   = (const float*)d_in[5];
    const float* Wv   = (const float*)d_in[6];
    const float* bv   = (const float*)d_in[7];
    const float* rke  = (const float*)d_in[8];
    const float* rve  = (const float*)d_in[9];
    float* out = (float*)d_out;

    (void)in_sizes; (void)n_in; (void)out_size;

    cudaFuncSetAttribute(attn_kernel,
                         cudaFuncAttributeMaxDynamicSharedMemorySize, SMEMB);

    qkv_kernel<<<dim3(32, 6, 3), 256>>>(X, Wq, bq, Wk, bk, Wv, bv);
    attn_kernel<<<dim3(32, NHn, Bn), 256, SMEMB>>>(mask, rke, rve, out);
}

// round 9
// speedup vs baseline: 1.5752x; 1.5752x over previous
#include <cuda_runtime.h>
#include <cuda_bf16.h>

// ---------------------------------------------------------------------------
// GraphEncoder relative-position attention, GB300 sm_103a — round 9
// HMMA bf16 hi/lo-split flash attention. 2 CTAs/SM, smem 101112 B.
// ---------------------------------------------------------------------------

namespace {
constexpr int Bn  = 2;
constexpr int Sn  = 2048;
constexpr int Hn  = 768;
constexpr int NHn = 12;

// smem byte offsets
constexpr int QHo   = 0;         // Q hi plane  64x64 bf16 (8192)
constexpr int QLo   = 8192;      // Q lo plane
constexpr int KVHo  = 16384;     // K/V hi plane (shared)
constexpr int KVLo  = 24576;     // K/V lo plane
constexpr int RELCo = 32768;     // relc bf16 [64][256]  (32768)
constexpr int Wo    = 65536;     // W bf16 [254][66]     (33528)
constexpr int EXMo  = 99064;     // f32 [2][64] half-max
constexpr int EXSo  = 99576;     // f32 [2][64] half-sum
constexpr int EXLo  = 100088;    // f32 [2][64] clamp-lo
constexpr int EXHo  = 100600;    // f32 [2][64] clamp-hi
constexpr int SMEMB = 101112;
// epilogue overlays (Q/KV planes dead)
constexpr int CTXo  = 0;         // f32 [64][64]
constexpr int LVo   = 16384;     // f32 [64]
constexpr int PLOo  = 16640;
constexpr int PHIo  = 16896;
constexpr int MUo   = 17152;
}

__device__ float g_Q[Bn * NHn * Sn * 64];
__device__ float g_K[Bn * NHn * Sn * 64];
__device__ float g_V[Bn * NHn * Sn * 64];

typedef unsigned long long u64;
typedef unsigned int u32;

__device__ __forceinline__ u64 pk2(float lo, float hi) {
    u64 r; asm("mov.b64 %0,{%1,%2};" : "=l"(r) : "f"(lo), "f"(hi)); return r;
}
__device__ __forceinline__ u64 dup2(float v) { return pk2(v, v); }
__device__ __forceinline__ u64 ffma2(u64 a, u64 b, u64 c) {
    u64 d; asm("fma.rn.f32x2 %0,%1,%2,%3;" : "=l"(d) : "l"(a), "l"(b), "l"(c)); return d;
}
__device__ __forceinline__ float2 up2(u64 v) {
    float2 f; asm("mov.b64 {%0,%1},%2;" : "=f"(f.x), "=f"(f.y) : "l"(v)); return f;
}
// pack two f32 -> bf16x2 (lo in low half)
__device__ __forceinline__ u32 pkbf(float lo, float hi) {
    u32 d; asm("cvt.rn.bf16x2.f32 %0,%1,%2;" : "=r"(d) : "f"(hi), "f"(lo)); return d;
}
__device__ __forceinline__ float bflo(u32 h) { return __uint_as_float(h << 16); }
__device__ __forceinline__ float bfhi(u32 h) { return __uint_as_float(h & 0xFFFF0000u); }

__device__ __forceinline__ void ldm_x4(u32& r0, u32& r1, u32& r2, u32& r3, u32 a) {
    asm volatile("ldmatrix.sync.aligned.m8n8.x4.shared.b16 {%0,%1,%2,%3},[%4];"
                 : "=r"(r0), "=r"(r1), "=r"(r2), "=r"(r3) : "r"(a));
}
__device__ __forceinline__ void ldm_x2(u32& r0, u32& r1, u32 a) {
    asm volatile("ldmatrix.sync.aligned.m8n8.x2.shared.b16 {%0,%1},[%2];"
                 : "=r"(r0), "=r"(r1) : "r"(a));
}
__device__ __forceinline__ void ldm_x4t(u32& r0, u32& r1, u32& r2, u32& r3, u32 a) {
    asm volatile("ldmatrix.sync.aligned.m8n8.x4.trans.shared.b16 {%0,%1,%2,%3},[%4];"
                 : "=r"(r0), "=r"(r1), "=r"(r2), "=r"(r3) : "r"(a));
}
__device__ __forceinline__ void mma_bf16(float* d, const u32* a, u32 b0, u32 b1) {
    asm volatile("mma.sync.aligned.m16n8k16.row.col.f32.bf16.bf16.f32 "
                 "{%0,%1,%2,%3},{%4,%5,%6,%7},{%8,%9},{%0,%1,%2,%3};"
                 : "+f"(d[0]), "+f"(d[1]), "+f"(d[2]), "+f"(d[3])
                 : "r"(a[0]), "r"(a[1]), "r"(a[2]), "r"(a[3]), "r"(b0), "r"(b1));
}

// load 64x64 f32 (row stride 64) -> hi/lo bf16 planes, 16B-chunk xor swizzle
__device__ __forceinline__ void load_split64(const float* __restrict__ src,
                                             char* smc, int hiOff, int loOff, int tid)
{
    #pragma unroll
    for (int s = 0; s < 4; s++) {
        int f = tid + s * 256;
        int row = f >> 4, cg = f & 15;
        float4 v = *(const float4*)(src + row * 64 + cg * 4);
        __nv_bfloat162 h0 = __floats2bfloat162_rn(v.x, v.y);
        __nv_bfloat162 h1 = __floats2bfloat162_rn(v.z, v.w);
        float2 f0 = __bfloat1622float2(h0);
        float2 f1 = __bfloat1622float2(h1);
        __nv_bfloat162 l0 = __floats2bfloat162_rn(v.x - f0.x, v.y - f0.y);
        __nv_bfloat162 l1 = __floats2bfloat162_rn(v.z - f1.x, v.w - f1.y);
        int off = row * 128 + (((cg >> 1) ^ (row & 7)) << 4) + ((cg & 1) << 3);
        *(__nv_bfloat162*)(smc + hiOff + off)     = h0;
        *(__nv_bfloat162*)(smc + hiOff + off + 4) = h1;
        *(__nv_bfloat162*)(smc + loOff + off)     = l0;
        *(__nv_bfloat162*)(smc + loOff + off + 4) = l1;
    }
}

// 64x64x64 split-bf16 score GEMM: c[nt][e] += Q[16wm rows] . KV[32wn cols]
__device__ __forceinline__ void mma_scores(float c[4][4], u32 smb,
                                           int wm, int wn, int lane)
{
    const int r8 = lane & 7;
    const int j4 = lane >> 3;               // 0..3
    const int jb = (lane >> 3) & 1;         // 0..1 (x2 addressing)
    #pragma unroll
    for (int ks = 0; ks < 4; ks++) {
        int mrow = 16 * wm + r8 + (j4 & 1) * 8;
        int chA = 2 * ks + (j4 >> 1);
        u32 aAddr = smb + (u32)(QHo + mrow * 128 + ((chA ^ (mrow & 7)) << 4));
        u32 ah[4], al[4];
        ldm_x4(ah[0], ah[1], ah[2], ah[3], aAddr);
        ldm_x4(al[0], al[1], al[2], al[3], aAddr + (QLo - QHo));
        #pragma unroll
        for (int nt = 0; nt < 4; nt++) {
            int n = 32 * wn + 8 * nt + r8;
            int chB = 2 * ks + jb;
            u32 bAddr = smb + (u32)(KVHo + n * 128 + ((chB ^ (n & 7)) << 4));
            u32 bh0, bh1, bl0, bl1;
            ldm_x2(bh0, bh1, bAddr);
            ldm_x2(bl0, bl1, bAddr + (KVLo - KVHo));
            mma_bf16(c[nt], ah, bh0, bh1);
            mma_bf16(c[nt], ah, bl0, bl1);
            mma_bf16(c[nt], al, bh0, bh1);
        }
    }
}

// ---------------------------------------------------------------------------
// Kernel 1: fused QKV projection (unchanged from R6, ~fp32x2 peak).
// ---------------------------------------------------------------------------
__global__ __launch_bounds__(256) void qkv_kernel(
    const float* __restrict__ X,
    const float* __restrict__ Wq, const float* __restrict__ bq,
    const float* __restrict__ Wk, const float* __restrict__ bk,
    const float* __restrict__ Wv, const float* __restrict__ bv)
{
    __shared__ float As[16][128];
    __shared__ float Bs[16][128];

    const int z = blockIdx.z;
    const float* Wp   = (z == 0) ? Wq : ((z == 1) ? Wk : Wv);
    const float* bp   = (z == 0) ? bq : ((z == 1) ? bk : bv);
    float*       outp = (z == 0) ? g_Q : ((z == 1) ? g_K : g_V);
    const float  sc   = (z == 0) ? 0.125f : 1.0f;

    const int r0 = blockIdx.x * 128;
    const int c0 = blockIdx.y * 128;
    const int tid = threadIdx.x;
    const int ty = tid >> 4, tx = tid & 15;

    u64 acc2[8][4] = {};

    for (int kt = 0; kt < 768; kt += 16) {
        #pragma unroll
        for (int s2 = 0; s2 < 2; s2++) {
            int f = tid + s2 * 256;
            int row = f >> 2, cg = f & 3;
            float4 v = *(const float4*)(X + (size_t)(r0 + row) * 768 + kt + cg * 4);
            As[cg * 4 + 0][row] = v.x;
            As[cg * 4 + 1][row] = v.y;
            As[cg * 4 + 2][row] = v.z;
            As[cg * 4 + 3][row] = v.w;
        }
        #pragma unroll
        for (int s2 = 0; s2 < 2; s2++) {
            int f = tid + s2 * 256;
            int kr = f >> 5, cg = f & 31;
            *(float4*)(&Bs[kr][cg * 4]) =
                *(const float4*)(Wp + (size_t)(kt + kr) * 768 + c0 + cg * 4);
        }
        __syncthreads();

        #pragma unroll
        for (int k = 0; k < 16; k++) {
            float a[8];
            *(float4*)(a)     = *(const float4*)&As[k][ty * 4];
            *(float4*)(a + 4) = *(const float4*)&As[k][64 + ty * 4];
            ulonglong2 b0 = *(const ulonglong2*)&Bs[k][tx * 4];
            ulonglong2 b1 = *(const ulonglong2*)&Bs[k][64 + tx * 4];
            u64 bpk[4] = {b0.x, b0.y, b1.x, b1.y};
            #pragma unroll
            for (int i = 0; i < 8; i++) {
                u64 ad = dup2(a[i]);
                #pragma unroll
                for (int jj = 0; jj < 4; jj++)
                    acc2[i][jj] = ffma2(ad, bpk[jj], acc2[i][jj]);
            }
        }
        __syncthreads();
    }

    #pragma unroll
    for (int i = 0; i < 8; i++) {
        int r = r0 + ((i < 4) ? (ty * 4 + i) : (64 + ty * 4 + (i - 4)));
        int b = r >> 11, s = r & 2047;
        #pragma unroll
        for (int jg = 0; jg < 2; jg++) {
            int c = c0 + ((jg == 0) ? (tx * 4) : (64 + tx * 4));
            int h = c >> 6, d = c & 63;
            float2 lo = up2(acc2[i][jg * 2 + 0]);
            float2 hi = up2(acc2[i][jg * 2 + 1]);
            float4 o;
            o.x = (lo.x + bp[c + 0]) * sc;
            o.y = (lo.y + bp[c + 1]) * sc;
            o.z = (hi.x + bp[c + 2]) * sc;
            o.w = (hi.y + bp[c + 3]) * sc;
            *(float4*)(outp + ((size_t)(b * NHn + h) * Sn + s) * 64 + d) = o;
        }
    }
}

// ---------------------------------------------------------------------------
// Kernel 2: HMMA flash attention.
// Warp w: wm=w&3 -> rows 16wm..+15 ; wn=w>>2 -> col half 32wn..+31.
// Thread fragment element (nt,e): row = 16wm+(lane>>2)+8*(e>>1),
//                                 col = 32wn+8nt+2*(lane&3)+(e&1).
// ---------------------------------------------------------------------------
__global__ __launch_bounds__(256, 2) void attn_kernel(
    const float* __restrict__ mask,
    const float* __restrict__ rke,
    const float* __restrict__ rve,
    float* __restrict__ out)
{
    extern __shared__ char smc[];
    __nv_bfloat16* smh = (__nv_bfloat16*)smc;
    const u32 smb = (u32)__cvta_generic_to_shared(smc);

    const int tid = threadIdx.x;
    const int lane = tid & 31;
    const int w = tid >> 5, wm = w & 3, wn = w >> 2;
    const int hq = blockIdx.y, bz = blockIdx.z;
    const int bh = bz * NHn + hq;
    const int i0 = blockIdx.x * 64;

    const float* Qg = g_Q + ((size_t)bh * Sn + i0) * 64;
    const float* Kg = g_K + (size_t)bh * Sn * 64;
    const float* Vg = g_V + (size_t)bh * Sn * 64;
    const float* maskg = mask + (size_t)bz * Sn;

    float* exm = (float*)(smc + EXMo);
    float* exs = (float*)(smc + EXSo);
    float* exl = (float*)(smc + EXLo);
    float* exh = (float*)(smc + EXHo);

    // ---- W init to -1e30 (16764 halves = 8382 u32) ----
    {
        __nv_bfloat16 hneg = __float2bfloat16(-1e30f);
        unsigned short us = __bfloat16_as_ushort(hneg);
        u32 vv = (u32)us | ((u32)us << 16);
        u32* w32 = (u32*)(smc + Wo);
        #pragma unroll
        for (int t = 0; t < 32; t++) w32[tid + t * 256] = vv;
        if (tid < 8382 - 32 * 256) w32[tid + 32 * 256] = vv;
    }

    // ---- Q planes ----
    load_split64(Qg, smc, QHo, QLo, tid);
    __syncthreads();

    // ---- relc via MMA: relc[m][r] = q_m . rke_r ----
    const int rb4 = lane & 3, rd4 = lane >> 2;
    for (int rb = 0; rb < 4; rb++) {
        load_split64(rke + rb * 64 * 64, smc, KVHo, KVLo, tid);
        __syncthreads();
        float c[4][4] = {};
        mma_scores(c, smb, wm, wn, lane);
        #pragma unroll
        for (int nt = 0; nt < 4; nt++) {
            #pragma unroll
            for (int e = 0; e < 4; e++) {
                int m = 16 * wm + rd4 + (e >> 1) * 8;
                int r = rb * 64 + 32 * wn + 8 * nt + 2 * rb4 + (e & 1);
                smh[(RELCo >> 1) + m * 256 + r] = __float2bfloat16(c[nt][e]);
            }
        }
        __syncthreads();
    }

    // ---- state ----
    float ctx[8][4] = {};
    float mu[2] = {-1e30f, -1e30f}, l[2] = {}, plo[2] = {}, phi[2] = {};
    const int rbase = 16 * wm + rd4;

    for (int jt = 0; jt < 32; jt++) {
        const int j0 = jt * 64;
        const int doff = j0 - i0;
        __syncthreads();                       // prev PV reads done
        load_split64(Kg + (size_t)j0 * 64, smc, KVHo, KVLo, tid);
        __syncthreads();                       // K ready

        float c[4][4] = {};
        mma_scores(c, smb, wm, wn, lane);

        // mask bias (per thread cols)
        float mb[4][2];
        #pragma unroll
        for (int nt = 0; nt < 4; nt++) {
            float2 mv = __ldg((const float2*)(maskg + j0 + 32 * wn + 8 * nt + 2 * rb4));
            mb[nt][0] = (1.0f - mv.x) * -10000.0f;
            mb[nt][1] = (1.0f - mv.y) * -10000.0f;
        }

        const bool pure_lo = (doff + 63 <= -128);
        const bool pure_hi = (doff - 63 >= 127);
        if (pure_lo || pure_hi) {
            const int b = pure_lo ? 0 : 255;
            float rb0 = __bfloat162float(smh[(RELCo >> 1) + rbase * 256 + b]);
            float rb1 = __bfloat162float(smh[(RELCo >> 1) + (rbase + 8) * 256 + b]);
            #pragma unroll
            for (int nt = 0; nt < 4; nt++)
                #pragma unroll
                for (int e = 0; e < 4; e++)
                    c[nt][e] += ((e >> 1) ? rb1 : rb0) + mb[nt][e & 1];
        } else {
            #pragma unroll
            for (int nt = 0; nt < 4; nt++) {
                #pragma unroll
                for (int e = 0; e < 4; e++) {
                    int row = rbase + (e >> 1) * 8;
                    int col = 32 * wn + 8 * nt + 2 * rb4 + (e & 1);
                    int dlt = doff + col - row;
                    int bkt = max(-128, min(127, dlt)) + 128;
                    c[nt][e] += __bfloat162float(
                                    smh[(RELCo >> 1) + row * 256 + bkt]) + mb[nt][e & 1];
                    if (dlt > -128 && dlt < 127)
                        smh[(Wo >> 1) + (dlt + 127) * 66 + row] = __float2bfloat16(c[nt][e]);
                }
            }
        }

        // softmax part 1: half-max per row
        float lm[2];
        #pragma unroll
        for (int rl = 0; rl < 2; rl++) {
            float m0 = fmaxf(fmaxf(c[0][2 * rl], c[0][2 * rl + 1]),
                             fmaxf(c[1][2 * rl], c[1][2 * rl + 1]));
            float m1 = fmaxf(fmaxf(c[2][2 * rl], c[2][2 * rl + 1]),
                             fmaxf(c[3][2 * rl], c[3][2 * rl + 1]));
            float v = fmaxf(m0, m1);
            v = fmaxf(v, __shfl_xor_sync(0xffffffffu, v, 1));
            v = fmaxf(v, __shfl_xor_sync(0xffffffffu, v, 2));
            lm[rl] = v;
        }
        if ((lane & 3) == 0) {
            exm[wn * 64 + rbase]     = lm[0];
            exm[wn * 64 + rbase + 8] = lm[1];
        }
        __syncthreads();                       // exm ready; K reads done

        // V planes into shared KV region (reads ready at next barrier)
        load_split64(Vg + (size_t)j0 * 64, smc, KVHo, KVLo, tid);

        // softmax part 2: exp, half sums + clamp masses
        float alpha[2];
        #pragma unroll
        for (int rl = 0; rl < 2; rl++) {
            int row = rbase + 8 * rl;
            float nm = fmaxf(mu[rl], fmaxf(exm[row], exm[64 + row]));
            alpha[rl] = __expf(mu[rl] - nm);
            mu[rl] = nm;
            float sum = 0.f, clo = 0.f, chi = 0.f;
            #pragma unroll
            for (int nt = 0; nt < 4; nt++) {
                #pragma unroll
                for (int h = 0; h < 2; h++) {
                    int e = 2 * rl + h;
                    float p = __expf(c[nt][e] - nm);
                    c[nt][e] = p;
                    sum += p;
                    int col = 32 * wn + 8 * nt + 2 * rb4 + h;
                    int dlt = doff + col - row;
                    if (dlt <= -128)     clo += p;
                    else if (dlt >= 127) chi += p;
                }
            }
            sum += __shfl_xor_sync(0xffffffffu, sum, 1);
            sum += __shfl_xor_sync(0xffffffffu, sum, 2);
            clo += __shfl_xor_sync(0xffffffffu, clo, 1);
            clo += __shfl_xor_sync(0xffffffffu, clo, 2);
            chi += __shfl_xor_sync(0xffffffffu, chi, 1);
            chi += __shfl_xor_sync(0xffffffffu, chi, 2);
            if ((lane & 3) == 0) {
                exs[wn * 64 + row] = sum;
                exl[wn * 64 + row] = clo;
                exh[wn * 64 + row] = chi;
            }
        }
        __syncthreads();                       // sums + V ready

        #pragma unroll
        for (int rl = 0; rl < 2; rl++) {
            int row = rbase + 8 * rl;
            l[rl]   = l[rl]   * alpha[rl] + exs[row] + exs[64 + row];
            plo[rl] = plo[rl] * alpha[rl] + exl[row] + exl[64 + row];
            phi[rl] = phi[rl] * alpha[rl] + exh[row] + exh[64 + row];
        }
        // rescale ctx
        #pragma unroll
        for (int dnt = 0; dnt < 8; dnt++) {
            ctx[dnt][0] *= alpha[0]; ctx[dnt][1] *= alpha[0];
            ctx[dnt][2] *= alpha[1]; ctx[dnt][3] *= alpha[1];
        }

        // pack P fragments (hi/lo) from score C-frags
        u32 Ah[2][4], Al[2][4];
        #pragma unroll
        for (int kf = 0; kf < 2; kf++) {
            #pragma unroll
            for (int h = 0; h < 2; h++) {
                int nt = 2 * kf + h;
                u32 h0 = pkbf(c[nt][0], c[nt][1]);
                u32 h1 = pkbf(c[nt][2], c[nt][3]);
                Ah[kf][2 * h]     = h0;
                Ah[kf][2 * h + 1] = h1;
                Al[kf][2 * h]     = pkbf(c[nt][0] - bflo(h0), c[nt][1] - bfhi(h0));
                Al[kf][2 * h + 1] = pkbf(c[nt][2] - bflo(h1), c[nt][3] - bfhi(h1));
            }
        }

        // PV: ctx[16 rows x 64 dims] partial over this warp's 32 nseq
        {
            int vrow = 32 * wn + lane;
            u32 vb = smb + (u32)(KVHo + vrow * 128);
            u32 vsw = (u32)((vrow & 7) << 4);
            #pragma unroll
            for (int dnt = 0; dnt < 8; dnt++) {
                u32 vAddr = vb + (((u32)(dnt << 4)) ^ vsw);
                u32 bhv[4], blv[4];
                ldm_x4t(bhv[0], bhv[1], bhv[2], bhv[3], vAddr);
                ldm_x4t(blv[0], blv[1], blv[2], blv[3], vAddr + (KVLo - KVHo));
                #pragma unroll
                for (int kf = 0; kf < 2; kf++) {
                    mma_bf16(ctx[dnt], Ah[kf], bhv[2 * kf], bhv[2 * kf + 1]);
                    mma_bf16(ctx[dnt], Ah[kf], blv[2 * kf], blv[2 * kf + 1]);
                    mma_bf16(ctx[dnt], Al[kf], bhv[2 * kf], bhv[2 * kf + 1]);
                }
            }
        }
    }

    // ---- epilogue: combine warp-pair partials into CTX, stats to vectors ----
    __syncthreads();
    float* ctxp = (float*)(smc + CTXo);
    float* lv   = (float*)(smc + LVo);
    float* plv  = (float*)(smc + PLOo);
    float* phv  = (float*)(smc + PHIo);
    float* muv  = (float*)(smc + MUo);
    if (wn == 0) {
        #pragma unroll
        for (int dnt = 0; dnt < 8; dnt++) {
            int dbase = 8 * dnt + 2 * rb4;
            *(float2*)&ctxp[rbase * 64 + dbase]       = make_float2(ctx[dnt][0], ctx[dnt][1]);
            *(float2*)&ctxp[(rbase + 8) * 64 + dbase] = make_float2(ctx[dnt][2], ctx[dnt][3]);
        }
        if ((lane & 3) == 0) {
            #pragma unroll
            for (int rl = 0; rl < 2; rl++) {
                int row = rbase + 8 * rl;
                lv[row] = l[rl]; plv[row] = plo[rl];
                phv[row] = phi[rl]; muv[row] = mu[rl];
            }
        }
    }
    __syncthreads();
    if (wn == 1) {
        #pragma unroll
        for (int dnt = 0; dnt < 8; dnt++) {
            int dbase = 8 * dnt + 2 * rb4;
            float2 a0 = *(float2*)&ctxp[rbase * 64 + dbase];
            float2 a1 = *(float2*)&ctxp[(rbase + 8) * 64 + dbase];
            *(float2*)&ctxp[rbase * 64 + dbase] =
                make_float2(a0.x + ctx[dnt][0], a0.y + ctx[dnt][1]);
            *(float2*)&ctxp[(rbase + 8) * 64 + dbase] =
                make_float2(a1.x + ctx[dnt][2], a1.y + ctx[dnt][3]);
        }
    }
    __syncthreads();

    // ---- E-pass: W := exp(W - mu[m]) ----
    #pragma unroll 4
    for (int t = 0; t < 64; t++) {
        int idx = tid + t * 256;
        if (idx < 254 * 64) {
            int r = idx >> 6, m = idx & 63;
            float wv = __bfloat162float(smh[(Wo >> 1) + r * 66 + m]);
            smh[(Wo >> 1) + r * 66 + m] = __float2bfloat16(__expf(wv - muv[m]));
        }
    }
    __syncthreads();

    // ---- rve GEMM + final (ty/tx layout: rows ty*8.., dim pair tx*2) ----
    {
        const int ty = tid >> 5, tx = tid & 31;
        u64 o2[4][2];
        #pragma unroll
        for (int rp = 0; rp < 4; rp++)
            #pragma unroll
            for (int di = 0; di < 2; di++)
                o2[rp][di] = pk2(ctxp[(ty * 8 + 2 * rp) * 64 + tx * 2 + di],
                                 ctxp[(ty * 8 + 2 * rp + 1) * 64 + tx * 2 + di]);

        #pragma unroll 2
        for (int r = 0; r < 254; r++) {
            const __nv_bfloat162* wr =
                (const __nv_bfloat162*)&smh[(Wo >> 1) + r * 66 + ty * 8];
            __nv_bfloat162 e0 = wr[0], e1 = wr[1], e2 = wr[2], e3 = wr[3];
            float2 rv = __ldg((const float2*)(rve + (r + 1) * 64 + tx * 2));
            u64 r0 = dup2(rv.x), r1 = dup2(rv.y);
            float2 f0 = __bfloat1622float2(e0);
            float2 f1 = __bfloat1622float2(e1);
            float2 f2 = __bfloat1622float2(e2);
            float2 f3 = __bfloat1622float2(e3);
            u64 ep0 = pk2(f0.x, f0.y), ep1 = pk2(f1.x, f1.y);
            u64 ep2 = pk2(f2.x, f2.y), ep3 = pk2(f3.x, f3.y);
            o2[0][0] = ffma2(ep0, r0, o2[0][0]);
            o2[0][1] = ffma2(ep0, r1, o2[0][1]);
            o2[1][0] = ffma2(ep1, r0, o2[1][0]);
            o2[1][1] = ffma2(ep1, r1, o2[1][1]);
            o2[2][0] = ffma2(ep2, r0, o2[2][0]);
            o2[2][1] = ffma2(ep2, r1, o2[2][1]);
            o2[3][0] = ffma2(ep3, r0, o2[3][0]);
            o2[3][1] = ffma2(ep3, r1, o2[3][1]);
        }

        float2 rv0 = __ldg((const float2*)(rve + 0 * 64 + tx * 2));
        float2 rvN = __ldg((const float2*)(rve + 255 * 64 + tx * 2));
        #pragma unroll
        for (int rp = 0; rp < 4; rp++) {
            float2 c0 = up2(o2[rp][0]), c1 = up2(o2[rp][1]);
            #pragma unroll
            for (int h = 0; h < 2; h++) {
                int ri = 2 * rp + h;
                int row = ty * 8 + ri;
                float ox = h ? c0.y : c0.x;
                float oy = h ? c1.y : c1.x;
                float inv = 1.0f / lv[row];
                float2 res;
                res.x = (ox + plv[row] * rv0.x + phv[row] * rvN.x) * inv;
                res.y = (oy + plv[row] * rv0.y + phv[row] * rvN.y) * inv;
                *(float2*)(out + ((size_t)bz * Sn + i0 + row) * Hn + hq * 64 + tx * 2) = res;
            }
        }
    }
}

// ---------------------------------------------------------------------------
extern "C" void kernel_launch(void* const* d_in, const int* in_sizes, int n_in,
                              void* d_out, int out_size)
{
    const float* X    = (const float*)d_in[0];
    const float* mask = (const float*)d_in[1];
    const float* Wq   = (const float*)d_in[2];
    const float* bq   = (const float*)d_in[3];
    const float* Wk   = (const float*)d_in[4];
    const float* bk   = (const float*)d_in[5];
    const float* Wv   = (const float*)d_in[6];
    const float* bv   = (const float*)d_in[7];
    const float* rke  = (const float*)d_in[8];
    const float* rve  = (const float*)d_in[9];
    float* out = (float*)d_out;

    (void)in_sizes; (void)n_in; (void)out_size;

    cudaFuncSetAttribute(attn_kernel,
                         cudaFuncAttributeMaxDynamicSharedMemorySize, SMEMB);

    qkv_kernel<<<dim3(32, 6, 3), 256>>>(X, Wq, bq, Wk, bk, Wv, bv);
    attn_kernel<<<dim3(32, NHn, Bn), 256, SMEMB>>>(mask, rke, rve, out);
}

// round 10
// speedup vs baseline: 1.6613x; 1.0546x over previous
#include <cuda_runtime.h>
#include <cuda_bf16.h>

// ---------------------------------------------------------------------------
// GraphEncoder relative-position attention, GB300 sm_103a — round 10
// R9 HMMA flash attention (unchanged) + NEW: HMMA split-bf16 QKV projection
// reusing the same 64x64 tile machinery (A=X chunk, B=W^T chunk).
// ---------------------------------------------------------------------------

namespace {
constexpr int Bn  = 2;
constexpr int Sn  = 2048;
constexpr int Hn  = 768;
constexpr int NHn = 12;

// smem byte offsets (attention)
constexpr int QHo   = 0;         // Q hi plane  64x64 bf16 (8192)
constexpr int QLo   = 8192;      // Q lo plane
constexpr int KVHo  = 16384;     // K/V hi plane (shared)
constexpr int KVLo  = 24576;     // K/V lo plane
constexpr int RELCo = 32768;     // relc bf16 [64][256]  (32768)
constexpr int Wo    = 65536;     // W bf16 [254][66]     (33528)
constexpr int EXMo  = 99064;     // f32 [2][64] half-max
constexpr int EXSo  = 99576;     // f32 [2][64] half-sum
constexpr int EXLo  = 100088;    // f32 [2][64] clamp-lo
constexpr int EXHo  = 100600;    // f32 [2][64] clamp-hi
constexpr int SMEMB = 101112;
// epilogue overlays
constexpr int CTXo  = 0;
constexpr int LVo   = 16384;
constexpr int PLOo  = 16640;
constexpr int PHIo  = 16896;
constexpr int MUo   = 17152;
// qkv kernel uses planes QHo/QLo (X) and KVHo/KVLo (W^T): 32768 B static.
}

__device__ float g_Q[Bn * NHn * Sn * 64];
__device__ float g_K[Bn * NHn * Sn * 64];
__device__ float g_V[Bn * NHn * Sn * 64];

typedef unsigned long long u64;
typedef unsigned int u32;

__device__ __forceinline__ u64 pk2(float lo, float hi) {
    u64 r; asm("mov.b64 %0,{%1,%2};" : "=l"(r) : "f"(lo), "f"(hi)); return r;
}
__device__ __forceinline__ u64 dup2(float v) { return pk2(v, v); }
__device__ __forceinline__ u64 ffma2(u64 a, u64 b, u64 c) {
    u64 d; asm("fma.rn.f32x2 %0,%1,%2,%3;" : "=l"(d) : "l"(a), "l"(b), "l"(c)); return d;
}
__device__ __forceinline__ float2 up2(u64 v) {
    float2 f; asm("mov.b64 {%0,%1},%2;" : "=f"(f.x), "=f"(f.y) : "l"(v)); return f;
}
__device__ __forceinline__ u32 pkbf(float lo, float hi) {
    u32 d; asm("cvt.rn.bf16x2.f32 %0,%1,%2;" : "=r"(d) : "f"(hi), "f"(lo)); return d;
}
__device__ __forceinline__ float bflo(u32 h) { return __uint_as_float(h << 16); }
__device__ __forceinline__ float bfhi(u32 h) { return __uint_as_float(h & 0xFFFF0000u); }

__device__ __forceinline__ void ldm_x4(u32& r0, u32& r1, u32& r2, u32& r3, u32 a) {
    asm volatile("ldmatrix.sync.aligned.m8n8.x4.shared.b16 {%0,%1,%2,%3},[%4];"
                 : "=r"(r0), "=r"(r1), "=r"(r2), "=r"(r3) : "r"(a));
}
__device__ __forceinline__ void ldm_x2(u32& r0, u32& r1, u32 a) {
    asm volatile("ldmatrix.sync.aligned.m8n8.x2.shared.b16 {%0,%1},[%2];"
                 : "=r"(r0), "=r"(r1) : "r"(a));
}
__device__ __forceinline__ void ldm_x4t(u32& r0, u32& r1, u32& r2, u32& r3, u32 a) {
    asm volatile("ldmatrix.sync.aligned.m8n8.x4.trans.shared.b16 {%0,%1,%2,%3},[%4];"
                 : "=r"(r0), "=r"(r1), "=r"(r2), "=r"(r3) : "r"(a));
}
__device__ __forceinline__ void mma_bf16(float* d, const u32* a, u32 b0, u32 b1) {
    asm volatile("mma.sync.aligned.m16n8k16.row.col.f32.bf16.bf16.f32 "
                 "{%0,%1,%2,%3},{%4,%5,%6,%7},{%8,%9},{%0,%1,%2,%3};"
                 : "+f"(d[0]), "+f"(d[1]), "+f"(d[2]), "+f"(d[3])
                 : "r"(a[0]), "r"(a[1]), "r"(a[2]), "r"(a[3]), "r"(b0), "r"(b1));
}

// load 64x64 f32 tile (row stride `stride`) -> hi/lo bf16 planes, swizzled
__device__ __forceinline__ void load_split_s(const float* __restrict__ src,
                                             int stride, char* smc,
                                             int hiOff, int loOff, int tid)
{
    #pragma unroll
    for (int s = 0; s < 4; s++) {
        int f = tid + s * 256;
        int row = f >> 4, cg = f & 15;
        float4 v = *(const float4*)(src + row * stride + cg * 4);
        __nv_bfloat162 h0 = __floats2bfloat162_rn(v.x, v.y);
        __nv_bfloat162 h1 = __floats2bfloat162_rn(v.z, v.w);
        float2 f0 = __bfloat1622float2(h0);
        float2 f1 = __bfloat1622float2(h1);
        __nv_bfloat162 l0 = __floats2bfloat162_rn(v.x - f0.x, v.y - f0.y);
        __nv_bfloat162 l1 = __floats2bfloat162_rn(v.z - f1.x, v.w - f1.y);
        int off = row * 128 + (((cg >> 1) ^ (row & 7)) << 4) + ((cg & 1) << 3);
        *(__nv_bfloat162*)(smc + hiOff + off)     = h0;
        *(__nv_bfloat162*)(smc + hiOff + off + 4) = h1;
        *(__nv_bfloat162*)(smc + loOff + off)     = l0;
        *(__nv_bfloat162*)(smc + loOff + off + 4) = l1;
    }
}
__device__ __forceinline__ void load_split64(const float* __restrict__ src,
                                             char* smc, int hiOff, int loOff, int tid)
{
    load_split_s(src, 64, smc, hiOff, loOff, tid);
}

// 64x64x64 split-bf16 GEMM step: c[nt][e] += A[16wm rows] . B[32wn cols]
// A planes at QHo/QLo, B planes at KVHo/KVLo. Accumulates into c.
__device__ __forceinline__ void mma_scores(float c[4][4], u32 smb,
                                           int wm, int wn, int lane)
{
    const int r8 = lane & 7;
    const int j4 = lane >> 3;
    const int jb = (lane >> 3) & 1;
    #pragma unroll
    for (int ks = 0; ks < 4; ks++) {
        int mrow = 16 * wm + r8 + (j4 & 1) * 8;
        int chA = 2 * ks + (j4 >> 1);
        u32 aAddr = smb + (u32)(QHo + mrow * 128 + ((chA ^ (mrow & 7)) << 4));
        u32 ah[4], al[4];
        ldm_x4(ah[0], ah[1], ah[2], ah[3], aAddr);
        ldm_x4(al[0], al[1], al[2], al[3], aAddr + (QLo - QHo));
        #pragma unroll
        for (int nt = 0; nt < 4; nt++) {
            int n = 32 * wn + 8 * nt + r8;
            int chB = 2 * ks + jb;
            u32 bAddr = smb + (u32)(KVHo + n * 128 + ((chB ^ (n & 7)) << 4));
            u32 bh0, bh1, bl0, bl1;
            ldm_x2(bh0, bh1, bAddr);
            ldm_x2(bl0, bl1, bAddr + (KVLo - KVHo));
            mma_bf16(c[nt], ah, bh0, bh1);
            mma_bf16(c[nt], ah, bl0, bl1);
            mma_bf16(c[nt], al, bh0, bh1);
        }
    }
}

// ---------------------------------------------------------------------------
// Kernel 1: HMMA QKV projection. Grid (64, 12, 3): 64 row-tiles, 12 heads,
// z = Q/K/V. C tile 64x64, K looped 12 chunks of 64.
// ---------------------------------------------------------------------------
__global__ __launch_bounds__(256) void qkv_kernel(
    const float* __restrict__ X,
    const float* __restrict__ Wq, const float* __restrict__ bq,
    const float* __restrict__ Wk, const float* __restrict__ bk,
    const float* __restrict__ Wv, const float* __restrict__ bv)
{
    __shared__ char smc[32768];
    const u32 smb = (u32)__cvta_generic_to_shared(smc);

    const int z = blockIdx.z;
    const float* Wp   = (z == 0) ? Wq : ((z == 1) ? Wk : Wv);
    const float* bp   = (z == 0) ? bq : ((z == 1) ? bk : bv);
    float*       outp = (z == 0) ? g_Q : ((z == 1) ? g_K : g_V);
    const float  sc   = (z == 0) ? 0.125f : 1.0f;

    const int r0 = blockIdx.x * 64;
    const int hq = blockIdx.y;
    const int n0 = hq * 64;
    const int tid = threadIdx.x;
    const int lane = tid & 31;
    const int w = tid >> 5, wm = w & 3, wn = w >> 2;
    const int rb4 = lane & 3, rd4 = lane >> 2;

    float c[4][4] = {};

    for (int kt = 0; kt < 12; kt++) {
        __syncthreads();   // previous MMA reads done
        // A = X[r0..+63][kt*64..+63]
        load_split_s(X + (size_t)r0 * 768 + kt * 64, 768, smc, QHo, QLo, tid);
        // B = W^T chunk: smem[n][k] <- W[kt*64+k][n0+n], pair-packed along k
        #pragma unroll
        for (int it = 0; it < 2; it++) {
            int f = tid + it * 256;
            int kp = f >> 4, ng = f & 15;
            int k0 = 2 * kp, nn = ng * 4;
            const float* w0 = Wp + (size_t)(kt * 64 + k0) * 768 + n0 + nn;
            float4 a = *(const float4*)(w0);
            float4 b = *(const float4*)(w0 + 768);
            float av[4] = {a.x, a.y, a.z, a.w};
            float bv_[4] = {b.x, b.y, b.z, b.w};
            #pragma unroll
            for (int i = 0; i < 4; i++) {
                int ni = nn + i;
                u32 hp = pkbf(av[i], bv_[i]);               // (k0, k0+1)
                u32 lp = pkbf(av[i] - bflo(hp), bv_[i] - bfhi(hp));
                int off = ni * 128 + ((((k0 >> 3)) ^ (ni & 7)) << 4) + (k0 & 7) * 2;
                *(u32*)(smc + KVHo + off) = hp;
                *(u32*)(smc + KVLo + off) = lp;
            }
        }
        __syncthreads();
        mma_scores(c, smb, wm, wn, lane);
    }

    // epilogue: bias, scale, scatter to [B,NH,S,64]
    #pragma unroll
    for (int nt = 0; nt < 4; nt++) {
        int d = 32 * wn + 8 * nt + 2 * rb4;
        float b0 = bp[n0 + d], b1 = bp[n0 + d + 1];
        #pragma unroll
        for (int half = 0; half < 2; half++) {
            int r = r0 + 16 * wm + rd4 + 8 * half;
            int b = r >> 11, s = r & 2047;
            float2 res;
            res.x = (c[nt][2 * half + 0] + b0) * sc;
            res.y = (c[nt][2 * half + 1] + b1) * sc;
            *(float2*)(outp + ((size_t)(b * NHn + hq) * Sn + s) * 64 + d) = res;
        }
    }
}

// ---------------------------------------------------------------------------
// Kernel 2: HMMA flash attention (unchanged from R9).
// ---------------------------------------------------------------------------
__global__ __launch_bounds__(256, 2) void attn_kernel(
    const float* __restrict__ mask,
    const float* __restrict__ rke,
    const float* __restrict__ rve,
    float* __restrict__ out)
{
    extern __shared__ char smc[];
    __nv_bfloat16* smh = (__nv_bfloat16*)smc;
    const u32 smb = (u32)__cvta_generic_to_shared(smc);

    const int tid = threadIdx.x;
    const int lane = tid & 31;
    const int w = tid >> 5, wm = w & 3, wn = w >> 2;
    const int hq = blockIdx.y, bz = blockIdx.z;
    const int bh = bz * NHn + hq;
    const int i0 = blockIdx.x * 64;

    const float* Qg = g_Q + ((size_t)bh * Sn + i0) * 64;
    const float* Kg = g_K + (size_t)bh * Sn * 64;
    const float* Vg = g_V + (size_t)bh * Sn * 64;
    const float* maskg = mask + (size_t)bz * Sn;

    float* exm = (float*)(smc + EXMo);
    float* exs = (float*)(smc + EXSo);
    float* exl = (float*)(smc + EXLo);
    float* exh = (float*)(smc + EXHo);

    {
        __nv_bfloat16 hneg = __float2bfloat16(-1e30f);
        unsigned short us = __bfloat16_as_ushort(hneg);
        u32 vv = (u32)us | ((u32)us << 16);
        u32* w32 = (u32*)(smc + Wo);
        #pragma unroll
        for (int t = 0; t < 32; t++) w32[tid + t * 256] = vv;
        if (tid < 8382 - 32 * 256) w32[tid + 32 * 256] = vv;
    }

    load_split64(Qg, smc, QHo, QLo, tid);
    __syncthreads();

    const int rb4 = lane & 3, rd4 = lane >> 2;
    for (int rb = 0; rb < 4; rb++) {
        load_split64(rke + rb * 64 * 64, smc, KVHo, KVLo, tid);
        __syncthreads();
        float c[4][4] = {};
        mma_scores(c, smb, wm, wn, lane);
        #pragma unroll
        for (int nt = 0; nt < 4; nt++) {
            #pragma unroll
            for (int e = 0; e < 4; e++) {
                int m = 16 * wm + rd4 + (e >> 1) * 8;
                int r = rb * 64 + 32 * wn + 8 * nt + 2 * rb4 + (e & 1);
                smh[(RELCo >> 1) + m * 256 + r] = __float2bfloat16(c[nt][e]);
            }
        }
        __syncthreads();
    }

    float ctx[8][4] = {};
    float mu[2] = {-1e30f, -1e30f}, l[2] = {}, plo[2] = {}, phi[2] = {};
    const int rbase = 16 * wm + rd4;

    for (int jt = 0; jt < 32; jt++) {
        const int j0 = jt * 64;
        const int doff = j0 - i0;
        __syncthreads();
        load_split64(Kg + (size_t)j0 * 64, smc, KVHo, KVLo, tid);
        __syncthreads();

        float c[4][4] = {};
        mma_scores(c, smb, wm, wn, lane);

        float mb[4][2];
        #pragma unroll
        for (int nt = 0; nt < 4; nt++) {
            float2 mv = __ldg((const float2*)(maskg + j0 + 32 * wn + 8 * nt + 2 * rb4));
            mb[nt][0] = (1.0f - mv.x) * -10000.0f;
            mb[nt][1] = (1.0f - mv.y) * -10000.0f;
        }

        const bool pure_lo = (doff + 63 <= -128);
        const bool pure_hi = (doff - 63 >= 127);
        if (pure_lo || pure_hi) {
            const int b = pure_lo ? 0 : 255;
            float rb0 = __bfloat162float(smh[(RELCo >> 1) + rbase * 256 + b]);
            float rb1 = __bfloat162float(smh[(RELCo >> 1) + (rbase + 8) * 256 + b]);
            #pragma unroll
            for (int nt = 0; nt < 4; nt++)
                #pragma unroll
                for (int e = 0; e < 4; e++)
                    c[nt][e] += ((e >> 1) ? rb1 : rb0) + mb[nt][e & 1];
        } else {
            #pragma unroll
            for (int nt = 0; nt < 4; nt++) {
                #pragma unroll
                for (int e = 0; e < 4; e++) {
                    int row = rbase + (e >> 1) * 8;
                    int col = 32 * wn + 8 * nt + 2 * rb4 + (e & 1);
                    int dlt = doff + col - row;
                    int bkt = max(-128, min(127, dlt)) + 128;
                    c[nt][e] += __bfloat162float(
                                    smh[(RELCo >> 1) + row * 256 + bkt]) + mb[nt][e & 1];
                    if (dlt > -128 && dlt < 127)
                        smh[(Wo >> 1) + (dlt + 127) * 66 + row] = __float2bfloat16(c[nt][e]);
                }
            }
        }

        float lm[2];
        #pragma unroll
        for (int rl = 0; rl < 2; rl++) {
            float m0 = fmaxf(fmaxf(c[0][2 * rl], c[0][2 * rl + 1]),
                             fmaxf(c[1][2 * rl], c[1][2 * rl + 1]));
            float m1 = fmaxf(fmaxf(c[2][2 * rl], c[2][2 * rl + 1]),
                             fmaxf(c[3][2 * rl], c[3][2 * rl + 1]));
            float v = fmaxf(m0, m1);
            v = fmaxf(v, __shfl_xor_sync(0xffffffffu, v, 1));
            v = fmaxf(v, __shfl_xor_sync(0xffffffffu, v, 2));
            lm[rl] = v;
        }
        if ((lane & 3) == 0) {
            exm[wn * 64 + rbase]     = lm[0];
            exm[wn * 64 + rbase + 8] = lm[1];
        }
        __syncthreads();

        load_split64(Vg + (size_t)j0 * 64, smc, KVHo, KVLo, tid);

        float alpha[2];
        #pragma unroll
        for (int rl = 0; rl < 2; rl++) {
            int row = rbase + 8 * rl;
            float nm = fmaxf(mu[rl], fmaxf(exm[row], exm[64 + row]));
            alpha[rl] = __expf(mu[rl] - nm);
            mu[rl] = nm;
            float sum = 0.f, clo = 0.f, chi = 0.f;
            #pragma unroll
            for (int nt = 0; nt < 4; nt++) {
                #pragma unroll
                for (int h = 0; h < 2; h++) {
                    int e = 2 * rl + h;
                    float p = __expf(c[nt][e] - nm);
                    c[nt][e] = p;
                    sum += p;
                    int col = 32 * wn + 8 * nt + 2 * rb4 + h;
                    int dlt = doff + col - row;
                    if (dlt <= -128)     clo += p;
                    else if (dlt >= 127) chi += p;
                }
            }
            sum += __shfl_xor_sync(0xffffffffu, sum, 1);
            sum += __shfl_xor_sync(0xffffffffu, sum, 2);
            clo += __shfl_xor_sync(0xffffffffu, clo, 1);
            clo += __shfl_xor_sync(0xffffffffu, clo, 2);
            chi += __shfl_xor_sync(0xffffffffu, chi, 1);
            chi += __shfl_xor_sync(0xffffffffu, chi, 2);
            if ((lane & 3) == 0) {
                exs[wn * 64 + row] = sum;
                exl[wn * 64 + row] = clo;
                exh[wn * 64 + row] = chi;
            }
        }
        __syncthreads();

        #pragma unroll
        for (int rl = 0; rl < 2; rl++) {
            int row = rbase + 8 * rl;
            l[rl]   = l[rl]   * alpha[rl] + exs[row] + exs[64 + row];
            plo[rl] = plo[rl] * alpha[rl] + exl[row] + exl[64 + row];
            phi[rl] = phi[rl] * alpha[rl] + exh[row] + exh[64 + row];
        }
        #pragma unroll
        for (int dnt = 0; dnt < 8; dnt++) {
            ctx[dnt][0] *= alpha[0]; ctx[dnt][1] *= alpha[0];
            ctx[dnt][2] *= alpha[1]; ctx[dnt][3] *= alpha[1];
        }

        u32 Ah[2][4], Al[2][4];
        #pragma unroll
        for (int kf = 0; kf < 2; kf++) {
            #pragma unroll
            for (int h = 0; h < 2; h++) {
                int nt = 2 * kf + h;
                u32 h0 = pkbf(c[nt][0], c[nt][1]);
                u32 h1 = pkbf(c[nt][2], c[nt][3]);
                Ah[kf][2 * h]     = h0;
                Ah[kf][2 * h + 1] = h1;
                Al[kf][2 * h]     = pkbf(c[nt][0] - bflo(h0), c[nt][1] - bfhi(h0));
                Al[kf][2 * h + 1] = pkbf(c[nt][2] - bflo(h1), c[nt][3] - bfhi(h1));
            }
        }

        {
            int vrow = 32 * wn + lane;
            u32 vb = smb + (u32)(KVHo + vrow * 128);
            u32 vsw = (u32)((vrow & 7) << 4);
            #pragma unroll
            for (int dnt = 0; dnt < 8; dnt++) {
                u32 vAddr = vb + (((u32)(dnt << 4)) ^ vsw);
                u32 bhv[4], blv[4];
                ldm_x4t(bhv[0], bhv[1], bhv[2], bhv[3], vAddr);
                ldm_x4t(blv[0], blv[1], blv[2], blv[3], vAddr + (KVLo - KVHo));
                #pragma unroll
                for (int kf = 0; kf < 2; kf++) {
                    mma_bf16(ctx[dnt], Ah[kf], bhv[2 * kf], bhv[2 * kf + 1]);
                    mma_bf16(ctx[dnt], Ah[kf], blv[2 * kf], blv[2 * kf + 1]);
                    mma_bf16(ctx[dnt], Al[kf], bhv[2 * kf], bhv[2 * kf + 1]);
                }
            }
        }
    }

    __syncthreads();
    float* ctxp = (float*)(smc + CTXo);
    float* lv   = (float*)(smc + LVo);
    float* plv  = (float*)(smc + PLOo);
    float* phv  = (float*)(smc + PHIo);
    float* muv  = (float*)(smc + MUo);
    if (wn == 0) {
        #pragma unroll
        for (int dnt = 0; dnt < 8; dnt++) {
            int dbase = 8 * dnt + 2 * rb4;
            *(float2*)&ctxp[rbase * 64 + dbase]       = make_float2(ctx[dnt][0], ctx[dnt][1]);
            *(float2*)&ctxp[(rbase + 8) * 64 + dbase] = make_float2(ctx[dnt][2], ctx[dnt][3]);
        }
        if ((lane & 3) == 0) {
            #pragma unroll
            for (int rl = 0; rl < 2; rl++) {
                int row = rbase + 8 * rl;
                lv[row] = l[rl]; plv[row] = plo[rl];
                phv[row] = phi[rl]; muv[row] = mu[rl];
            }
        }
    }
    __syncthreads();
    if (wn == 1) {
        #pragma unroll
        for (int dnt = 0; dnt < 8; dnt++) {
            int dbase = 8 * dnt + 2 * rb4;
            float2 a0 = *(float2*)&ctxp[rbase * 64 + dbase];
            float2 a1 = *(float2*)&ctxp[(rbase + 8) * 64 + dbase];
            *(float2*)&ctxp[rbase * 64 + dbase] =
                make_float2(a0.x + ctx[dnt][0], a0.y + ctx[dnt][1]);
            *(float2*)&ctxp[(rbase + 8) * 64 + dbase] =
                make_float2(a1.x + ctx[dnt][2], a1.y + ctx[dnt][3]);
        }
    }
    __syncthreads();

    #pragma unroll 4
    for (int t = 0; t < 64; t++) {
        int idx = tid + t * 256;
        if (idx < 254 * 64) {
            int r = idx >> 6, m = idx & 63;
            float wv = __bfloat162float(smh[(Wo >> 1) + r * 66 + m]);
            smh[(Wo >> 1) + r * 66 + m] = __float2bfloat16(__expf(wv - muv[m]));
        }
    }
    __syncthreads();

    {
        const int ty = tid >> 5, tx = tid & 31;
        u64 o2[4][2];
        #pragma unroll
        for (int rp = 0; rp < 4; rp++)
            #pragma unroll
            for (int di = 0; di < 2; di++)
                o2[rp][di] = pk2(ctxp[(ty * 8 + 2 * rp) * 64 + tx * 2 + di],
                                 ctxp[(ty * 8 + 2 * rp + 1) * 64 + tx * 2 + di]);

        #pragma unroll 2
        for (int r = 0; r < 254; r++) {
            const __nv_bfloat162* wr =
                (const __nv_bfloat162*)&smh[(Wo >> 1) + r * 66 + ty * 8];
            __nv_bfloat162 e0 = wr[0], e1 = wr[1], e2 = wr[2], e3 = wr[3];
            float2 rv = __ldg((const float2*)(rve + (r + 1) * 64 + tx * 2));
            u64 r0 = dup2(rv.x), r1 = dup2(rv.y);
            float2 f0 = __bfloat1622float2(e0);
            float2 f1 = __bfloat1622float2(e1);
            float2 f2 = __bfloat1622float2(e2);
            float2 f3 = __bfloat1622float2(e3);
            u64 ep0 = pk2(f0.x, f0.y), ep1 = pk2(f1.x, f1.y);
            u64 ep2 = pk2(f2.x, f2.y), ep3 = pk2(f3.x, f3.y);
            o2[0][0] = ffma2(ep0, r0, o2[0][0]);
            o2[0][1] = ffma2(ep0, r1, o2[0][1]);
            o2[1][0] = ffma2(ep1, r0, o2[1][0]);
            o2[1][1] = ffma2(ep1, r1, o2[1][1]);
            o2[2][0] = ffma2(ep2, r0, o2[2][0]);
            o2[2][1] = ffma2(ep2, r1, o2[2][1]);
            o2[3][0] = ffma2(ep3, r0, o2[3][0]);
            o2[3][1] = ffma2(ep3, r1, o2[3][1]);
        }

        float2 rv0 = __ldg((const float2*)(rve + 0 * 64 + tx * 2));
        float2 rvN = __ldg((const float2*)(rve + 255 * 64 + tx * 2));
        #pragma unroll
        for (int rp = 0; rp < 4; rp++) {
            float2 c0 = up2(o2[rp][0]), c1 = up2(o2[rp][1]);
            #pragma unroll
            for (int h = 0; h < 2; h++) {
                int ri = 2 * rp + h;
                int row = ty * 8 + ri;
                float ox = h ? c0.y : c0.x;
                float oy = h ? c1.y : c1.x;
                float inv = 1.0f / lv[row];
                float2 res;
                res.x = (ox + plv[row] * rv0.x + phv[row] * rvN.x) * inv;
                res.y = (oy + plv[row] * rv0.y + phv[row] * rvN.y) * inv;
                *(float2*)(out + ((size_t)bz * Sn + i0 + row) * Hn + hq * 64 + tx * 2) = res;
            }
        }
    }
}

// ---------------------------------------------------------------------------
extern "C" void kernel_launch(void* const* d_in, const int* in_sizes, int n_in,
                              void* d_out, int out_size)
{
    const float* X    = (const float*)d_in[0];
    const float* mask = (const float*)d_in[1];
    const float* Wq   = (const float*)d_in[2];
    const float* bq   = (const float*)d_in[3];
    const float* Wk   = (const float*)d_in[4];
    const float* bk   = (const float*)d_in[5];
    const float* Wv   = (const float*)d_in[6];
    const float* bv   = (const float*)d_in[7];
    const float* rke  = (const float*)d_in[8];
    const float* rve  = (const float*)d_in[9];
    float* out = (float*)d_out;

    (void)in_sizes; (void)n_in; (void)out_size;

    cudaFuncSetAttribute(attn_kernel,
                         cudaFuncAttributeMaxDynamicSharedMemorySize, SMEMB);

    qkv_kernel<<<dim3(64, NHn, 3), 256>>>(X, Wq, bq, Wk, bk, Wv, bv);
    attn_kernel<<<dim3(32, NHn, Bn), 256, SMEMB>>>(mask, rke, rve, out);
}

// round 11
// speedup vs baseline: 1.6781x; 1.0101x over previous
#include <cuda_runtime.h>
#include <cuda_bf16.h>

// ---------------------------------------------------------------------------
// GraphEncoder relative-position attention, GB300 sm_103a — round 11
// R10 HMMA kernels + register-staged prefetch (K/V and X/W tiles LDG'd into
// registers one stage ahead) + clamp-mass tile-class specialization.
// ---------------------------------------------------------------------------

namespace {
constexpr int Bn  = 2;
constexpr int Sn  = 2048;
constexpr int Hn  = 768;
constexpr int NHn = 12;

// smem byte offsets (attention)
constexpr int QHo   = 0;         // Q hi plane  64x64 bf16 (8192)
constexpr int QLo   = 8192;      // Q lo plane
constexpr int KVHo  = 16384;     // K/V hi plane (shared)
constexpr int KVLo  = 24576;     // K/V lo plane
constexpr int RELCo = 32768;     // relc bf16 [64][256]  (32768)
constexpr int Wo    = 65536;     // W bf16 [254][66]     (33528)
constexpr int EXMo  = 99064;     // f32 [2][64] half-max
constexpr int EXSo  = 99576;     // f32 [2][64] half-sum
constexpr int EXLo  = 100088;    // f32 [2][64] clamp-lo
constexpr int EXHo  = 100600;    // f32 [2][64] clamp-hi
constexpr int SMEMB = 101112;
// epilogue overlays
constexpr int CTXo  = 0;
constexpr int LVo   = 16384;
constexpr int PLOo  = 16640;
constexpr int PHIo  = 16896;
constexpr int MUo   = 17152;
}

__device__ float g_Q[Bn * NHn * Sn * 64];
__device__ float g_K[Bn * NHn * Sn * 64];
__device__ float g_V[Bn * NHn * Sn * 64];

typedef unsigned long long u64;
typedef unsigned int u32;

__device__ __forceinline__ u64 pk2(float lo, float hi) {
    u64 r; asm("mov.b64 %0,{%1,%2};" : "=l"(r) : "f"(lo), "f"(hi)); return r;
}
__device__ __forceinline__ u64 dup2(float v) { return pk2(v, v); }
__device__ __forceinline__ u64 ffma2(u64 a, u64 b, u64 c) {
    u64 d; asm("fma.rn.f32x2 %0,%1,%2,%3;" : "=l"(d) : "l"(a), "l"(b), "l"(c)); return d;
}
__device__ __forceinline__ float2 up2(u64 v) {
    float2 f; asm("mov.b64 {%0,%1},%2;" : "=f"(f.x), "=f"(f.y) : "l"(v)); return f;
}
__device__ __forceinline__ u32 pkbf(float lo, float hi) {
    u32 d; asm("cvt.rn.bf16x2.f32 %0,%1,%2;" : "=r"(d) : "f"(hi), "f"(lo)); return d;
}
__device__ __forceinline__ float bflo(u32 h) { return __uint_as_float(h << 16); }
__device__ __forceinline__ float bfhi(u32 h) { return __uint_as_float(h & 0xFFFF0000u); }

__device__ __forceinline__ void ldm_x4(u32& r0, u32& r1, u32& r2, u32& r3, u32 a) {
    asm volatile("ldmatrix.sync.aligned.m8n8.x4.shared.b16 {%0,%1,%2,%3},[%4];"
                 : "=r"(r0), "=r"(r1), "=r"(r2), "=r"(r3) : "r"(a));
}
__device__ __forceinline__ void ldm_x2(u32& r0, u32& r1, u32 a) {
    asm volatile("ldmatrix.sync.aligned.m8n8.x2.shared.b16 {%0,%1},[%2];"
                 : "=r"(r0), "=r"(r1) : "r"(a));
}
__device__ __forceinline__ void ldm_x4t(u32& r0, u32& r1, u32& r2, u32& r3, u32 a) {
    asm volatile("ldmatrix.sync.aligned.m8n8.x4.trans.shared.b16 {%0,%1,%2,%3},[%4];"
                 : "=r"(r0), "=r"(r1), "=r"(r2), "=r"(r3) : "r"(a));
}
__device__ __forceinline__ void mma_bf16(float* d, const u32* a, u32 b0, u32 b1) {
    asm volatile("mma.sync.aligned.m16n8k16.row.col.f32.bf16.bf16.f32 "
                 "{%0,%1,%2,%3},{%4,%5,%6,%7},{%8,%9},{%0,%1,%2,%3};"
                 : "+f"(d[0]), "+f"(d[1]), "+f"(d[2]), "+f"(d[3])
                 : "r"(a[0]), "r"(a[1]), "r"(a[2]), "r"(a[3]), "r"(b0), "r"(b1));
}

// ---- tile staging: LDG into registers / convert+STS to hi/lo planes ----
__device__ __forceinline__ void ldg_tile_s(const float* __restrict__ src,
                                           int stride, float4 v[4], int tid)
{
    #pragma unroll
    for (int s = 0; s < 4; s++) {
        int f = tid + s * 256;
        v[s] = __ldg((const float4*)(src + (size_t)(f >> 4) * stride + (f & 15) * 4));
    }
}
__device__ __forceinline__ void sts_split(const float4 v[4], char* smc,
                                          int hiOff, int loOff, int tid)
{
    #pragma unroll
    for (int s = 0; s < 4; s++) {
        int f = tid + s * 256;
        int row = f >> 4, cg = f & 15;
        float4 w = v[s];
        __nv_bfloat162 h0 = __floats2bfloat162_rn(w.x, w.y);
        __nv_bfloat162 h1 = __floats2bfloat162_rn(w.z, w.w);
        float2 f0 = __bfloat1622float2(h0);
        float2 f1 = __bfloat1622float2(h1);
        __nv_bfloat162 l0 = __floats2bfloat162_rn(w.x - f0.x, w.y - f0.y);
        __nv_bfloat162 l1 = __floats2bfloat162_rn(w.z - f1.x, w.w - f1.y);
        int off = row * 128 + (((cg >> 1) ^ (row & 7)) << 4) + ((cg & 1) << 3);
        *(__nv_bfloat162*)(smc + hiOff + off)     = h0;
        *(__nv_bfloat162*)(smc + hiOff + off + 4) = h1;
        *(__nv_bfloat162*)(smc + loOff + off)     = l0;
        *(__nv_bfloat162*)(smc + loOff + off + 4) = l1;
    }
}
__device__ __forceinline__ void load_split_s(const float* __restrict__ src,
                                             int stride, char* smc,
                                             int hiOff, int loOff, int tid)
{
    float4 v[4];
    ldg_tile_s(src, stride, v, tid);
    sts_split(v, smc, hiOff, loOff, tid);
}
__device__ __forceinline__ void load_split64(const float* __restrict__ src,
                                             char* smc, int hiOff, int loOff, int tid)
{
    load_split_s(src, 64, smc, hiOff, loOff, tid);
}

// 64x64x64 split-bf16 GEMM step: c[nt][e] += A[16wm rows] . B[32wn cols]
__device__ __forceinline__ void mma_scores(float c[4][4], u32 smb,
                                           int wm, int wn, int lane)
{
    const int r8 = lane & 7;
    const int j4 = lane >> 3;
    const int jb = (lane >> 3) & 1;
    #pragma unroll
    for (int ks = 0; ks < 4; ks++) {
        int mrow = 16 * wm + r8 + (j4 & 1) * 8;
        int chA = 2 * ks + (j4 >> 1);
        u32 aAddr = smb + (u32)(QHo + mrow * 128 + ((chA ^ (mrow & 7)) << 4));
        u32 ah[4], al[4];
        ldm_x4(ah[0], ah[1], ah[2], ah[3], aAddr);
        ldm_x4(al[0], al[1], al[2], al[3], aAddr + (QLo - QHo));
        #pragma unroll
        for (int nt = 0; nt < 4; nt++) {
            int n = 32 * wn + 8 * nt + r8;
            int chB = 2 * ks + jb;
            u32 bAddr = smb + (u32)(KVHo + n * 128 + ((chB ^ (n & 7)) << 4));
            u32 bh0, bh1, bl0, bl1;
            ldm_x2(bh0, bh1, bAddr);
            ldm_x2(bl0, bl1, bAddr + (KVLo - KVHo));
            mma_bf16(c[nt], ah, bh0, bh1);
            mma_bf16(c[nt], ah, bl0, bl1);
            mma_bf16(c[nt], al, bh0, bh1);
        }
    }
}

// ---------------------------------------------------------------------------
// Kernel 1: HMMA QKV projection with register-staged prefetch.
// Grid (64, 12, 3). C tile 64x64, K looped 12 chunks of 64.
// ---------------------------------------------------------------------------
__global__ __launch_bounds__(256) void qkv_kernel(
    const float* __restrict__ X,
    const float* __restrict__ Wq, const float* __restrict__ bq,
    const float* __restrict__ Wk, const float* __restrict__ bk,
    const float* __restrict__ Wv, const float* __restrict__ bv)
{
    __shared__ char smc[32768];
    const u32 smb = (u32)__cvta_generic_to_shared(smc);

    const int z = blockIdx.z;
    const float* Wp   = (z == 0) ? Wq : ((z == 1) ? Wk : Wv);
    const float* bp   = (z == 0) ? bq : ((z == 1) ? bk : bv);
    float*       outp = (z == 0) ? g_Q : ((z == 1) ? g_K : g_V);
    const float  sc   = (z == 0) ? 0.125f : 1.0f;

    const int r0 = blockIdx.x * 64;
    const int hq = blockIdx.y;
    const int n0 = hq * 64;
    const int tid = threadIdx.x;
    const int lane = tid & 31;
    const int w = tid >> 5, wm = w & 3, wn = w >> 2;
    const int rb4 = lane & 3, rd4 = lane >> 2;

    float c[4][4] = {};
    float4 xr[4], wra[2], wrb[2];

    // W^T loader thread coords
    const int f0i = tid, f1i = tid + 256;
    const int kp0 = f0i >> 4, ng0 = f0i & 15;
    const int kp1 = f1i >> 4, ng1 = f1i & 15;

    // prefetch chunk 0
    ldg_tile_s(X + (size_t)r0 * 768, 768, xr, tid);
    {
        const float* w0 = Wp + (size_t)(2 * kp0) * 768 + n0 + ng0 * 4;
        const float* w1 = Wp + (size_t)(2 * kp1) * 768 + n0 + ng1 * 4;
        wra[0] = __ldg((const float4*)w0); wrb[0] = __ldg((const float4*)(w0 + 768));
        wra[1] = __ldg((const float4*)w1); wrb[1] = __ldg((const float4*)(w1 + 768));
    }

    for (int kt = 0; kt < 12; kt++) {
        __syncthreads();   // previous MMA reads done
        sts_split(xr, smc, QHo, QLo, tid);
        #pragma unroll
        for (int it = 0; it < 2; it++) {
            int kp = it ? kp1 : kp0, ng = it ? ng1 : ng0;
            int k0 = 2 * kp, nn = ng * 4;
            float av[4] = {it ? wra[1].x : wra[0].x, it ? wra[1].y : wra[0].y,
                           it ? wra[1].z : wra[0].z, it ? wra[1].w : wra[0].w};
            float bw[4] = {it ? wrb[1].x : wrb[0].x, it ? wrb[1].y : wrb[0].y,
                           it ? wrb[1].z : wrb[0].z, it ? wrb[1].w : wrb[0].w};
            #pragma unroll
            for (int i = 0; i < 4; i++) {
                int ni = nn + i;
                u32 hp = pkbf(av[i], bw[i]);
                u32 lp = pkbf(av[i] - bflo(hp), bw[i] - bfhi(hp));
                int off = ni * 128 + (((k0 >> 3) ^ (ni & 7)) << 4) + (k0 & 7) * 2;
                *(u32*)(smc + KVHo + off) = hp;
                *(u32*)(smc + KVLo + off) = lp;
            }
        }
        __syncthreads();
        // prefetch chunk kt+1 (overlaps MMA below)
        if (kt < 11) {
            ldg_tile_s(X + (size_t)r0 * 768 + (kt + 1) * 64, 768, xr, tid);
            const float* w0 = Wp + (size_t)((kt + 1) * 64 + 2 * kp0) * 768 + n0 + ng0 * 4;
            const float* w1 = Wp + (size_t)((kt + 1) * 64 + 2 * kp1) * 768 + n0 + ng1 * 4;
            wra[0] = __ldg((const float4*)w0); wrb[0] = __ldg((const float4*)(w0 + 768));
            wra[1] = __ldg((const float4*)w1); wrb[1] = __ldg((const float4*)(w1 + 768));
        }
        mma_scores(c, smb, wm, wn, lane);
    }

    #pragma unroll
    for (int nt = 0; nt < 4; nt++) {
        int d = 32 * wn + 8 * nt + 2 * rb4;
        float b0 = bp[n0 + d], b1 = bp[n0 + d + 1];
        #pragma unroll
        for (int half = 0; half < 2; half++) {
            int r = r0 + 16 * wm + rd4 + 8 * half;
            int b = r >> 11, s = r & 2047;
            float2 res;
            res.x = (c[nt][2 * half + 0] + b0) * sc;
            res.y = (c[nt][2 * half + 1] + b1) * sc;
            *(float2*)(outp + ((size_t)(b * NHn + hq) * Sn + s) * 64 + d) = res;
        }
    }
}

// ---------------------------------------------------------------------------
// Kernel 2: HMMA flash attention with register-staged K/V prefetch.
// ---------------------------------------------------------------------------
__global__ __launch_bounds__(256, 2) void attn_kernel(
    const float* __restrict__ mask,
    const float* __restrict__ rke,
    const float* __restrict__ rve,
    float* __restrict__ out)
{
    extern __shared__ char smc[];
    __nv_bfloat16* smh = (__nv_bfloat16*)smc;
    const u32 smb = (u32)__cvta_generic_to_shared(smc);

    const int tid = threadIdx.x;
    const int lane = tid & 31;
    const int w = tid >> 5, wm = w & 3, wn = w >> 2;
    const int hq = blockIdx.y, bz = blockIdx.z;
    const int bh = bz * NHn + hq;
    const int i0 = blockIdx.x * 64;

    const float* Qg = g_Q + ((size_t)bh * Sn + i0) * 64;
    const float* Kg = g_K + (size_t)bh * Sn * 64;
    const float* Vg = g_V + (size_t)bh * Sn * 64;
    const float* maskg = mask + (size_t)bz * Sn;

    float* exm = (float*)(smc + EXMo);
    float* exs = (float*)(smc + EXSo);
    float* exl = (float*)(smc + EXLo);
    float* exh = (float*)(smc + EXHo);

    {
        __nv_bfloat16 hneg = __float2bfloat16(-1e30f);
        unsigned short us = __bfloat16_as_ushort(hneg);
        u32 vv = (u32)us | ((u32)us << 16);
        u32* w32 = (u32*)(smc + Wo);
        #pragma unroll
        for (int t = 0; t < 32; t++) w32[tid + t * 256] = vv;
        if (tid < 8382 - 32 * 256) w32[tid + 32 * 256] = vv;
    }

    load_split64(Qg, smc, QHo, QLo, tid);
    __syncthreads();

    const int rb4 = lane & 3, rd4 = lane >> 2;
    for (int rb = 0; rb < 4; rb++) {
        load_split64(rke + rb * 64 * 64, smc, KVHo, KVLo, tid);
        __syncthreads();
        float c[4][4] = {};
        mma_scores(c, smb, wm, wn, lane);
        #pragma unroll
        for (int nt = 0; nt < 4; nt++) {
            #pragma unroll
            for (int e = 0; e < 4; e++) {
                int m = 16 * wm + rd4 + (e >> 1) * 8;
                int r = rb * 64 + 32 * wn + 8 * nt + 2 * rb4 + (e & 1);
                smh[(RELCo >> 1) + m * 256 + r] = __float2bfloat16(c[nt][e]);
            }
        }
        __syncthreads();
    }

    float ctx[8][4] = {};
    float mu[2] = {-1e30f, -1e30f}, l[2] = {}, plo[2] = {}, phi[2] = {};
    const int rbase = 16 * wm + rd4;

    float4 kr[4], vr[4];
    ldg_tile_s(Kg, 64, kr, tid);   // prefetch K tile 0

    for (int jt = 0; jt < 32; jt++) {
        const int j0 = jt * 64;
        const int doff = j0 - i0;
        __syncthreads();                       // prev PV reads done
        sts_split(kr, smc, KVHo, KVLo, tid);
        __syncthreads();                       // K ready

        float c[4][4] = {};
        mma_scores(c, smb, wm, wn, lane);

        ldg_tile_s(Vg + (size_t)j0 * 64, 64, vr, tid);   // V prefetch

        float mb[4][2];
        #pragma unroll
        for (int nt = 0; nt < 4; nt++) {
            float2 mv = __ldg((const float2*)(maskg + j0 + 32 * wn + 8 * nt + 2 * rb4));
            mb[nt][0] = (1.0f - mv.x) * -10000.0f;
            mb[nt][1] = (1.0f - mv.y) * -10000.0f;
        }

        const bool pure_lo = (doff + 63 <= -128);
        const bool pure_hi = (doff - 63 >= 127);
        const bool pure = pure_lo || pure_hi;
        const bool has_clamp = !pure && !((doff - 63 >= -127) && (doff + 63 <= 126));

        if (pure) {
            const int b = pure_lo ? 0 : 255;
            float rb0 = __bfloat162float(smh[(RELCo >> 1) + rbase * 256 + b]);
            float rb1 = __bfloat162float(smh[(RELCo >> 1) + (rbase + 8) * 256 + b]);
            #pragma unroll
            for (int nt = 0; nt < 4; nt++)
                #pragma unroll
                for (int e = 0; e < 4; e++)
                    c[nt][e] += ((e >> 1) ? rb1 : rb0) + mb[nt][e & 1];
        } else {
            #pragma unroll
            for (int nt = 0; nt < 4; nt++) {
                #pragma unroll
                for (int e = 0; e < 4; e++) {
                    int row = rbase + (e >> 1) * 8;
                    int col = 32 * wn + 8 * nt + 2 * rb4 + (e & 1);
                    int dlt = doff + col - row;
                    int bkt = max(-128, min(127, dlt)) + 128;
                    c[nt][e] += __bfloat162float(
                                    smh[(RELCo >> 1) + row * 256 + bkt]) + mb[nt][e & 1];
                    if (dlt > -128 && dlt < 127)
                        smh[(Wo >> 1) + (dlt + 127) * 66 + row] = __float2bfloat16(c[nt][e]);
                }
            }
        }

        float lm[2];
        #pragma unroll
        for (int rl = 0; rl < 2; rl++) {
            float m0 = fmaxf(fmaxf(c[0][2 * rl], c[0][2 * rl + 1]),
                             fmaxf(c[1][2 * rl], c[1][2 * rl + 1]));
            float m1 = fmaxf(fmaxf(c[2][2 * rl], c[2][2 * rl + 1]),
                             fmaxf(c[3][2 * rl], c[3][2 * rl + 1]));
            float v = fmaxf(m0, m1);
            v = fmaxf(v, __shfl_xor_sync(0xffffffffu, v, 1));
            v = fmaxf(v, __shfl_xor_sync(0xffffffffu, v, 2));
            lm[rl] = v;
        }
        if ((lane & 3) == 0) {
            exm[wn * 64 + rbase]     = lm[0];
            exm[wn * 64 + rbase + 8] = lm[1];
        }
        __syncthreads();                       // exm ready; K reads done

        sts_split(vr, smc, KVHo, KVLo, tid);   // V into planes

        float alpha[2];
        #pragma unroll
        for (int rl = 0; rl < 2; rl++) {
            int row = rbase + 8 * rl;
            float nm = fmaxf(mu[rl], fmaxf(exm[row], exm[64 + row]));
            alpha[rl] = __expf(mu[rl] - nm);
            mu[rl] = nm;
            float sum = 0.f;
            #pragma unroll
            for (int nt = 0; nt < 4; nt++) {
                #pragma unroll
                for (int h = 0; h < 2; h++) {
                    int e = 2 * rl + h;
                    float p = __expf(c[nt][e] - nm);
                    c[nt][e] = p;
                    sum += p;
                }
            }
            sum += __shfl_xor_sync(0xffffffffu, sum, 1);
            sum += __shfl_xor_sync(0xffffffffu, sum, 2);
            float clo, chi;
            if (has_clamp) {
                clo = 0.f; chi = 0.f;
                #pragma unroll
                for (int nt = 0; nt < 4; nt++) {
                    #pragma unroll
                    for (int h = 0; h < 2; h++) {
                        int col = 32 * wn + 8 * nt + 2 * rb4 + h;
                        int dlt = doff + col - row;
                        float p = c[nt][2 * rl + h];
                        if (dlt <= -128)     clo += p;
                        else if (dlt >= 127) chi += p;
                    }
                }
                clo += __shfl_xor_sync(0xffffffffu, clo, 1);
                clo += __shfl_xor_sync(0xffffffffu, clo, 2);
                chi += __shfl_xor_sync(0xffffffffu, chi, 1);
                chi += __shfl_xor_sync(0xffffffffu, chi, 2);
            } else {
                clo = pure_lo ? sum : 0.f;
                chi = pure_hi ? sum : 0.f;
            }
            if ((lane & 3) == 0) {
                exs[wn * 64 + row] = sum;
                exl[wn * 64 + row] = clo;
                exh[wn * 64 + row] = chi;
            }
        }
        __syncthreads();                       // sums + V ready

        #pragma unroll
        for (int rl = 0; rl < 2; rl++) {
            int row = rbase + 8 * rl;
            l[rl]   = l[rl]   * alpha[rl] + exs[row] + exs[64 + row];
            plo[rl] = plo[rl] * alpha[rl] + exl[row] + exl[64 + row];
            phi[rl] = phi[rl] * alpha[rl] + exh[row] + exh[64 + row];
        }
        #pragma unroll
        for (int dnt = 0; dnt < 8; dnt++) {
            ctx[dnt][0] *= alpha[0]; ctx[dnt][1] *= alpha[0];
            ctx[dnt][2] *= alpha[1]; ctx[dnt][3] *= alpha[1];
        }

        u32 Ah[2][4], Al[2][4];
        #pragma unroll
        for (int kf = 0; kf < 2; kf++) {
            #pragma unroll
            for (int h = 0; h < 2; h++) {
                int nt = 2 * kf + h;
                u32 h0 = pkbf(c[nt][0], c[nt][1]);
                u32 h1 = pkbf(c[nt][2], c[nt][3]);
                Ah[kf][2 * h]     = h0;
                Ah[kf][2 * h + 1] = h1;
                Al[kf][2 * h]     = pkbf(c[nt][0] - bflo(h0), c[nt][1] - bfhi(h0));
                Al[kf][2 * h + 1] = pkbf(c[nt][2] - bflo(h1), c[nt][3] - bfhi(h1));
            }
        }

        if (jt < 31)
            ldg_tile_s(Kg + (size_t)(j0 + 64) * 64, 64, kr, tid);  // K prefetch

        {
            int vrow = 32 * wn + lane;
            u32 vb = smb + (u32)(KVHo + vrow * 128);
            u32 vsw = (u32)((vrow & 7) << 4);
            #pragma unroll
            for (int dnt = 0; dnt < 8; dnt++) {
                u32 vAddr = vb + (((u32)(dnt << 4)) ^ vsw);
                u32 bhv[4], blv[4];
                ldm_x4t(bhv[0], bhv[1], bhv[2], bhv[3], vAddr);
                ldm_x4t(blv[0], blv[1], blv[2], blv[3], vAddr + (KVLo - KVHo));
                #pragma unroll
                for (int kf = 0; kf < 2; kf++) {
                    mma_bf16(ctx[dnt], Ah[kf], bhv[2 * kf], bhv[2 * kf + 1]);
                    mma_bf16(ctx[dnt], Ah[kf], blv[2 * kf], blv[2 * kf + 1]);
                    mma_bf16(ctx[dnt], Al[kf], bhv[2 * kf], bhv[2 * kf + 1]);
                }
            }
        }
    }

    __syncthreads();
    float* ctxp = (float*)(smc + CTXo);
    float* lv   = (float*)(smc + LVo);
    float* plv  = (float*)(smc + PLOo);
    float* phv  = (float*)(smc + PHIo);
    float* muv  = (float*)(smc + MUo);
    if (wn == 0) {
        #pragma unroll
        for (int dnt = 0; dnt < 8; dnt++) {
            int dbase = 8 * dnt + 2 * rb4;
            *(float2*)&ctxp[rbase * 64 + dbase]       = make_float2(ctx[dnt][0], ctx[dnt][1]);
            *(float2*)&ctxp[(rbase + 8) * 64 + dbase] = make_float2(ctx[dnt][2], ctx[dnt][3]);
        }
        if ((lane & 3) == 0) {
            #pragma unroll
            for (int rl = 0; rl < 2; rl++) {
                int row = rbase + 8 * rl;
                lv[row] = l[rl]; plv[row] = plo[rl];
                phv[row] = phi[rl]; muv[row] = mu[rl];
            }
        }
    }
    __syncthreads();
    if (wn == 1) {
        #pragma unroll
        for (int dnt = 0; dnt < 8; dnt++) {
            int dbase = 8 * dnt + 2 * rb4;
            float2 a0 = *(float2*)&ctxp[rbase * 64 + dbase];
            float2 a1 = *(float2*)&ctxp[(rbase + 8) * 64 + dbase];
            *(float2*)&ctxp[rbase * 64 + dbase] =
                make_float2(a0.x + ctx[dnt][0], a0.y + ctx[dnt][1]);
            *(float2*)&ctxp[(rbase + 8) * 64 + dbase] =
                make_float2(a1.x + ctx[dnt][2], a1.y + ctx[dnt][3]);
        }
    }
    __syncthreads();

    #pragma unroll 4
    for (int t = 0; t < 64; t++) {
        int idx = tid + t * 256;
        if (idx < 254 * 64) {
            int r = idx >> 6, m = idx & 63;
            float wv = __bfloat162float(smh[(Wo >> 1) + r * 66 + m]);
            smh[(Wo >> 1) + r * 66 + m] = __float2bfloat16(__expf(wv - muv[m]));
        }
    }
    __syncthreads();

    {
        const int ty = tid >> 5, tx = tid & 31;
        u64 o2[4][2];
        #pragma unroll
        for (int rp = 0; rp < 4; rp++)
            #pragma unroll
            for (int di = 0; di < 2; di++)
                o2[rp][di] = pk2(ctxp[(ty * 8 + 2 * rp) * 64 + tx * 2 + di],
                                 ctxp[(ty * 8 + 2 * rp + 1) * 64 + tx * 2 + di]);

        #pragma unroll 2
        for (int r = 0; r < 254; r++) {
            const __nv_bfloat162* wr =
                (const __nv_bfloat162*)&smh[(Wo >> 1) + r * 66 + ty * 8];
            __nv_bfloat162 e0 = wr[0], e1 = wr[1], e2 = wr[2], e3 = wr[3];
            float2 rv = __ldg((const float2*)(rve + (r + 1) * 64 + tx * 2));
            u64 r0 = dup2(rv.x), r1 = dup2(rv.y);
            float2 f0 = __bfloat1622float2(e0);
            float2 f1 = __bfloat1622float2(e1);
            float2 f2 = __bfloat1622float2(e2);
            float2 f3 = __bfloat1622float2(e3);
            u64 ep0 = pk2(f0.x, f0.y), ep1 = pk2(f1.x, f1.y);
            u64 ep2 = pk2(f2.x, f2.y), ep3 = pk2(f3.x, f3.y);
            o2[0][0] = ffma2(ep0, r0, o2[0][0]);
            o2[0][1] = ffma2(ep0, r1, o2[0][1]);
            o2[1][0] = ffma2(ep1, r0, o2[1][0]);
            o2[1][1] = ffma2(ep1, r1, o2[1][1]);
            o2[2][0] = ffma2(ep2, r0, o2[2][0]);
            o2[2][1] = ffma2(ep2, r1, o2[2][1]);
            o2[3][0] = ffma2(ep3, r0, o2[3][0]);
            o2[3][1] = ffma2(ep3, r1, o2[3][1]);
        }

        float2 rv0 = __ldg((const float2*)(rve + 0 * 64 + tx * 2));
        float2 rvN = __ldg((const float2*)(rve + 255 * 64 + tx * 2));
        #pragma unroll
        for (int rp = 0; rp < 4; rp++) {
            float2 c0 = up2(o2[rp][0]), c1 = up2(o2[rp][1]);
            #pragma unroll
            for (int h = 0; h < 2; h++) {
                int ri = 2 * rp + h;
                int row = ty * 8 + ri;
                float ox = h ? c0.y : c0.x;
                float oy = h ? c1.y : c1.x;
                float inv = 1.0f / lv[row];
                float2 res;
                res.x = (ox + plv[row] * rv0.x + phv[row] * rvN.x) * inv;
                res.y = (oy + plv[row] * rv0.y + phv[row] * rvN.y) * inv;
                *(float2*)(out + ((size_t)bz * Sn + i0 + row) * Hn + hq * 64 + tx * 2) = res;
            }
        }
    }
}

// ---------------------------------------------------------------------------
extern "C" void kernel_launch(void* const* d_in, const int* in_sizes, int n_in,
                              void* d_out, int out_size)
{
    const float* X    = (const float*)d_in[0];
    const float* mask = (const float*)d_in[1];
    const float* Wq   = (const float*)d_in[2];
    const float* bq   = (const float*)d_in[3];
    const float* Wk   = (const float*)d_in[4];
    const float* bk   = (const float*)d_in[5];
    const float* Wv   = (const float*)d_in[6];
    const float* bv   = (const float*)d_in[7];
    const float* rke  = (const float*)d_in[8];
    const float* rve  = (const float*)d_in[9];
    float* out = (float*)d_out;

    (void)in_sizes; (void)n_in; (void)out_size;

    cudaFuncSetAttribute(attn_kernel,
                         cudaFuncAttributeMaxDynamicSharedMemorySize, SMEMB);

    qkv_kernel<<<dim3(64, NHn, 3), 256>>>(X, Wq, bq, Wk, bk, Wv, bv);
    attn_kernel<<<dim3(32, NHn, Bn), 256, SMEMB>>>(mask, rke, rve, out);
}

// round 12
// speedup vs baseline: 1.8877x; 1.1249x over previous
#include <cuda_runtime.h>
#include <cuda_bf16.h>

// ---------------------------------------------------------------------------
// GraphEncoder relative-position attention, GB300 sm_103a — round 12
// R11 + plane-swizzle fix (adds (row>>3)&3 term: kills 8-way bank conflicts
// in the qkv W-transpose store; ldmatrix reads stay conflict-free) and
// clamp-mass exchange skipped on non-clamp tiles.
// ---------------------------------------------------------------------------

namespace {
constexpr int Bn  = 2;
constexpr int Sn  = 2048;
constexpr int Hn  = 768;
constexpr int NHn = 12;

// smem byte offsets (attention)
constexpr int QHo   = 0;         // Q hi plane  64x64 bf16 (8192)
constexpr int QLo   = 8192;      // Q lo plane
constexpr int KVHo  = 16384;     // K/V hi plane (shared)
constexpr int KVLo  = 24576;     // K/V lo plane
constexpr int RELCo = 32768;     // relc bf16 [64][256]  (32768)
constexpr int Wo    = 65536;     // W bf16 [254][66]     (33528)
constexpr int EXMo  = 99064;     // f32 [2][64] half-max
constexpr int EXSo  = 99576;     // f32 [2][64] half-sum
constexpr int EXLo  = 100088;    // f32 [2][64] clamp-lo
constexpr int EXHo  = 100600;    // f32 [2][64] clamp-hi
constexpr int SMEMB = 101112;
// epilogue overlays
constexpr int CTXo  = 0;
constexpr int LVo   = 16384;
constexpr int PLOo  = 16640;
constexpr int PHIo  = 16896;
constexpr int MUo   = 17152;
}

__device__ float g_Q[Bn * NHn * Sn * 64];
__device__ float g_K[Bn * NHn * Sn * 64];
__device__ float g_V[Bn * NHn * Sn * 64];

typedef unsigned long long u64;
typedef unsigned int u32;

__device__ __forceinline__ u64 pk2(float lo, float hi) {
    u64 r; asm("mov.b64 %0,{%1,%2};" : "=l"(r) : "f"(lo), "f"(hi)); return r;
}
__device__ __forceinline__ u64 dup2(float v) { return pk2(v, v); }
__device__ __forceinline__ u64 ffma2(u64 a, u64 b, u64 c) {
    u64 d; asm("fma.rn.f32x2 %0,%1,%2,%3;" : "=l"(d) : "l"(a), "l"(b), "l"(c)); return d;
}
__device__ __forceinline__ float2 up2(u64 v) {
    float2 f; asm("mov.b64 {%0,%1},%2;" : "=f"(f.x), "=f"(f.y) : "l"(v)); return f;
}
__device__ __forceinline__ u32 pkbf(float lo, float hi) {
    u32 d; asm("cvt.rn.bf16x2.f32 %0,%1,%2;" : "=r"(d) : "f"(hi), "f"(lo)); return d;
}
__device__ __forceinline__ float bflo(u32 h) { return __uint_as_float(h << 16); }
__device__ __forceinline__ float bfhi(u32 h) { return __uint_as_float(h & 0xFFFF0000u); }

// plane byte offset: row-major 128B rows, 16B chunk ch swizzled by row bits
// (row&7 for ldmatrix spread, (row>>3)&3 for cross-group store spread).
__device__ __forceinline__ int swq(int row, int ch) {
    return row * 128 + ((ch ^ (row & 7) ^ ((row >> 3) & 3)) << 4);
}

__device__ __forceinline__ void ldm_x4(u32& r0, u32& r1, u32& r2, u32& r3, u32 a) {
    asm volatile("ldmatrix.sync.aligned.m8n8.x4.shared.b16 {%0,%1,%2,%3},[%4];"
                 : "=r"(r0), "=r"(r1), "=r"(r2), "=r"(r3) : "r"(a));
}
__device__ __forceinline__ void ldm_x2(u32& r0, u32& r1, u32 a) {
    asm volatile("ldmatrix.sync.aligned.m8n8.x2.shared.b16 {%0,%1},[%2];"
                 : "=r"(r0), "=r"(r1) : "r"(a));
}
__device__ __forceinline__ void ldm_x4t(u32& r0, u32& r1, u32& r2, u32& r3, u32 a) {
    asm volatile("ldmatrix.sync.aligned.m8n8.x4.trans.shared.b16 {%0,%1,%2,%3},[%4];"
                 : "=r"(r0), "=r"(r1), "=r"(r2), "=r"(r3) : "r"(a));
}
__device__ __forceinline__ void mma_bf16(float* d, const u32* a, u32 b0, u32 b1) {
    asm volatile("mma.sync.aligned.m16n8k16.row.col.f32.bf16.bf16.f32 "
                 "{%0,%1,%2,%3},{%4,%5,%6,%7},{%8,%9},{%0,%1,%2,%3};"
                 : "+f"(d[0]), "+f"(d[1]), "+f"(d[2]), "+f"(d[3])
                 : "r"(a[0]), "r"(a[1]), "r"(a[2]), "r"(a[3]), "r"(b0), "r"(b1));
}

// ---- tile staging: LDG into registers / convert+STS to hi/lo planes ----
__device__ __forceinline__ void ldg_tile_s(const float* __restrict__ src,
                                           int stride, float4 v[4], int tid)
{
    #pragma unroll
    for (int s = 0; s < 4; s++) {
        int f = tid + s * 256;
        v[s] = __ldg((const float4*)(src + (size_t)(f >> 4) * stride + (f & 15) * 4));
    }
}
__device__ __forceinline__ void sts_split(const float4 v[4], char* smc,
                                          int hiOff, int loOff, int tid)
{
    #pragma unroll
    for (int s = 0; s < 4; s++) {
        int f = tid + s * 256;
        int row = f >> 4, cg = f & 15;
        float4 w = v[s];
        __nv_bfloat162 h0 = __floats2bfloat162_rn(w.x, w.y);
        __nv_bfloat162 h1 = __floats2bfloat162_rn(w.z, w.w);
        float2 f0 = __bfloat1622float2(h0);
        float2 f1 = __bfloat1622float2(h1);
        __nv_bfloat162 l0 = __floats2bfloat162_rn(w.x - f0.x, w.y - f0.y);
        __nv_bfloat162 l1 = __floats2bfloat162_rn(w.z - f1.x, w.w - f1.y);
        int off = swq(row, cg >> 1) + ((cg & 1) << 3);
        *(__nv_bfloat162*)(smc + hiOff + off)     = h0;
        *(__nv_bfloat162*)(smc + hiOff + off + 4) = h1;
        *(__nv_bfloat162*)(smc + loOff + off)     = l0;
        *(__nv_bfloat162*)(smc + loOff + off + 4) = l1;
    }
}
__device__ __forceinline__ void load_split_s(const float* __restrict__ src,
                                             int stride, char* smc,
                                             int hiOff, int loOff, int tid)
{
    float4 v[4];
    ldg_tile_s(src, stride, v, tid);
    sts_split(v, smc, hiOff, loOff, tid);
}
__device__ __forceinline__ void load_split64(const float* __restrict__ src,
                                             char* smc, int hiOff, int loOff, int tid)
{
    load_split_s(src, 64, smc, hiOff, loOff, tid);
}

// 64x64x64 split-bf16 GEMM step: c[nt][e] += A[16wm rows] . B[32wn cols]
__device__ __forceinline__ void mma_scores(float c[4][4], u32 smb,
                                           int wm, int wn, int lane)
{
    const int r8 = lane & 7;
    const int j4 = lane >> 3;
    const int jb = (lane >> 3) & 1;
    #pragma unroll
    for (int ks = 0; ks < 4; ks++) {
        int mrow = 16 * wm + r8 + (j4 & 1) * 8;
        int chA = 2 * ks + (j4 >> 1);
        u32 aAddr = smb + (u32)(QHo + swq(mrow, chA));
        u32 ah[4], al[4];
        ldm_x4(ah[0], ah[1], ah[2], ah[3], aAddr);
        ldm_x4(al[0], al[1], al[2], al[3], aAddr + (QLo - QHo));
        #pragma unroll
        for (int nt = 0; nt < 4; nt++) {
            int n = 32 * wn + 8 * nt + r8;
            int chB = 2 * ks + jb;
            u32 bAddr = smb + (u32)(KVHo + swq(n, chB));
            u32 bh0, bh1, bl0, bl1;
            ldm_x2(bh0, bh1, bAddr);
            ldm_x2(bl0, bl1, bAddr + (KVLo - KVHo));
            mma_bf16(c[nt], ah, bh0, bh1);
            mma_bf16(c[nt], ah, bl0, bl1);
            mma_bf16(c[nt], al, bh0, bh1);
        }
    }
}

// ---------------------------------------------------------------------------
// Kernel 1: HMMA QKV projection with register-staged prefetch.
// ---------------------------------------------------------------------------
__global__ __launch_bounds__(256) void qkv_kernel(
    const float* __restrict__ X,
    const float* __restrict__ Wq, const float* __restrict__ bq,
    const float* __restrict__ Wk, const float* __restrict__ bk,
    const float* __restrict__ Wv, const float* __restrict__ bv)
{
    __shared__ char smc[32768];
    const u32 smb = (u32)__cvta_generic_to_shared(smc);

    const int z = blockIdx.z;
    const float* Wp   = (z == 0) ? Wq : ((z == 1) ? Wk : Wv);
    const float* bp   = (z == 0) ? bq : ((z == 1) ? bk : bv);
    float*       outp = (z == 0) ? g_Q : ((z == 1) ? g_K : g_V);
    const float  sc   = (z == 0) ? 0.125f : 1.0f;

    const int r0 = blockIdx.x * 64;
    const int hq = blockIdx.y;
    const int n0 = hq * 64;
    const int tid = threadIdx.x;
    const int lane = tid & 31;
    const int w = tid >> 5, wm = w & 3, wn = w >> 2;
    const int rb4 = lane & 3, rd4 = lane >> 2;

    float c[4][4] = {};
    float4 xr[4], wra[2], wrb[2];

    const int f0i = tid, f1i = tid + 256;
    const int kp0 = f0i >> 4, ng0 = f0i & 15;
    const int kp1 = f1i >> 4, ng1 = f1i & 15;

    ldg_tile_s(X + (size_t)r0 * 768, 768, xr, tid);
    {
        const float* w0 = Wp + (size_t)(2 * kp0) * 768 + n0 + ng0 * 4;
        const float* w1 = Wp + (size_t)(2 * kp1) * 768 + n0 + ng1 * 4;
        wra[0] = __ldg((const float4*)w0); wrb[0] = __ldg((const float4*)(w0 + 768));
        wra[1] = __ldg((const float4*)w1); wrb[1] = __ldg((const float4*)(w1 + 768));
    }

    for (int kt = 0; kt < 12; kt++) {
        __syncthreads();
        sts_split(xr, smc, QHo, QLo, tid);
        #pragma unroll
        for (int it = 0; it < 2; it++) {
            int kp = it ? kp1 : kp0, ng = it ? ng1 : ng0;
            int k0 = 2 * kp, nn = ng * 4;
            float av[4] = {it ? wra[1].x : wra[0].x, it ? wra[1].y : wra[0].y,
                           it ? wra[1].z : wra[0].z, it ? wra[1].w : wra[0].w};
            float bw[4] = {it ? wrb[1].x : wrb[0].x, it ? wrb[1].y : wrb[0].y,
                           it ? wrb[1].z : wrb[0].z, it ? wrb[1].w : wrb[0].w};
            #pragma unroll
            for (int i = 0; i < 4; i++) {
                int ni = nn + i;
                u32 hp = pkbf(av[i], bw[i]);
                u32 lp = pkbf(av[i] - bflo(hp), bw[i] - bfhi(hp));
                int off = swq(ni, k0 >> 3) + (k0 & 7) * 2;
                *(u32*)(smc + KVHo + off) = hp;
                *(u32*)(smc + KVLo + off) = lp;
            }
        }
        __syncthreads();
        if (kt < 11) {
            ldg_tile_s(X + (size_t)r0 * 768 + (kt + 1) * 64, 768, xr, tid);
            const float* w0 = Wp + (size_t)((kt + 1) * 64 + 2 * kp0) * 768 + n0 + ng0 * 4;
            const float* w1 = Wp + (size_t)((kt + 1) * 64 + 2 * kp1) * 768 + n0 + ng1 * 4;
            wra[0] = __ldg((const float4*)w0); wrb[0] = __ldg((const float4*)(w0 + 768));
            wra[1] = __ldg((const float4*)w1); wrb[1] = __ldg((const float4*)(w1 + 768));
        }
        mma_scores(c, smb, wm, wn, lane);
    }

    #pragma unroll
    for (int nt = 0; nt < 4; nt++) {
        int d = 32 * wn + 8 * nt + 2 * rb4;
        float b0 = bp[n0 + d], b1 = bp[n0 + d + 1];
        #pragma unroll
        for (int half = 0; half < 2; half++) {
            int r = r0 + 16 * wm + rd4 + 8 * half;
            int b = r >> 11, s = r & 2047;
            float2 res;
            res.x = (c[nt][2 * half + 0] + b0) * sc;
            res.y = (c[nt][2 * half + 1] + b1) * sc;
            *(float2*)(outp + ((size_t)(b * NHn + hq) * Sn + s) * 64 + d) = res;
        }
    }
}

// ---------------------------------------------------------------------------
// Kernel 2: HMMA flash attention with register-staged K/V prefetch.
// ---------------------------------------------------------------------------
__global__ __launch_bounds__(256, 2) void attn_kernel(
    const float* __restrict__ mask,
    const float* __restrict__ rke,
    const float* __restrict__ rve,
    float* __restrict__ out)
{
    extern __shared__ char smc[];
    __nv_bfloat16* smh = (__nv_bfloat16*)smc;
    const u32 smb = (u32)__cvta_generic_to_shared(smc);

    const int tid = threadIdx.x;
    const int lane = tid & 31;
    const int w = tid >> 5, wm = w & 3, wn = w >> 2;
    const int hq = blockIdx.y, bz = blockIdx.z;
    const int bh = bz * NHn + hq;
    const int i0 = blockIdx.x * 64;

    const float* Qg = g_Q + ((size_t)bh * Sn + i0) * 64;
    const float* Kg = g_K + (size_t)bh * Sn * 64;
    const float* Vg = g_V + (size_t)bh * Sn * 64;
    const float* maskg = mask + (size_t)bz * Sn;

    float* exm = (float*)(smc + EXMo);
    float* exs = (float*)(smc + EXSo);
    float* exl = (float*)(smc + EXLo);
    float* exh = (float*)(smc + EXHo);

    {
        __nv_bfloat16 hneg = __float2bfloat16(-1e30f);
        unsigned short us = __bfloat16_as_ushort(hneg);
        u32 vv = (u32)us | ((u32)us << 16);
        u32* w32 = (u32*)(smc + Wo);
        #pragma unroll
        for (int t = 0; t < 32; t++) w32[tid + t * 256] = vv;
        if (tid < 8382 - 32 * 256) w32[tid + 32 * 256] = vv;
    }

    load_split64(Qg, smc, QHo, QLo, tid);
    __syncthreads();

    const int rb4 = lane & 3, rd4 = lane >> 2;
    for (int rb = 0; rb < 4; rb++) {
        load_split64(rke + rb * 64 * 64, smc, KVHo, KVLo, tid);
        __syncthreads();
        float c[4][4] = {};
        mma_scores(c, smb, wm, wn, lane);
        #pragma unroll
        for (int nt = 0; nt < 4; nt++) {
            #pragma unroll
            for (int e = 0; e < 4; e++) {
                int m = 16 * wm + rd4 + (e >> 1) * 8;
                int r = rb * 64 + 32 * wn + 8 * nt + 2 * rb4 + (e & 1);
                smh[(RELCo >> 1) + m * 256 + r] = __float2bfloat16(c[nt][e]);
            }
        }
        __syncthreads();
    }

    float ctx[8][4] = {};
    float mu[2] = {-1e30f, -1e30f}, l[2] = {}, plo[2] = {}, phi[2] = {};
    const int rbase = 16 * wm + rd4;

    float4 kr[4], vr[4];
    ldg_tile_s(Kg, 64, kr, tid);

    for (int jt = 0; jt < 32; jt++) {
        const int j0 = jt * 64;
        const int doff = j0 - i0;
        __syncthreads();
        sts_split(kr, smc, KVHo, KVLo, tid);
        __syncthreads();

        float c[4][4] = {};
        mma_scores(c, smb, wm, wn, lane);

        ldg_tile_s(Vg + (size_t)j0 * 64, 64, vr, tid);

        float mb[4][2];
        #pragma unroll
        for (int nt = 0; nt < 4; nt++) {
            float2 mv = __ldg((const float2*)(maskg + j0 + 32 * wn + 8 * nt + 2 * rb4));
            mb[nt][0] = (1.0f - mv.x) * -10000.0f;
            mb[nt][1] = (1.0f - mv.y) * -10000.0f;
        }

        const bool pure_lo = (doff + 63 <= -128);
        const bool pure_hi = (doff - 63 >= 127);
        const bool pure = pure_lo || pure_hi;
        const bool has_clamp = !pure && !((doff - 63 >= -127) && (doff + 63 <= 126));

        if (pure) {
            const int b = pure_lo ? 0 : 255;
            float rb0 = __bfloat162float(smh[(RELCo >> 1) + rbase * 256 + b]);
            float rb1 = __bfloat162float(smh[(RELCo >> 1) + (rbase + 8) * 256 + b]);
            #pragma unroll
            for (int nt = 0; nt < 4; nt++)
                #pragma unroll
                for (int e = 0; e < 4; e++)
                    c[nt][e] += ((e >> 1) ? rb1 : rb0) + mb[nt][e & 1];
        } else {
            #pragma unroll
            for (int nt = 0; nt < 4; nt++) {
                #pragma unroll
                for (int e = 0; e < 4; e++) {
                    int row = rbase + (e >> 1) * 8;
                    int col = 32 * wn + 8 * nt + 2 * rb4 + (e & 1);
                    int dlt = doff + col - row;
                    int bkt = max(-128, min(127, dlt)) + 128;
                    c[nt][e] += __bfloat162float(
                                    smh[(RELCo >> 1) + row * 256 + bkt]) + mb[nt][e & 1];
                    if (dlt > -128 && dlt < 127)
                        smh[(Wo >> 1) + (dlt + 127) * 66 + row] = __float2bfloat16(c[nt][e]);
                }
            }
        }

        float lm[2];
        #pragma unroll
        for (int rl = 0; rl < 2; rl++) {
            float m0 = fmaxf(fmaxf(c[0][2 * rl], c[0][2 * rl + 1]),
                             fmaxf(c[1][2 * rl], c[1][2 * rl + 1]));
            float m1 = fmaxf(fmaxf(c[2][2 * rl], c[2][2 * rl + 1]),
                             fmaxf(c[3][2 * rl], c[3][2 * rl + 1]));
            float v = fmaxf(m0, m1);
            v = fmaxf(v, __shfl_xor_sync(0xffffffffu, v, 1));
            v = fmaxf(v, __shfl_xor_sync(0xffffffffu, v, 2));
            lm[rl] = v;
        }
        if ((lane & 3) == 0) {
            exm[wn * 64 + rbase]     = lm[0];
            exm[wn * 64 + rbase + 8] = lm[1];
        }
        __syncthreads();

        sts_split(vr, smc, KVHo, KVLo, tid);

        float alpha[2];
        #pragma unroll
        for (int rl = 0; rl < 2; rl++) {
            int row = rbase + 8 * rl;
            float nm = fmaxf(mu[rl], fmaxf(exm[row], exm[64 + row]));
            alpha[rl] = __expf(mu[rl] - nm);
            mu[rl] = nm;
            float sum = 0.f;
            #pragma unroll
            for (int nt = 0; nt < 4; nt++) {
                #pragma unroll
                for (int h = 0; h < 2; h++) {
                    int e = 2 * rl + h;
                    float p = __expf(c[nt][e] - nm);
                    c[nt][e] = p;
                    sum += p;
                }
            }
            sum += __shfl_xor_sync(0xffffffffu, sum, 1);
            sum += __shfl_xor_sync(0xffffffffu, sum, 2);
            if (has_clamp) {
                float clo = 0.f, chi = 0.f;
                #pragma unroll
                for (int nt = 0; nt < 4; nt++) {
                    #pragma unroll
                    for (int h = 0; h < 2; h++) {
                        int col = 32 * wn + 8 * nt + 2 * rb4 + h;
                        int dlt = doff + col - row;
                        float p = c[nt][2 * rl + h];
                        if (dlt <= -128)     clo += p;
                        else if (dlt >= 127) chi += p;
                    }
                }
                clo += __shfl_xor_sync(0xffffffffu, clo, 1);
                clo += __shfl_xor_sync(0xffffffffu, clo, 2);
                chi += __shfl_xor_sync(0xffffffffu, chi, 1);
                chi += __shfl_xor_sync(0xffffffffu, chi, 2);
                if ((lane & 3) == 0) {
                    exl[wn * 64 + row] = clo;
                    exh[wn * 64 + row] = chi;
                }
            }
            if ((lane & 3) == 0)
                exs[wn * 64 + row] = sum;
        }
        __syncthreads();

        #pragma unroll
        for (int rl = 0; rl < 2; rl++) {
            int row = rbase + 8 * rl;
            float fullsum = exs[row] + exs[64 + row];
            l[rl] = l[rl] * alpha[rl] + fullsum;
            float addlo = 0.f, addhi = 0.f;
            if (pure_lo)       addlo = fullsum;
            else if (pure_hi)  addhi = fullsum;
            else if (has_clamp) {
                addlo = exl[row] + exl[64 + row];
                addhi = exh[row] + exh[64 + row];
            }
            plo[rl] = plo[rl] * alpha[rl] + addlo;
            phi[rl] = phi[rl] * alpha[rl] + addhi;
        }
        #pragma unroll
        for (int dnt = 0; dnt < 8; dnt++) {
            ctx[dnt][0] *= alpha[0]; ctx[dnt][1] *= alpha[0];
            ctx[dnt][2] *= alpha[1]; ctx[dnt][3] *= alpha[1];
        }

        u32 Ah[2][4], Al[2][4];
        #pragma unroll
        for (int kf = 0; kf < 2; kf++) {
            #pragma unroll
            for (int h = 0; h < 2; h++) {
                int nt = 2 * kf + h;
                u32 h0 = pkbf(c[nt][0], c[nt][1]);
                u32 h1 = pkbf(c[nt][2], c[nt][3]);
                Ah[kf][2 * h]     = h0;
                Ah[kf][2 * h + 1] = h1;
                Al[kf][2 * h]     = pkbf(c[nt][0] - bflo(h0), c[nt][1] - bfhi(h0));
                Al[kf][2 * h + 1] = pkbf(c[nt][2] - bflo(h1), c[nt][3] - bfhi(h1));
            }
        }

        if (jt < 31)
            ldg_tile_s(Kg + (size_t)(j0 + 64) * 64, 64, kr, tid);

        {
            int vrow = 32 * wn + lane;
            #pragma unroll
            for (int dnt = 0; dnt < 8; dnt++) {
                u32 vAddr = smb + (u32)(KVHo + swq(vrow, dnt));
                u32 bhv[4], blv[4];
                ldm_x4t(bhv[0], bhv[1], bhv[2], bhv[3], vAddr);
                ldm_x4t(blv[0], blv[1], blv[2], blv[3], vAddr + (KVLo - KVHo));
                #pragma unroll
                for (int kf = 0; kf < 2; kf++) {
                    mma_bf16(ctx[dnt], Ah[kf], bhv[2 * kf], bhv[2 * kf + 1]);
                    mma_bf16(ctx[dnt], Ah[kf], blv[2 * kf], blv[2 * kf + 1]);
                    mma_bf16(ctx[dnt], Al[kf], bhv[2 * kf], bhv[2 * kf + 1]);
                }
            }
        }
    }

    __syncthreads();
    float* ctxp = (float*)(smc + CTXo);
    float* lv   = (float*)(smc + LVo);
    float* plv  = (float*)(smc + PLOo);
    float* phv  = (float*)(smc + PHIo);
    float* muv  = (float*)(smc + MUo);
    if (wn == 0) {
        #pragma unroll
        for (int dnt = 0; dnt < 8; dnt++) {
            int dbase = 8 * dnt + 2 * rb4;
            *(float2*)&ctxp[rbase * 64 + dbase]       = make_float2(ctx[dnt][0], ctx[dnt][1]);
            *(float2*)&ctxp[(rbase + 8) * 64 + dbase] = make_float2(ctx[dnt][2], ctx[dnt][3]);
        }
        if ((lane & 3) == 0) {
            #pragma unroll
            for (int rl = 0; rl < 2; rl++) {
                int row = rbase + 8 * rl;
                lv[row] = l[rl]; plv[row] = plo[rl];
                phv[row] = phi[rl]; muv[row] = mu[rl];
            }
        }
    }
    __syncthreads();
    if (wn == 1) {
        #pragma unroll
        for (int dnt = 0; dnt < 8; dnt++) {
            int dbase = 8 * dnt + 2 * rb4;
            float2 a0 = *(float2*)&ctxp[rbase * 64 + dbase];
            float2 a1 = *(float2*)&ctxp[(rbase + 8) * 64 + dbase];
            *(float2*)&ctxp[rbase * 64 + dbase] =
                make_float2(a0.x + ctx[dnt][0], a0.y + ctx[dnt][1]);
            *(float2*)&ctxp[(rbase + 8) * 64 + dbase] =
                make_float2(a1.x + ctx[dnt][2], a1.y + ctx[dnt][3]);
        }
    }
    __syncthreads();

    #pragma unroll 4
    for (int t = 0; t < 64; t++) {
        int idx = tid + t * 256;
        if (idx < 254 * 64) {
            int r = idx >> 6, m = idx & 63;
            float wv = __bfloat162float(smh[(Wo >> 1) + r * 66 + m]);
            smh[(Wo >> 1) + r * 66 + m] = __float2bfloat16(__expf(wv - muv[m]));
        }
    }
    __syncthreads();

    {
        const int ty = tid >> 5, tx = tid & 31;
        u64 o2[4][2];
        #pragma unroll
        for (int rp = 0; rp < 4; rp++)
            #pragma unroll
            for (int di = 0; di < 2; di++)
                o2[rp][di] = pk2(ctxp[(ty * 8 + 2 * rp) * 64 + tx * 2 + di],
                                 ctxp[(ty * 8 + 2 * rp + 1) * 64 + tx * 2 + di]);

        #pragma unroll 2
        for (int r = 0; r < 254; r++) {
            const __nv_bfloat162* wr =
                (const __nv_bfloat162*)&smh[(Wo >> 1) + r * 66 + ty * 8];
            __nv_bfloat162 e0 = wr[0], e1 = wr[1], e2 = wr[2], e3 = wr[3];
            float2 rv = __ldg((const float2*)(rve + (r + 1) * 64 + tx * 2));
            u64 r0 = dup2(rv.x), r1 = dup2(rv.y);
            float2 f0 = __bfloat1622float2(e0);
            float2 f1 = __bfloat1622float2(e1);
            float2 f2 = __bfloat1622float2(e2);
            float2 f3 = __bfloat1622float2(e3);
            u64 ep0 = pk2(f0.x, f0.y), ep1 = pk2(f1.x, f1.y);
            u64 ep2 = pk2(f2.x, f2.y), ep3 = pk2(f3.x, f3.y);
            o2[0][0] = ffma2(ep0, r0, o2[0][0]);
            o2[0][1] = ffma2(ep0, r1, o2[0][1]);
            o2[1][0] = ffma2(ep1, r0, o2[1][0]);
            o2[1][1] = ffma2(ep1, r1, o2[1][1]);
            o2[2][0] = ffma2(ep2, r0, o2[2][0]);
            o2[2][1] = ffma2(ep2, r1, o2[2][1]);
            o2[3][0] = ffma2(ep3, r0, o2[3][0]);
            o2[3][1] = ffma2(ep3, r1, o2[3][1]);
        }

        float2 rv0 = __ldg((const float2*)(rve + 0 * 64 + tx * 2));
        float2 rvN = __ldg((const float2*)(rve + 255 * 64 + tx * 2));
        #pragma unroll
        for (int rp = 0; rp < 4; rp++) {
            float2 c0 = up2(o2[rp][0]), c1 = up2(o2[rp][1]);
            #pragma unroll
            for (int h = 0; h < 2; h++) {
                int ri = 2 * rp + h;
                int row = ty * 8 + ri;
                float ox = h ? c0.y : c0.x;
                float oy = h ? c1.y : c1.x;
                float inv = 1.0f / lv[row];
                float2 res;
                res.x = (ox + plv[row] * rv0.x + phv[row] * rvN.x) * inv;
                res.y = (oy + plv[row] * rv0.y + phv[row] * rvN.y) * inv;
                *(float2*)(out + ((size_t)bz * Sn + i0 + row) * Hn + hq * 64 + tx * 2) = res;
            }
        }
    }
}

// ---------------------------------------------------------------------------
extern "C" void kernel_launch(void* const* d_in, const int* in_sizes, int n_in,
                              void* d_out, int out_size)
{
    const float* X    = (const float*)d_in[0];
    const float* mask = (const float*)d_in[1];
    const float* Wq   = (const float*)d_in[2];
    const float* bq   = (const float*)d_in[3];
    const float* Wk   = (const float*)d_in[4];
    const float* bk   = (const float*)d_in[5];
    const float* Wv   = (const float*)d_in[6];
    const float* bv   = (const float*)d_in[7];
    const float* rke  = (const float*)d_in[8];
    const float* rve  = (const float*)d_in[9];
    float* out = (float*)d_out;

    (void)in_sizes; (void)n_in; (void)out_size;

    cudaFuncSetAttribute(attn_kernel,
                         cudaFuncAttributeMaxDynamicSharedMemorySize, SMEMB);

    qkv_kernel<<<dim3(64, NHn, 3), 256>>>(X, Wq, bq, Wk, bk, Wv, bv);
    attn_kernel<<<dim3(32, NHn, Bn), 256, SMEMB>>>(mask, rke, rve, out);
}

// round 13
// speedup vs baseline: 1.9488x; 1.0324x over previous
#include <cuda_runtime.h>
#include <cuda_bf16.h>

// ---------------------------------------------------------------------------
// GraphEncoder relative-position attention, GB300 sm_103a — round 13
// R12 + (1) independent per-half online softmax with epilogue merge (removes
// per-tile cross-warp exchange), (2) Q/K/V stored as pre-split, pre-swizzled
// bf16 hi/lo plane tiles in gmem by the QKV kernel (attention staging is a
// pure copy, no conversion math).
// ---------------------------------------------------------------------------

namespace {
constexpr int Bn  = 2;
constexpr int Sn  = 2048;
constexpr int Hn  = 768;
constexpr int NHn = 12;
constexpr int TILE_U32 = 2048;        // one 64x64 bf16 plane tile = 8192 B

// smem byte offsets (attention)
constexpr int QHo   = 0;         // Q hi plane  64x64 bf16 (8192)
constexpr int QLo   = 8192;      // Q lo plane
constexpr int KVHo  = 16384;     // K/V hi plane (shared)
constexpr int KVLo  = 24576;     // K/V lo plane
constexpr int RELCo = 32768;     // relc bf16 [64][256]  (32768)
constexpr int Wo    = 65536;     // W bf16 [254][66]     (33528)
// epilogue split-softmax stats (f32 [64] each)
constexpr int MUAo  = 99064;
constexpr int MUBo  = 99320;
constexpr int LAo   = 99576;
constexpr int LBo   = 99832;
constexpr int PLAo  = 100088;
constexpr int PLBo  = 100344;
constexpr int PHAo  = 100600;
constexpr int PHBo  = 100856;
constexpr int SMEMB = 101112;
// epilogue overlays (Q/KV planes dead)
constexpr int CTXo  = 0;
constexpr int LVo   = 16384;
constexpr int PLOo  = 16640;
constexpr int PHIo  = 16896;
constexpr int MUo   = 17152;
}

typedef unsigned long long u64;
typedef unsigned int u32;

// pre-split bf16 plane tiles: [Bn*NHn*32 tiles][2048 u32]
__device__ u32 g_Qh[Bn * NHn * 32 * TILE_U32];
__device__ u32 g_Ql[Bn * NHn * 32 * TILE_U32];
__device__ u32 g_Kh[Bn * NHn * 32 * TILE_U32];
__device__ u32 g_Kl[Bn * NHn * 32 * TILE_U32];
__device__ u32 g_Vh[Bn * NHn * 32 * TILE_U32];
__device__ u32 g_Vl[Bn * NHn * 32 * TILE_U32];

__device__ __forceinline__ u64 pk2(float lo, float hi) {
    u64 r; asm("mov.b64 %0,{%1,%2};" : "=l"(r) : "f"(lo), "f"(hi)); return r;
}
__device__ __forceinline__ u64 dup2(float v) { return pk2(v, v); }
__device__ __forceinline__ u64 ffma2(u64 a, u64 b, u64 c) {
    u64 d; asm("fma.rn.f32x2 %0,%1,%2,%3;" : "=l"(d) : "l"(a), "l"(b), "l"(c)); return d;
}
__device__ __forceinline__ float2 up2(u64 v) {
    float2 f; asm("mov.b64 {%0,%1},%2;" : "=f"(f.x), "=f"(f.y) : "l"(v)); return f;
}
__device__ __forceinline__ u32 pkbf(float lo, float hi) {
    u32 d; asm("cvt.rn.bf16x2.f32 %0,%1,%2;" : "=r"(d) : "f"(hi), "f"(lo)); return d;
}
__device__ __forceinline__ float bflo(u32 h) { return __uint_as_float(h << 16); }
__device__ __forceinline__ float bfhi(u32 h) { return __uint_as_float(h & 0xFFFF0000u); }

// plane byte offset: 128B rows, 16B chunk ch swizzled by row bits
__device__ __forceinline__ int swq(int row, int ch) {
    return row * 128 + ((ch ^ (row & 7) ^ ((row >> 3) & 3)) << 4);
}

__device__ __forceinline__ void ldm_x4(u32& r0, u32& r1, u32& r2, u32& r3, u32 a) {
    asm volatile("ldmatrix.sync.aligned.m8n8.x4.shared.b16 {%0,%1,%2,%3},[%4];"
                 : "=r"(r0), "=r"(r1), "=r"(r2), "=r"(r3) : "r"(a));
}
__device__ __forceinline__ void ldm_x2(u32& r0, u32& r1, u32 a) {
    asm volatile("ldmatrix.sync.aligned.m8n8.x2.shared.b16 {%0,%1},[%2];"
                 : "=r"(r0), "=r"(r1) : "r"(a));
}
__device__ __forceinline__ void ldm_x4t(u32& r0, u32& r1, u32& r2, u32& r3, u32 a) {
    asm volatile("ldmatrix.sync.aligned.m8n8.x4.trans.shared.b16 {%0,%1,%2,%3},[%4];"
                 : "=r"(r0), "=r"(r1), "=r"(r2), "=r"(r3) : "r"(a));
}
__device__ __forceinline__ void mma_bf16(float* d, const u32* a, u32 b0, u32 b1) {
    asm volatile("mma.sync.aligned.m16n8k16.row.col.f32.bf16.bf16.f32 "
                 "{%0,%1,%2,%3},{%4,%5,%6,%7},{%8,%9},{%0,%1,%2,%3};"
                 : "+f"(d[0]), "+f"(d[1]), "+f"(d[2]), "+f"(d[3])
                 : "r"(a[0]), "r"(a[1]), "r"(a[2]), "r"(a[3]), "r"(b0), "r"(b1));
}

// ---- bf16 plane-tile copy (gmem layout == smem layout) ----
__device__ __forceinline__ void ldg_planes(const u32* __restrict__ gh,
                                           const u32* __restrict__ gl,
                                           float4 v[4], int tid)
{
    v[0] = __ldg((const float4*)gh + tid);
    v[1] = __ldg((const float4*)gh + tid + 256);
    v[2] = __ldg((const float4*)gl + tid);
    v[3] = __ldg((const float4*)gl + tid + 256);
}
__device__ __forceinline__ void sts_planes(const float4 v[4], char* smc,
                                           int hiOff, int loOff, int tid)
{
    *((float4*)(smc + hiOff) + tid)       = v[0];
    *((float4*)(smc + hiOff) + tid + 256) = v[1];
    *((float4*)(smc + loOff) + tid)       = v[2];
    *((float4*)(smc + loOff) + tid + 256) = v[3];
}

// ---- f32 tile -> split planes (used for rke and qkv X only) ----
__device__ __forceinline__ void ldg_tile_s(const float* __restrict__ src,
                                           int stride, float4 v[4], int tid)
{
    #pragma unroll
    for (int s = 0; s < 4; s++) {
        int f = tid + s * 256;
        v[s] = __ldg((const float4*)(src + (size_t)(f >> 4) * stride + (f & 15) * 4));
    }
}
__device__ __forceinline__ void sts_split(const float4 v[4], char* smc,
                                          int hiOff, int loOff, int tid)
{
    #pragma unroll
    for (int s = 0; s < 4; s++) {
        int f = tid + s * 256;
        int row = f >> 4, cg = f & 15;
        float4 w = v[s];
        __nv_bfloat162 h0 = __floats2bfloat162_rn(w.x, w.y);
        __nv_bfloat162 h1 = __floats2bfloat162_rn(w.z, w.w);
        float2 f0 = __bfloat1622float2(h0);
        float2 f1 = __bfloat1622float2(h1);
        __nv_bfloat162 l0 = __floats2bfloat162_rn(w.x - f0.x, w.y - f0.y);
        __nv_bfloat162 l1 = __floats2bfloat162_rn(w.z - f1.x, w.w - f1.y);
        int off = swq(row, cg >> 1) + ((cg & 1) << 3);
        *(__nv_bfloat162*)(smc + hiOff + off)     = h0;
        *(__nv_bfloat162*)(smc + hiOff + off + 4) = h1;
        *(__nv_bfloat162*)(smc + loOff + off)     = l0;
        *(__nv_bfloat162*)(smc + loOff + off + 4) = l1;
    }
}
__device__ __forceinline__ void load_split_s(const float* __restrict__ src,
                                             int stride, char* smc,
                                             int hiOff, int loOff, int tid)
{
    float4 v[4];
    ldg_tile_s(src, stride, v, tid);
    sts_split(v, smc, hiOff, loOff, tid);
}

// 64x64x64 split-bf16 GEMM step: c[nt][e] += A[16wm rows] . B[32wn cols]
__device__ __forceinline__ void mma_scores(float c[4][4], u32 smb,
                                           int wm, int wn, int lane)
{
    const int r8 = lane & 7;
    const int j4 = lane >> 3;
    const int jb = (lane >> 3) & 1;
    #pragma unroll
    for (int ks = 0; ks < 4; ks++) {
        int mrow = 16 * wm + r8 + (j4 & 1) * 8;
        int chA = 2 * ks + (j4 >> 1);
        u32 aAddr = smb + (u32)(QHo + swq(mrow, chA));
        u32 ah[4], al[4];
        ldm_x4(ah[0], ah[1], ah[2], ah[3], aAddr);
        ldm_x4(al[0], al[1], al[2], al[3], aAddr + (QLo - QHo));
        #pragma unroll
        for (int nt = 0; nt < 4; nt++) {
            int n = 32 * wn + 8 * nt + r8;
            int chB = 2 * ks + jb;
            u32 bAddr = smb + (u32)(KVHo + swq(n, chB));
            u32 bh0, bh1, bl0, bl1;
            ldm_x2(bh0, bh1, bAddr);
            ldm_x2(bl0, bl1, bAddr + (KVLo - KVHo));
            mma_bf16(c[nt], ah, bh0, bh1);
            mma_bf16(c[nt], ah, bl0, bl1);
            mma_bf16(c[nt], al, bh0, bh1);
        }
    }
}

// ---------------------------------------------------------------------------
// Kernel 1: HMMA QKV projection -> pre-split bf16 plane tiles in gmem.
// Grid (64, 12, 3). C tile 64x64, K looped 12 chunks of 64.
// ---------------------------------------------------------------------------
__global__ __launch_bounds__(256) void qkv_kernel(
    const float* __restrict__ X,
    const float* __restrict__ Wq, const float* __restrict__ bq,
    const float* __restrict__ Wk, const float* __restrict__ bk,
    const float* __restrict__ Wv, const float* __restrict__ bv)
{
    __shared__ char smc[32768];
    const u32 smb = (u32)__cvta_generic_to_shared(smc);

    const int z = blockIdx.z;
    const float* Wp = (z == 0) ? Wq : ((z == 1) ? Wk : Wv);
    const float* bp = (z == 0) ? bq : ((z == 1) ? bk : bv);
    u32* gh = (z == 0) ? g_Qh : ((z == 1) ? g_Kh : g_Vh);
    u32* gl = (z == 0) ? g_Ql : ((z == 1) ? g_Kl : g_Vl);
    const float sc = (z == 0) ? 0.125f : 1.0f;

    const int r0 = blockIdx.x * 64;
    const int hq = blockIdx.y;
    const int n0 = hq * 64;
    const int tid = threadIdx.x;
    const int lane = tid & 31;
    const int w = tid >> 5, wm = w & 3, wn = w >> 2;
    const int rb4 = lane & 3, rd4 = lane >> 2;

    float c[4][4] = {};
    float4 xr[4], wra[2], wrb[2];

    const int f0i = tid, f1i = tid + 256;
    const int kp0 = f0i >> 4, ng0 = f0i & 15;
    const int kp1 = f1i >> 4, ng1 = f1i & 15;

    ldg_tile_s(X + (size_t)r0 * 768, 768, xr, tid);
    {
        const float* w0 = Wp + (size_t)(2 * kp0) * 768 + n0 + ng0 * 4;
        const float* w1 = Wp + (size_t)(2 * kp1) * 768 + n0 + ng1 * 4;
        wra[0] = __ldg((const float4*)w0); wrb[0] = __ldg((const float4*)(w0 + 768));
        wra[1] = __ldg((const float4*)w1); wrb[1] = __ldg((const float4*)(w1 + 768));
    }

    for (int kt = 0; kt < 12; kt++) {
        __syncthreads();
        sts_split(xr, smc, QHo, QLo, tid);
        #pragma unroll
        for (int it = 0; it < 2; it++) {
            int kp = it ? kp1 : kp0, ng = it ? ng1 : ng0;
            int k0 = 2 * kp, nn = ng * 4;
            float av[4] = {it ? wra[1].x : wra[0].x, it ? wra[1].y : wra[0].y,
                           it ? wra[1].z : wra[0].z, it ? wra[1].w : wra[0].w};
            float bw[4] = {it ? wrb[1].x : wrb[0].x, it ? wrb[1].y : wrb[0].y,
                           it ? wrb[1].z : wrb[0].z, it ? wrb[1].w : wrb[0].w};
            #pragma unroll
            for (int i = 0; i < 4; i++) {
                int ni = nn + i;
                u32 hp = pkbf(av[i], bw[i]);
                u32 lp = pkbf(av[i] - bflo(hp), bw[i] - bfhi(hp));
                int off = swq(ni, k0 >> 3) + (k0 & 7) * 2;
                *(u32*)(smc + KVHo + off) = hp;
                *(u32*)(smc + KVLo + off) = lp;
            }
        }
        __syncthreads();
        if (kt < 11) {
            ldg_tile_s(X + (size_t)r0 * 768 + (kt + 1) * 64, 768, xr, tid);
            const float* w0 = Wp + (size_t)((kt + 1) * 64 + 2 * kp0) * 768 + n0 + ng0 * 4;
            const float* w1 = Wp + (size_t)((kt + 1) * 64 + 2 * kp1) * 768 + n0 + ng1 * 4;
            wra[0] = __ldg((const float4*)w0); wrb[0] = __ldg((const float4*)(w0 + 768));
            wra[1] = __ldg((const float4*)w1); wrb[1] = __ldg((const float4*)(w1 + 768));
        }
        mma_scores(c, smb, wm, wn, lane);
    }

    // epilogue: bias+scale, split to bf16 hi/lo, store into plane tile
    const int b  = r0 >> 11;
    const int jt = (r0 & 2047) >> 6;
    const size_t tilebase = ((size_t)(b * NHn + hq) * 32 + jt) * TILE_U32;
    #pragma unroll
    for (int nt = 0; nt < 4; nt++) {
        int d = 32 * wn + 8 * nt + 2 * rb4;
        float b0 = bp[n0 + d], b1 = bp[n0 + d + 1];
        #pragma unroll
        for (int half = 0; half < 2; half++) {
            int row = 16 * wm + rd4 + 8 * half;
            float v0 = (c[nt][2 * half + 0] + b0) * sc;
            float v1 = (c[nt][2 * half + 1] + b1) * sc;
            u32 hp = pkbf(v0, v1);
            u32 lp = pkbf(v0 - bflo(hp), v1 - bfhi(hp));
            int offu = (swq(row, d >> 3) + (d & 7) * 2) >> 2;
            gh[tilebase + offu] = hp;
            gl[tilebase + offu] = lp;
        }
    }
}

// ---------------------------------------------------------------------------
// Kernel 2: HMMA flash attention, split-softmax per wn-half, plane-copy
// staging, register prefetch.
// ---------------------------------------------------------------------------
__global__ __launch_bounds__(256, 2) void attn_kernel(
    const float* __restrict__ mask,
    const float* __restrict__ rke,
    const float* __restrict__ rve,
    float* __restrict__ out)
{
    extern __shared__ char smc[];
    __nv_bfloat16* smh = (__nv_bfloat16*)smc;
    const u32 smb = (u32)__cvta_generic_to_shared(smc);

    const int tid = threadIdx.x;
    const int lane = tid & 31;
    const int w = tid >> 5, wm = w & 3, wn = w >> 2;
    const int hq = blockIdx.y, bz = blockIdx.z;
    const int bh = bz * NHn + hq;
    const int i0 = blockIdx.x * 64;

    const size_t tb = (size_t)bh * 32;
    const float* maskg = mask + (size_t)bz * Sn;

    // ---- W init to -1e30 ----
    {
        __nv_bfloat16 hneg = __float2bfloat16(-1e30f);
        unsigned short us = __bfloat16_as_ushort(hneg);
        u32 vv = (u32)us | ((u32)us << 16);
        u32* w32 = (u32*)(smc + Wo);
        #pragma unroll
        for (int t = 0; t < 32; t++) w32[tid + t * 256] = vv;
        if (tid < 8382 - 32 * 256) w32[tid + 32 * 256] = vv;
    }

    // ---- Q planes: pure copy ----
    {
        float4 qv[4];
        ldg_planes(g_Qh + (tb + blockIdx.x) * TILE_U32,
                   g_Ql + (tb + blockIdx.x) * TILE_U32, qv, tid);
        sts_planes(qv, smc, QHo, QLo, tid);
    }
    __syncthreads();

    const int rb4 = lane & 3, rd4 = lane >> 2;
    // ---- relc via MMA (rke is f32: conversion path) ----
    for (int rb = 0; rb < 4; rb++) {
        load_split_s(rke + rb * 64 * 64, 64, smc, KVHo, KVLo, tid);
        __syncthreads();
        float c[4][4] = {};
        mma_scores(c, smb, wm, wn, lane);
        #pragma unroll
        for (int nt = 0; nt < 4; nt++) {
            #pragma unroll
            for (int e = 0; e < 4; e++) {
                int m = 16 * wm + rd4 + (e >> 1) * 8;
                int r = rb * 64 + 32 * wn + 8 * nt + 2 * rb4 + (e & 1);
                smh[(RELCo >> 1) + m * 256 + r] = __float2bfloat16(c[nt][e]);
            }
        }
        __syncthreads();
    }

    float ctx[8][4] = {};
    float mu[2] = {-1e30f, -1e30f}, l[2] = {}, plo[2] = {}, phi[2] = {};
    const int rbase = 16 * wm + rd4;

    float4 kr[4], vr[4];
    ldg_planes(g_Kh + tb * TILE_U32, g_Kl + tb * TILE_U32, kr, tid);

    for (int jt = 0; jt < 32; jt++) {
        const int j0 = jt * 64;
        const int doff = j0 - i0;
        __syncthreads();                       // prev PV reads done
        sts_planes(kr, smc, KVHo, KVLo, tid);
        __syncthreads();                       // K ready

        float c[4][4] = {};
        mma_scores(c, smb, wm, wn, lane);

        ldg_planes(g_Vh + (tb + jt) * TILE_U32, g_Vl + (tb + jt) * TILE_U32, vr, tid);

        float mb[4][2];
        #pragma unroll
        for (int nt = 0; nt < 4; nt++) {
            float2 mv = __ldg((const float2*)(maskg + j0 + 32 * wn + 8 * nt + 2 * rb4));
            mb[nt][0] = (1.0f - mv.x) * -10000.0f;
            mb[nt][1] = (1.0f - mv.y) * -10000.0f;
        }

        const bool pure_lo = (doff + 63 <= -128);
        const bool pure_hi = (doff - 63 >= 127);
        const bool pure = pure_lo || pure_hi;
        const bool has_clamp = !pure && !((doff - 63 >= -127) && (doff + 63 <= 126));

        if (pure) {
            const int b = pure_lo ? 0 : 255;
            float rb0 = __bfloat162float(smh[(RELCo >> 1) + rbase * 256 + b]);
            float rb1 = __bfloat162float(smh[(RELCo >> 1) + (rbase + 8) * 256 + b]);
            #pragma unroll
            for (int nt = 0; nt < 4; nt++)
                #pragma unroll
                for (int e = 0; e < 4; e++)
                    c[nt][e] += ((e >> 1) ? rb1 : rb0) + mb[nt][e & 1];
        } else {
            #pragma unroll
            for (int nt = 0; nt < 4; nt++) {
                #pragma unroll
                for (int e = 0; e < 4; e++) {
                    int row = rbase + (e >> 1) * 8;
                    int col = 32 * wn + 8 * nt + 2 * rb4 + (e & 1);
                    int dlt = doff + col - row;
                    int bkt = max(-128, min(127, dlt)) + 128;
                    c[nt][e] += __bfloat162float(
                                    smh[(RELCo >> 1) + row * 256 + bkt]) + mb[nt][e & 1];
                    if (dlt > -128 && dlt < 127)
                        smh[(Wo >> 1) + (dlt + 127) * 66 + row] = __float2bfloat16(c[nt][e]);
                }
            }
        }

        // ---- independent per-half online softmax (warp-local only) ----
        float alpha[2];
        #pragma unroll
        for (int rl = 0; rl < 2; rl++) {
            int row = rbase + 8 * rl;
            float rm = fmaxf(fmaxf(c[0][2 * rl], c[0][2 * rl + 1]),
                             fmaxf(c[1][2 * rl], c[1][2 * rl + 1]));
            rm = fmaxf(rm, fmaxf(fmaxf(c[2][2 * rl], c[2][2 * rl + 1]),
                                 fmaxf(c[3][2 * rl], c[3][2 * rl + 1])));
            rm = fmaxf(rm, __shfl_xor_sync(0xffffffffu, rm, 1));
            rm = fmaxf(rm, __shfl_xor_sync(0xffffffffu, rm, 2));
            float nm = fmaxf(mu[rl], rm);
            alpha[rl] = __expf(mu[rl] - nm);
            mu[rl] = nm;
            float sum = 0.f;
            #pragma unroll
            for (int nt = 0; nt < 4; nt++) {
                #pragma unroll
                for (int h = 0; h < 2; h++) {
                    int e = 2 * rl + h;
                    float p = __expf(c[nt][e] - nm);
                    c[nt][e] = p;
                    sum += p;
                }
            }
            sum += __shfl_xor_sync(0xffffffffu, sum, 1);
            sum += __shfl_xor_sync(0xffffffffu, sum, 2);
            l[rl] = l[rl] * alpha[rl] + sum;
            float addlo = 0.f, addhi = 0.f;
            if (pure_lo)      addlo = sum;
            else if (pure_hi) addhi = sum;
            else if (has_clamp) {
                float clo = 0.f, chi = 0.f;
                #pragma unroll
                for (int nt = 0; nt < 4; nt++) {
                    #pragma unroll
                    for (int h = 0; h < 2; h++) {
                        int col = 32 * wn + 8 * nt + 2 * rb4 + h;
                        int dlt = doff + col - row;
                        float p = c[nt][2 * rl + h];
                        if (dlt <= -128)     clo += p;
                        else if (dlt >= 127) chi += p;
                    }
                }
                clo += __shfl_xor_sync(0xffffffffu, clo, 1);
                clo += __shfl_xor_sync(0xffffffffu, clo, 2);
                chi += __shfl_xor_sync(0xffffffffu, chi, 1);
                chi += __shfl_xor_sync(0xffffffffu, chi, 2);
                addlo = clo; addhi = chi;
            }
            plo[rl] = plo[rl] * alpha[rl] + addlo;
            phi[rl] = phi[rl] * alpha[rl] + addhi;
        }
        #pragma unroll
        for (int dnt = 0; dnt < 8; dnt++) {
            ctx[dnt][0] *= alpha[0]; ctx[dnt][1] *= alpha[0];
            ctx[dnt][2] *= alpha[1]; ctx[dnt][3] *= alpha[1];
        }

        // pack P fragments (hi/lo)
        u32 Ah[2][4], Al[2][4];
        #pragma unroll
        for (int kf = 0; kf < 2; kf++) {
            #pragma unroll
            for (int h = 0; h < 2; h++) {
                int nt = 2 * kf + h;
                u32 h0 = pkbf(c[nt][0], c[nt][1]);
                u32 h1 = pkbf(c[nt][2], c[nt][3]);
                Ah[kf][2 * h]     = h0;
                Ah[kf][2 * h + 1] = h1;
                Al[kf][2 * h]     = pkbf(c[nt][0] - bflo(h0), c[nt][1] - bfhi(h0));
                Al[kf][2 * h + 1] = pkbf(c[nt][2] - bflo(h1), c[nt][3] - bfhi(h1));
            }
        }

        __syncthreads();                       // all score K-reads done
        sts_planes(vr, smc, KVHo, KVLo, tid);  // V into planes
        if (jt < 31)
            ldg_planes(g_Kh + (tb + jt + 1) * TILE_U32,
                       g_Kl + (tb + jt + 1) * TILE_U32, kr, tid);
        __syncthreads();                       // V ready

        // PV
        {
            int vrow = 32 * wn + lane;
            #pragma unroll
            for (int dnt = 0; dnt < 8; dnt++) {
                u32 vAddr = smb + (u32)(KVHo + swq(vrow, dnt));
                u32 bhv[4], blv[4];
                ldm_x4t(bhv[0], bhv[1], bhv[2], bhv[3], vAddr);
                ldm_x4t(blv[0], blv[1], blv[2], blv[3], vAddr + (KVLo - KVHo));
                #pragma unroll
                for (int kf = 0; kf < 2; kf++) {
                    mma_bf16(ctx[dnt], Ah[kf], bhv[2 * kf], bhv[2 * kf + 1]);
                    mma_bf16(ctx[dnt], Ah[kf], blv[2 * kf], blv[2 * kf + 1]);
                    mma_bf16(ctx[dnt], Al[kf], bhv[2 * kf], bhv[2 * kf + 1]);
                }
            }
        }
    }

    // ---- epilogue: publish per-half stats, merge, combine ctx ----
    float* muA = (float*)(smc + MUAo);
    float* muB = (float*)(smc + MUBo);
    float* lA  = (float*)(smc + LAo);
    float* lB  = (float*)(smc + LBo);
    float* plA = (float*)(smc + PLAo);
    float* plB = (float*)(smc + PLBo);
    float* phA = (float*)(smc + PHAo);
    float* phB = (float*)(smc + PHBo);
    __syncthreads();
    if ((lane & 3) == 0) {
        #pragma unroll
        for (int rl = 0; rl < 2; rl++) {
            int row = rbase + 8 * rl;
            if (wn == 0) { muA[row] = mu[rl]; lA[row] = l[rl];
                           plA[row] = plo[rl]; phA[row] = phi[rl]; }
            else         { muB[row] = mu[rl]; lB[row] = l[rl];
                           plB[row] = plo[rl]; phB[row] = phi[rl]; }
        }
    }
    __syncthreads();

    float* ctxp = (float*)(smc + CTXo);
    float* lv   = (float*)(smc + LVo);
    float* plv  = (float*)(smc + PLOo);
    float* phv  = (float*)(smc + PHIo);
    float* muv  = (float*)(smc + MUo);
    float fw[2];
    #pragma unroll
    for (int rl = 0; rl < 2; rl++) {
        int row = rbase + 8 * rl;
        float M = fmaxf(muA[row], muB[row]);
        fw[rl] = __expf((wn == 0 ? muA[row] : muB[row]) - M);
        if (wn == 0 && (lane & 3) == 0) {
            float fa = __expf(muA[row] - M), fb = __expf(muB[row] - M);
            lv[row]  = lA[row]  * fa + lB[row]  * fb;
            plv[row] = plA[row] * fa + plB[row] * fb;
            phv[row] = phA[row] * fa + phB[row] * fb;
            muv[row] = M;
        }
    }
    if (wn == 0) {
        #pragma unroll
        for (int dnt = 0; dnt < 8; dnt++) {
            int dbase = 8 * dnt + 2 * rb4;
            *(float2*)&ctxp[rbase * 64 + dbase] =
                make_float2(ctx[dnt][0] * fw[0], ctx[dnt][1] * fw[0]);
            *(float2*)&ctxp[(rbase + 8) * 64 + dbase] =
                make_float2(ctx[dnt][2] * fw[1], ctx[dnt][3] * fw[1]);
        }
    }
    __syncthreads();
    if (wn == 1) {
        #pragma unroll
        for (int dnt = 0; dnt < 8; dnt++) {
            int dbase = 8 * dnt + 2 * rb4;
            float2 a0 = *(float2*)&ctxp[rbase * 64 + dbase];
            float2 a1 = *(float2*)&ctxp[(rbase + 8) * 64 + dbase];
            *(float2*)&ctxp[rbase * 64 + dbase] =
                make_float2(a0.x + ctx[dnt][0] * fw[0], a0.y + ctx[dnt][1] * fw[0]);
            *(float2*)&ctxp[(rbase + 8) * 64 + dbase] =
                make_float2(a1.x + ctx[dnt][2] * fw[1], a1.y + ctx[dnt][3] * fw[1]);
        }
    }
    __syncthreads();

    // ---- E-pass: W := exp(W - mu[m]) ----
    #pragma unroll 4
    for (int t = 0; t < 64; t++) {
        int idx = tid + t * 256;
        if (idx < 254 * 64) {
            int r = idx >> 6, m = idx & 63;
            float wv = __bfloat162float(smh[(Wo >> 1) + r * 66 + m]);
            smh[(Wo >> 1) + r * 66 + m] = __float2bfloat16(__expf(wv - muv[m]));
        }
    }
    __syncthreads();

    // ---- rve GEMM + final ----
    {
        const int ty = tid >> 5, tx = tid & 31;
        u64 o2[4][2];
        #pragma unroll
        for (int rp = 0; rp < 4; rp++)
            #pragma unroll
            for (int di = 0; di < 2; di++)
                o2[rp][di] = pk2(ctxp[(ty * 8 + 2 * rp) * 64 + tx * 2 + di],
                                 ctxp[(ty * 8 + 2 * rp + 1) * 64 + tx * 2 + di]);

        #pragma unroll 2
        for (int r = 0; r < 254; r++) {
            const __nv_bfloat162* wr =
                (const __nv_bfloat162*)&smh[(Wo >> 1) + r * 66 + ty * 8];
            __nv_bfloat162 e0 = wr[0], e1 = wr[1], e2 = wr[2], e3 = wr[3];
            float2 rv = __ldg((const float2*)(rve + (r + 1) * 64 + tx * 2));
            u64 r0 = dup2(rv.x), r1 = dup2(rv.y);
            float2 f0 = __bfloat1622float2(e0);
            float2 f1 = __bfloat1622float2(e1);
            float2 f2 = __bfloat1622float2(e2);
            float2 f3 = __bfloat1622float2(e3);
            u64 ep0 = pk2(f0.x, f0.y), ep1 = pk2(f1.x, f1.y);
            u64 ep2 = pk2(f2.x, f2.y), ep3 = pk2(f3.x, f3.y);
            o2[0][0] = ffma2(ep0, r0, o2[0][0]);
            o2[0][1] = ffma2(ep0, r1, o2[0][1]);
            o2[1][0] = ffma2(ep1, r0, o2[1][0]);
            o2[1][1] = ffma2(ep1, r1, o2[1][1]);
            o2[2][0] = ffma2(ep2, r0, o2[2][0]);
            o2[2][1] = ffma2(ep2, r1, o2[2][1]);
            o2[3][0] = ffma2(ep3, r0, o2[3][0]);
            o2[3][1] = ffma2(ep3, r1, o2[3][1]);
        }

        float2 rv0 = __ldg((const float2*)(rve + 0 * 64 + tx * 2));
        float2 rvN = __ldg((const float2*)(rve + 255 * 64 + tx * 2));
        #pragma unroll
        for (int rp = 0; rp < 4; rp++) {
            float2 c0 = up2(o2[rp][0]), c1 = up2(o2[rp][1]);
            #pragma unroll
            for (int h = 0; h < 2; h++) {
                int ri = 2 * rp + h;
                int row = ty * 8 + ri;
                float ox = h ? c0.y : c0.x;
                float oy = h ? c1.y : c1.x;
                float inv = 1.0f / lv[row];
                float2 res;
                res.x = (ox + plv[row] * rv0.x + phv[row] * rvN.x) * inv;
                res.y = (oy + plv[row] * rv0.y + phv[row] * rvN.y) * inv;
                *(float2*)(out + ((size_t)bz * Sn + i0 + row) * Hn + hq * 64 + tx * 2) = res;
            }
        }
    }
}

// ---------------------------------------------------------------------------
extern "C" void kernel_launch(void* const* d_in, const int* in_sizes, int n_in,
                              void* d_out, int out_size)
{
    const float* X    = (const float*)d_in[0];
    const float* mask = (const float*)d_in[1];
    const float* Wq   = (const float*)d_in[2];
    const float* bq   = (const float*)d_in[3];
    const float* Wk   = (const float*)d_in[4];
    const float* bk   = (const float*)d_in[5];
    const float* Wv   = (const float*)d_in[6];
    const float* bv   = (const float*)d_in[7];
    const float* rke  = (const float*)d_in[8];
    const float* rve  = (const float*)d_in[9];
    float* out = (float*)d_out;

    (void)in_sizes; (void)n_in; (void)out_size;

    cudaFuncSetAttribute(attn_kernel,
                         cudaFuncAttributeMaxDynamicSharedMemorySize, SMEMB);

    qkv_kernel<<<dim3(64, NHn, 3), 256>>>(X, Wq, bq, Wk, bk, Wv, bv);
    attn_kernel<<<dim3(32, NHn, Bn), 256, SMEMB>>>(mask, rke, rve, out);
}

// round 14
// speedup vs baseline: 2.0928x; 1.0739x over previous
#include <cuda_runtime.h>
#include <cuda_bf16.h>

// ---------------------------------------------------------------------------
// GraphEncoder relative-position attention, GB300 sm_103a — round 14
// R13 + (1) V kept as bf16 hi-plane only in PV (drop Ah*Bl correction),
// (2) separate K and V smem regions -> 2 syncs per tile (was 4), batched
// staging window, K/V register prefetch carried across iterations.
// ---------------------------------------------------------------------------

namespace {
constexpr int Bn  = 2;
constexpr int Sn  = 2048;
constexpr int Hn  = 768;
constexpr int NHn = 12;
constexpr int TILE_U32 = 2048;        // one 64x64 bf16 plane tile = 8192 B

// smem byte offsets (attention)
constexpr int QHo   = 0;         // Q hi plane (8192)
constexpr int QLo   = 8192;      // Q lo plane
constexpr int KHo   = 16384;     // K hi plane
constexpr int KLo   = 24576;     // K lo plane
constexpr int VHo   = 32768;     // V hi plane (8192)
constexpr int RELCo = 40960;     // relc bf16 [64][256] (32768)
constexpr int Wo    = 73728;     // W bf16 [254][66]    (33528)
// split-softmax stats (f32 [64] each)
constexpr int MUAo  = 107256;
constexpr int MUBo  = 107512;
constexpr int LAo   = 107768;
constexpr int LBo   = 108024;
constexpr int PLAo  = 108280;
constexpr int PLBo  = 108536;
constexpr int PHAo  = 108792;
constexpr int PHBo  = 109048;
constexpr int SMEMB = 109304;
// epilogue overlays (Q/K planes dead)
constexpr int CTXo  = 0;
constexpr int LVo   = 16384;
constexpr int PLOo  = 16640;
constexpr int PHIo  = 16896;
constexpr int MUo   = 17152;
}

typedef unsigned long long u64;
typedef unsigned int u32;

// pre-split bf16 plane tiles: [Bn*NHn*32 tiles][2048 u32]
__device__ u32 g_Qh[Bn * NHn * 32 * TILE_U32];
__device__ u32 g_Ql[Bn * NHn * 32 * TILE_U32];
__device__ u32 g_Kh[Bn * NHn * 32 * TILE_U32];
__device__ u32 g_Kl[Bn * NHn * 32 * TILE_U32];
__device__ u32 g_Vh[Bn * NHn * 32 * TILE_U32];

__device__ __forceinline__ u64 pk2(float lo, float hi) {
    u64 r; asm("mov.b64 %0,{%1,%2};" : "=l"(r) : "f"(lo), "f"(hi)); return r;
}
__device__ __forceinline__ u64 dup2(float v) { return pk2(v, v); }
__device__ __forceinline__ u64 ffma2(u64 a, u64 b, u64 c) {
    u64 d; asm("fma.rn.f32x2 %0,%1,%2,%3;" : "=l"(d) : "l"(a), "l"(b), "l"(c)); return d;
}
__device__ __forceinline__ float2 up2(u64 v) {
    float2 f; asm("mov.b64 {%0,%1},%2;" : "=f"(f.x), "=f"(f.y) : "l"(v)); return f;
}
__device__ __forceinline__ u32 pkbf(float lo, float hi) {
    u32 d; asm("cvt.rn.bf16x2.f32 %0,%1,%2;" : "=r"(d) : "f"(hi), "f"(lo)); return d;
}
__device__ __forceinline__ float bflo(u32 h) { return __uint_as_float(h << 16); }
__device__ __forceinline__ float bfhi(u32 h) { return __uint_as_float(h & 0xFFFF0000u); }

// plane byte offset: 128B rows, 16B chunk ch swizzled by row bits
__device__ __forceinline__ int swq(int row, int ch) {
    return row * 128 + ((ch ^ (row & 7) ^ ((row >> 3) & 3)) << 4);
}

__device__ __forceinline__ void ldm_x4(u32& r0, u32& r1, u32& r2, u32& r3, u32 a) {
    asm volatile("ldmatrix.sync.aligned.m8n8.x4.shared.b16 {%0,%1,%2,%3},[%4];"
                 : "=r"(r0), "=r"(r1), "=r"(r2), "=r"(r3) : "r"(a));
}
__device__ __forceinline__ void ldm_x2(u32& r0, u32& r1, u32 a) {
    asm volatile("ldmatrix.sync.aligned.m8n8.x2.shared.b16 {%0,%1},[%2];"
                 : "=r"(r0), "=r"(r1) : "r"(a));
}
__device__ __forceinline__ void ldm_x4t(u32& r0, u32& r1, u32& r2, u32& r3, u32 a) {
    asm volatile("ldmatrix.sync.aligned.m8n8.x4.trans.shared.b16 {%0,%1,%2,%3},[%4];"
                 : "=r"(r0), "=r"(r1), "=r"(r2), "=r"(r3) : "r"(a));
}
__device__ __forceinline__ void mma_bf16(float* d, const u32* a, u32 b0, u32 b1) {
    asm volatile("mma.sync.aligned.m16n8k16.row.col.f32.bf16.bf16.f32 "
                 "{%0,%1,%2,%3},{%4,%5,%6,%7},{%8,%9},{%0,%1,%2,%3};"
                 : "+f"(d[0]), "+f"(d[1]), "+f"(d[2]), "+f"(d[3])
                 : "r"(a[0]), "r"(a[1]), "r"(a[2]), "r"(a[3]), "r"(b0), "r"(b1));
}

// ---- bf16 plane-tile copies ----
__device__ __forceinline__ void ldg_planes(const u32* __restrict__ gh,
                                           const u32* __restrict__ gl,
                                           float4 v[4], int tid)
{
    v[0] = __ldg((const float4*)gh + tid);
    v[1] = __ldg((const float4*)gh + tid + 256);
    v[2] = __ldg((const float4*)gl + tid);
    v[3] = __ldg((const float4*)gl + tid + 256);
}
__device__ __forceinline__ void sts_planes(const float4 v[4], char* smc,
                                           int hiOff, int loOff, int tid)
{
    *((float4*)(smc + hiOff) + tid)       = v[0];
    *((float4*)(smc + hiOff) + tid + 256) = v[1];
    *((float4*)(smc + loOff) + tid)       = v[2];
    *((float4*)(smc + loOff) + tid + 256) = v[3];
}
__device__ __forceinline__ void ldg_planes_hi(const u32* __restrict__ gh,
                                              float4 v[2], int tid)
{
    v[0] = __ldg((const float4*)gh + tid);
    v[1] = __ldg((const float4*)gh + tid + 256);
}
__device__ __forceinline__ void sts_planes_hi(const float4 v[2], char* smc,
                                              int hiOff, int tid)
{
    *((float4*)(smc + hiOff) + tid)       = v[0];
    *((float4*)(smc + hiOff) + tid + 256) = v[1];
}

// ---- f32 tile -> split planes (rke / qkv X) ----
__device__ __forceinline__ void ldg_tile_s(const float* __restrict__ src,
                                           int stride, float4 v[4], int tid)
{
    #pragma unroll
    for (int s = 0; s < 4; s++) {
        int f = tid + s * 256;
        v[s] = __ldg((const float4*)(src + (size_t)(f >> 4) * stride + (f & 15) * 4));
    }
}
__device__ __forceinline__ void sts_split(const float4 v[4], char* smc,
                                          int hiOff, int loOff, int tid)
{
    #pragma unroll
    for (int s = 0; s < 4; s++) {
        int f = tid + s * 256;
        int row = f >> 4, cg = f & 15;
        float4 w = v[s];
        __nv_bfloat162 h0 = __floats2bfloat162_rn(w.x, w.y);
        __nv_bfloat162 h1 = __floats2bfloat162_rn(w.z, w.w);
        float2 f0 = __bfloat1622float2(h0);
        float2 f1 = __bfloat1622float2(h1);
        __nv_bfloat162 l0 = __floats2bfloat162_rn(w.x - f0.x, w.y - f0.y);
        __nv_bfloat162 l1 = __floats2bfloat162_rn(w.z - f1.x, w.w - f1.y);
        int off = swq(row, cg >> 1) + ((cg & 1) << 3);
        *(__nv_bfloat162*)(smc + hiOff + off)     = h0;
        *(__nv_bfloat162*)(smc + hiOff + off + 4) = h1;
        *(__nv_bfloat162*)(smc + loOff + off)     = l0;
        *(__nv_bfloat162*)(smc + loOff + off + 4) = l1;
    }
}
__device__ __forceinline__ void load_split_s(const float* __restrict__ src,
                                             int stride, char* smc,
                                             int hiOff, int loOff, int tid)
{
    float4 v[4];
    ldg_tile_s(src, stride, v, tid);
    sts_split(v, smc, hiOff, loOff, tid);
}

// 64x64x64 split-bf16 GEMM step: c[nt][e] += A(Q planes) . B(K planes)
__device__ __forceinline__ void mma_scores(float c[4][4], u32 smb,
                                           int wm, int wn, int lane)
{
    const int r8 = lane & 7;
    const int j4 = lane >> 3;
    const int jb = (lane >> 3) & 1;
    #pragma unroll
    for (int ks = 0; ks < 4; ks++) {
        int mrow = 16 * wm + r8 + (j4 & 1) * 8;
        int chA = 2 * ks + (j4 >> 1);
        u32 aAddr = smb + (u32)(QHo + swq(mrow, chA));
        u32 ah[4], al[4];
        ldm_x4(ah[0], ah[1], ah[2], ah[3], aAddr);
        ldm_x4(al[0], al[1], al[2], al[3], aAddr + (QLo - QHo));
        #pragma unroll
        for (int nt = 0; nt < 4; nt++) {
            int n = 32 * wn + 8 * nt + r8;
            int chB = 2 * ks + jb;
            u32 bAddr = smb + (u32)(KHo + swq(n, chB));
            u32 bh0, bh1, bl0, bl1;
            ldm_x2(bh0, bh1, bAddr);
            ldm_x2(bl0, bl1, bAddr + (KLo - KHo));
            mma_bf16(c[nt], ah, bh0, bh1);
            mma_bf16(c[nt], ah, bl0, bl1);
            mma_bf16(c[nt], al, bh0, bh1);
        }
    }
}

// ---------------------------------------------------------------------------
// Kernel 1: HMMA QKV projection -> pre-split bf16 plane tiles in gmem.
// ---------------------------------------------------------------------------
__global__ __launch_bounds__(256) void qkv_kernel(
    const float* __restrict__ X,
    const float* __restrict__ Wq, const float* __restrict__ bq,
    const float* __restrict__ Wk, const float* __restrict__ bk,
    const float* __restrict__ Wv, const float* __restrict__ bv)
{
    __shared__ char smc[32768];
    const u32 smb = (u32)__cvta_generic_to_shared(smc);

    const int z = blockIdx.z;
    const float* Wp = (z == 0) ? Wq : ((z == 1) ? Wk : Wv);
    const float* bp = (z == 0) ? bq : ((z == 1) ? bk : bv);
    u32* gh = (z == 0) ? g_Qh : ((z == 1) ? g_Kh : g_Vh);
    u32* gl = (z == 0) ? g_Ql : ((z == 1) ? g_Kl : (u32*)nullptr);
    const float sc = (z == 0) ? 0.125f : 1.0f;

    const int r0 = blockIdx.x * 64;
    const int hq = blockIdx.y;
    const int n0 = hq * 64;
    const int tid = threadIdx.x;
    const int lane = tid & 31;
    const int w = tid >> 5, wm = w & 3, wn = w >> 2;
    const int rb4 = lane & 3, rd4 = lane >> 2;

    float c[4][4] = {};
    float4 xr[4], wra[2], wrb[2];

    const int f0i = tid, f1i = tid + 256;
    const int kp0 = f0i >> 4, ng0 = f0i & 15;
    const int kp1 = f1i >> 4, ng1 = f1i & 15;

    ldg_tile_s(X + (size_t)r0 * 768, 768, xr, tid);
    {
        const float* w0 = Wp + (size_t)(2 * kp0) * 768 + n0 + ng0 * 4;
        const float* w1 = Wp + (size_t)(2 * kp1) * 768 + n0 + ng1 * 4;
        wra[0] = __ldg((const float4*)w0); wrb[0] = __ldg((const float4*)(w0 + 768));
        wra[1] = __ldg((const float4*)w1); wrb[1] = __ldg((const float4*)(w1 + 768));
    }

    for (int kt = 0; kt < 12; kt++) {
        __syncthreads();
        sts_split(xr, smc, QHo, QLo, tid);
        #pragma unroll
        for (int it = 0; it < 2; it++) {
            int kp = it ? kp1 : kp0, ng = it ? ng1 : ng0;
            int k0 = 2 * kp, nn = ng * 4;
            float av[4] = {it ? wra[1].x : wra[0].x, it ? wra[1].y : wra[0].y,
                           it ? wra[1].z : wra[0].z, it ? wra[1].w : wra[0].w};
            float bw[4] = {it ? wrb[1].x : wrb[0].x, it ? wrb[1].y : wrb[0].y,
                           it ? wrb[1].z : wrb[0].z, it ? wrb[1].w : wrb[0].w};
            #pragma unroll
            for (int i = 0; i < 4; i++) {
                int ni = nn + i;
                u32 hp = pkbf(av[i], bw[i]);
                u32 lp = pkbf(av[i] - bflo(hp), bw[i] - bfhi(hp));
                int off = swq(ni, k0 >> 3) + (k0 & 7) * 2;
                *(u32*)(smc + KHo + off) = hp;
                *(u32*)(smc + KLo + off) = lp;
            }
        }
        __syncthreads();
        if (kt < 11) {
            ldg_tile_s(X + (size_t)r0 * 768 + (kt + 1) * 64, 768, xr, tid);
            const float* w0 = Wp + (size_t)((kt + 1) * 64 + 2 * kp0) * 768 + n0 + ng0 * 4;
            const float* w1 = Wp + (size_t)((kt + 1) * 64 + 2 * kp1) * 768 + n0 + ng1 * 4;
            wra[0] = __ldg((const float4*)w0); wrb[0] = __ldg((const float4*)(w0 + 768));
            wra[1] = __ldg((const float4*)w1); wrb[1] = __ldg((const float4*)(w1 + 768));
        }
        mma_scores(c, smb, wm, wn, lane);
    }

    // epilogue: bias+scale, split to bf16 hi/lo plane tiles
    const int b  = r0 >> 11;
    const int jt = (r0 & 2047) >> 6;
    const size_t tilebase = ((size_t)(b * NHn + hq) * 32 + jt) * TILE_U32;
    #pragma unroll
    for (int nt = 0; nt < 4; nt++) {
        int d = 32 * wn + 8 * nt + 2 * rb4;
        float b0 = bp[n0 + d], b1 = bp[n0 + d + 1];
        #pragma unroll
        for (int half = 0; half < 2; half++) {
            int row = 16 * wm + rd4 + 8 * half;
            float v0 = (c[nt][2 * half + 0] + b0) * sc;
            float v1 = (c[nt][2 * half + 1] + b1) * sc;
            u32 hp = pkbf(v0, v1);
            int offu = (swq(row, d >> 3) + (d & 7) * 2) >> 2;
            gh[tilebase + offu] = hp;
            if (z != 2) {
                u32 lp = pkbf(v0 - bflo(hp), v1 - bfhi(hp));
                gl[tilebase + offu] = lp;
            }
        }
    }
}

// ---------------------------------------------------------------------------
// Kernel 2: HMMA flash attention, 2-sync pipelined tile loop.
// ---------------------------------------------------------------------------
__global__ __launch_bounds__(256, 2) void attn_kernel(
    const float* __restrict__ mask,
    const float* __restrict__ rke,
    const float* __restrict__ rve,
    float* __restrict__ out)
{
    extern __shared__ char smc[];
    __nv_bfloat16* smh = (__nv_bfloat16*)smc;
    const u32 smb = (u32)__cvta_generic_to_shared(smc);

    const int tid = threadIdx.x;
    const int lane = tid & 31;
    const int w = tid >> 5, wm = w & 3, wn = w >> 2;
    const int hq = blockIdx.y, bz = blockIdx.z;
    const int bh = bz * NHn + hq;
    const int i0 = blockIdx.x * 64;

    const size_t tb = (size_t)bh * 32;
    const float* maskg = mask + (size_t)bz * Sn;

    // ---- W init to -1e30 ----
    {
        __nv_bfloat16 hneg = __float2bfloat16(-1e30f);
        unsigned short us = __bfloat16_as_ushort(hneg);
        u32 vv = (u32)us | ((u32)us << 16);
        u32* w32 = (u32*)(smc + Wo);
        #pragma unroll
        for (int t = 0; t < 32; t++) w32[tid + t * 256] = vv;
        if (tid < 8382 - 32 * 256) w32[tid + 32 * 256] = vv;
    }

    // ---- Q planes: pure copy ----
    {
        float4 qv[4];
        ldg_planes(g_Qh + (tb + blockIdx.x) * TILE_U32,
                   g_Ql + (tb + blockIdx.x) * TILE_U32, qv, tid);
        sts_planes(qv, smc, QHo, QLo, tid);
    }
    __syncthreads();

    const int rb4 = lane & 3, rd4 = lane >> 2;
    // ---- relc via MMA (rke f32 -> split into K planes) ----
    for (int rb = 0; rb < 4; rb++) {
        load_split_s(rke + rb * 64 * 64, 64, smc, KHo, KLo, tid);
        __syncthreads();
        float c[4][4] = {};
        mma_scores(c, smb, wm, wn, lane);
        #pragma unroll
        for (int nt = 0; nt < 4; nt++) {
            #pragma unroll
            for (int e = 0; e < 4; e++) {
                int m = 16 * wm + rd4 + (e >> 1) * 8;
                int r = rb * 64 + 32 * wn + 8 * nt + 2 * rb4 + (e & 1);
                smh[(RELCo >> 1) + m * 256 + r] = __float2bfloat16(c[nt][e]);
            }
        }
        __syncthreads();
    }

    float ctx[8][4] = {};
    float mu[2] = {-1e30f, -1e30f}, l[2] = {}, plo[2] = {}, phi[2] = {};
    const int rbase = 16 * wm + rd4;

    // ---- pipeline prologue: stage K0, prefetch V0 and K1 ----
    float4 kr[4], vr[2];
    ldg_planes(g_Kh + tb * TILE_U32, g_Kl + tb * TILE_U32, kr, tid);
    sts_planes(kr, smc, KHo, KLo, tid);
    ldg_planes_hi(g_Vh + tb * TILE_U32, vr, tid);
    ldg_planes(g_Kh + (tb + 1) * TILE_U32, g_Kl + (tb + 1) * TILE_U32, kr, tid);
    __syncthreads();   // K0 ready

    for (int jt = 0; jt < 32; jt++) {
        const int j0 = jt * 64;
        const int doff = j0 - i0;

        float c[4][4] = {};
        mma_scores(c, smb, wm, wn, lane);   // K_jt

        float mb[4][2];
        #pragma unroll
        for (int nt = 0; nt < 4; nt++) {
            float2 mv = __ldg((const float2*)(maskg + j0 + 32 * wn + 8 * nt + 2 * rb4));
            mb[nt][0] = (1.0f - mv.x) * -10000.0f;
            mb[nt][1] = (1.0f - mv.y) * -10000.0f;
        }

        const bool pure_lo = (doff + 63 <= -128);
        const bool pure_hi = (doff - 63 >= 127);
        const bool pure = pure_lo || pure_hi;
        const bool has_clamp = !pure && !((doff - 63 >= -127) && (doff + 63 <= 126));

        if (pure) {
            const int b = pure_lo ? 0 : 255;
            float rb0 = __bfloat162float(smh[(RELCo >> 1) + rbase * 256 + b]);
            float rb1 = __bfloat162float(smh[(RELCo >> 1) + (rbase + 8) * 256 + b]);
            #pragma unroll
            for (int nt = 0; nt < 4; nt++)
                #pragma unroll
                for (int e = 0; e < 4; e++)
                    c[nt][e] += ((e >> 1) ? rb1 : rb0) + mb[nt][e & 1];
        } else {
            #pragma unroll
            for (int nt = 0; nt < 4; nt++) {
                #pragma unroll
                for (int e = 0; e < 4; e++) {
                    int row = rbase + (e >> 1) * 8;
                    int col = 32 * wn + 8 * nt + 2 * rb4 + (e & 1);
                    int dlt = doff + col - row;
                    int bkt = max(-128, min(127, dlt)) + 128;
                    c[nt][e] += __bfloat162float(
                                    smh[(RELCo >> 1) + row * 256 + bkt]) + mb[nt][e & 1];
                    if (dlt > -128 && dlt < 127)
                        smh[(Wo >> 1) + (dlt + 127) * 66 + row] = __float2bfloat16(c[nt][e]);
                }
            }
        }

        // ---- per-half online softmax (warp-local) ----
        float alpha[2];
        #pragma unroll
        for (int rl = 0; rl < 2; rl++) {
            int row = rbase + 8 * rl;
            float rm = fmaxf(fmaxf(c[0][2 * rl], c[0][2 * rl + 1]),
                             fmaxf(c[1][2 * rl], c[1][2 * rl + 1]));
            rm = fmaxf(rm, fmaxf(fmaxf(c[2][2 * rl], c[2][2 * rl + 1]),
                                 fmaxf(c[3][2 * rl], c[3][2 * rl + 1])));
            rm = fmaxf(rm, __shfl_xor_sync(0xffffffffu, rm, 1));
            rm = fmaxf(rm, __shfl_xor_sync(0xffffffffu, rm, 2));
            float nm = fmaxf(mu[rl], rm);
            alpha[rl] = __expf(mu[rl] - nm);
            mu[rl] = nm;
            float sum = 0.f;
            #pragma unroll
            for (int nt = 0; nt < 4; nt++) {
                #pragma unroll
                for (int h = 0; h < 2; h++) {
                    int e = 2 * rl + h;
                    float p = __expf(c[nt][e] - nm);
                    c[nt][e] = p;
                    sum += p;
                }
            }
            sum += __shfl_xor_sync(0xffffffffu, sum, 1);
            sum += __shfl_xor_sync(0xffffffffu, sum, 2);
            l[rl] = l[rl] * alpha[rl] + sum;
            float addlo = 0.f, addhi = 0.f;
            if (pure_lo)      addlo = sum;
            else if (pure_hi) addhi = sum;
            else if (has_clamp) {
                float clo = 0.f, chi = 0.f;
                #pragma unroll
                for (int nt = 0; nt < 4; nt++) {
                    #pragma unroll
                    for (int h = 0; h < 2; h++) {
                        int col = 32 * wn + 8 * nt + 2 * rb4 + h;
                        int dlt = doff + col - row;
                        float p = c[nt][2 * rl + h];
                        if (dlt <= -128)     clo += p;
                        else if (dlt >= 127) chi += p;
                    }
                }
                clo += __shfl_xor_sync(0xffffffffu, clo, 1);
                clo += __shfl_xor_sync(0xffffffffu, clo, 2);
                chi += __shfl_xor_sync(0xffffffffu, chi, 1);
                chi += __shfl_xor_sync(0xffffffffu, chi, 2);
                addlo = clo; addhi = chi;
            }
            plo[rl] = plo[rl] * alpha[rl] + addlo;
            phi[rl] = phi[rl] * alpha[rl] + addhi;
        }
        #pragma unroll
        for (int dnt = 0; dnt < 8; dnt++) {
            ctx[dnt][0] *= alpha[0]; ctx[dnt][1] *= alpha[0];
            ctx[dnt][2] *= alpha[1]; ctx[dnt][3] *= alpha[1];
        }

        // pack P fragments (hi/lo)
        u32 Ah[2][4], Al[2][4];
        #pragma unroll
        for (int kf = 0; kf < 2; kf++) {
            #pragma unroll
            for (int h = 0; h < 2; h++) {
                int nt = 2 * kf + h;
                u32 h0 = pkbf(c[nt][0], c[nt][1]);
                u32 h1 = pkbf(c[nt][2], c[nt][3]);
                Ah[kf][2 * h]     = h0;
                Ah[kf][2 * h + 1] = h1;
                Al[kf][2 * h]     = pkbf(c[nt][0] - bflo(h0), c[nt][1] - bfhi(h0));
                Al[kf][2 * h + 1] = pkbf(c[nt][2] - bflo(h1), c[nt][3] - bfhi(h1));
            }
        }

        __syncthreads();   // prev PV V-reads + this tile's K-reads done
        sts_planes_hi(vr, smc, VHo, tid);            // V_jt
        if (jt < 31) sts_planes(kr, smc, KHo, KLo, tid);   // K_{jt+1}
        if (jt < 31)
            ldg_planes_hi(g_Vh + (tb + jt + 1) * TILE_U32, vr, tid);
        if (jt < 30)
            ldg_planes(g_Kh + (tb + jt + 2) * TILE_U32,
                       g_Kl + (tb + jt + 2) * TILE_U32, kr, tid);
        __syncthreads();   // V_jt + K_{jt+1} ready

        // ---- PV (V hi only): ctx += P_hi . V + P_lo . V ----
        {
            int vrow = 32 * wn + lane;
            #pragma unroll
            for (int dnt = 0; dnt < 8; dnt++) {
                u32 vAddr = smb + (u32)(VHo + swq(vrow, dnt));
                u32 bhv[4];
                ldm_x4t(bhv[0], bhv[1], bhv[2], bhv[3], vAddr);
                #pragma unroll
                for (int kf = 0; kf < 2; kf++) {
                    mma_bf16(ctx[dnt], Ah[kf], bhv[2 * kf], bhv[2 * kf + 1]);
                    mma_bf16(ctx[dnt], Al[kf], bhv[2 * kf], bhv[2 * kf + 1]);
                }
            }
        }
    }

    // ---- epilogue: per-half stats, merge, combine ctx ----
    float* muA = (float*)(smc + MUAo);
    float* muB = (float*)(smc + MUBo);
    float* lA  = (float*)(smc + LAo);
    float* lB  = (float*)(smc + LBo);
    float* plA = (float*)(smc + PLAo);
    float* plB = (float*)(smc + PLBo);
    float* phA = (float*)(smc + PHAo);
    float* phB = (float*)(smc + PHBo);
    __syncthreads();
    if ((lane & 3) == 0) {
        #pragma unroll
        for (int rl = 0; rl < 2; rl++) {
            int row = rbase + 8 * rl;
            if (wn == 0) { muA[row] = mu[rl]; lA[row] = l[rl];
                           plA[row] = plo[rl]; phA[row] = phi[rl]; }
            else         { muB[row] = mu[rl]; lB[row] = l[rl];
                           plB[row] = plo[rl]; phB[row] = phi[rl]; }
        }
    }
    __syncthreads();

    float* ctxp = (float*)(smc + CTXo);
    float* lv   = (float*)(smc + LVo);
    float* plv  = (float*)(smc + PLOo);
    float* phv  = (float*)(smc + PHIo);
    float* muv  = (float*)(smc + MUo);
    float fw[2];
    #pragma unroll
    for (int rl = 0; rl < 2; rl++) {
        int row = rbase + 8 * rl;
        float M = fmaxf(muA[row], muB[row]);
        fw[rl] = __expf((wn == 0 ? muA[row] : muB[row]) - M);
        if (wn == 0 && (lane & 3) == 0) {
            float fa = __expf(muA[row] - M), fb = __expf(muB[row] - M);
            lv[row]  = lA[row]  * fa + lB[row]  * fb;
            plv[row] = plA[row] * fa + plB[row] * fb;
            phv[row] = phA[row] * fa + phB[row] * fb;
            muv[row] = M;
        }
    }
    if (wn == 0) {
        #pragma unroll
        for (int dnt = 0; dnt < 8; dnt++) {
            int dbase = 8 * dnt + 2 * rb4;
            *(float2*)&ctxp[rbase * 64 + dbase] =
                make_float2(ctx[dnt][0] * fw[0], ctx[dnt][1] * fw[0]);
            *(float2*)&ctxp[(rbase + 8) * 64 + dbase] =
                make_float2(ctx[dnt][2] * fw[1], ctx[dnt][3] * fw[1]);
        }
    }
    __syncthreads();
    if (wn == 1) {
        #pragma unroll
        for (int dnt = 0; dnt < 8; dnt++) {
            int dbase = 8 * dnt + 2 * rb4;
            float2 a0 = *(float2*)&ctxp[rbase * 64 + dbase];
            float2 a1 = *(float2*)&ctxp[(rbase + 8) * 64 + dbase];
            *(float2*)&ctxp[rbase * 64 + dbase] =
                make_float2(a0.x + ctx[dnt][0] * fw[0], a0.y + ctx[dnt][1] * fw[0]);
            *(float2*)&ctxp[(rbase + 8) * 64 + dbase] =
                make_float2(a1.x + ctx[dnt][2] * fw[1], a1.y + ctx[dnt][3] * fw[1]);
        }
    }
    __syncthreads();

    // ---- E-pass: W := exp(W - mu[m]) ----
    #pragma unroll 4
    for (int t = 0; t < 64; t++) {
        int idx = tid + t * 256;
        if (idx < 254 * 64) {
            int r = idx >> 6, m = idx & 63;
            float wv = __bfloat162float(smh[(Wo >> 1) + r * 66 + m]);
            smh[(Wo >> 1) + r * 66 + m] = __float2bfloat16(__expf(wv - muv[m]));
        }
    }
    __syncthreads();

    // ---- rve GEMM + final ----
    {
        const int ty = tid >> 5, tx = tid & 31;
        u64 o2[4][2];
        #pragma unroll
        for (int rp = 0; rp < 4; rp++)
            #pragma unroll
            for (int di = 0; di < 2; di++)
                o2[rp][di] = pk2(ctxp[(ty * 8 + 2 * rp) * 64 + tx * 2 + di],
                                 ctxp[(ty * 8 + 2 * rp + 1) * 64 + tx * 2 + di]);

        #pragma unroll 2
        for (int r = 0; r < 254; r++) {
            const __nv_bfloat162* wr =
                (const __nv_bfloat162*)&smh[(Wo >> 1) + r * 66 + ty * 8];
            __nv_bfloat162 e0 = wr[0], e1 = wr[1], e2 = wr[2], e3 = wr[3];
            float2 rv = __ldg((const float2*)(rve + (r + 1) * 64 + tx * 2));
            u64 r0 = dup2(rv.x), r1 = dup2(rv.y);
            float2 f0 = __bfloat1622float2(e0);
            float2 f1 = __bfloat1622float2(e1);
            float2 f2 = __bfloat1622float2(e2);
            float2 f3 = __bfloat1622float2(e3);
            u64 ep0 = pk2(f0.x, f0.y), ep1 = pk2(f1.x, f1.y);
            u64 ep2 = pk2(f2.x, f2.y), ep3 = pk2(f3.x, f3.y);
            o2[0][0] = ffma2(ep0, r0, o2[0][0]);
            o2[0][1] = ffma2(ep0, r1, o2[0][1]);
            o2[1][0] = ffma2(ep1, r0, o2[1][0]);
            o2[1][1] = ffma2(ep1, r1, o2[1][1]);
            o2[2][0] = ffma2(ep2, r0, o2[2][0]);
            o2[2][1] = ffma2(ep2, r1, o2[2][1]);
            o2[3][0] = ffma2(ep3, r0, o2[3][0]);
            o2[3][1] = ffma2(ep3, r1, o2[3][1]);
        }

        float2 rv0 = __ldg((const float2*)(rve + 0 * 64 + tx * 2));
        float2 rvN = __ldg((const float2*)(rve + 255 * 64 + tx * 2));
        #pragma unroll
        for (int rp = 0; rp < 4; rp++) {
            float2 c0 = up2(o2[rp][0]), c1 = up2(o2[rp][1]);
            #pragma unroll
            for (int h = 0; h < 2; h++) {
                int ri = 2 * rp + h;
                int row = ty * 8 + ri;
                float ox = h ? c0.y : c0.x;
                float oy = h ? c1.y : c1.x;
                float inv = 1.0f / lv[row];
                float2 res;
                res.x = (ox + plv[row] * rv0.x + phv[row] * rvN.x) * inv;
                res.y = (oy + plv[row] * rv0.y + phv[row] * rvN.y) * inv;
                *(float2*)(out + ((size_t)bz * Sn + i0 + row) * Hn + hq * 64 + tx * 2) = res;
            }
        }
    }
}

// ---------------------------------------------------------------------------
extern "C" void kernel_launch(void* const* d_in, const int* in_sizes, int n_in,
                              void* d_out, int out_size)
{
    const float* X    = (const float*)d_in[0];
    const float* mask = (const float*)d_in[1];
    const float* Wq   = (const float*)d_in[2];
    const float* bq   = (const float*)d_in[3];
    const float* Wk   = (const float*)d_in[4];
    const float* bk   = (const float*)d_in[5];
    const float* Wv   = (const float*)d_in[6];
    const float* bv   = (const float*)d_in[7];
    const float* rke  = (const float*)d_in[8];
    const float* rve  = (const float*)d_in[9];
    float* out = (float*)d_out;

    (void)in_sizes; (void)n_in; (void)out_size;

    cudaFuncSetAttribute(attn_kernel,
                         cudaFuncAttributeMaxDynamicSharedMemorySize, SMEMB);

    qkv_kernel<<<dim3(64, NHn, 3), 256>>>(X, Wq, bq, Wk, bk, Wv, bv);
    attn_kernel<<<dim3(32, NHn, Bn), 256, SMEMB>>>(mask, rke, rve, out);
}